// round 2
// baseline (speedup 1.0000x reference)
#include <cuda_runtime.h>
#include <math.h>

#define NN 3072
#define BB 32
#define LL 96
#define EE (NN*LL)
#define HIDD 128
#define LATD 64

// ---------------- device scratch (no allocations allowed) ----------------
__device__ float g_Hin[NN*320];
__device__ float g_h[NN*HIDD];
__device__ float g_tmp[NN*HIDD];
__device__ float g_a[NN*HIDD];
__device__ float g_bn[NN*HIDD];
__device__ float g_agg[NN*HIDD];
__device__ float g_X[2][NN*3];
__device__ float g_vH[NN*LATD];
__device__ float g_wd2[HIDD];
__device__ float g_etab[2*HIDD];
__device__ int   g_off[BB+1];
__device__ int   g_mask[NN];
__device__ float g_lpart[64*5];

// ---------------- mask canonicalization (dtype auto-detect) ----------------
// JAX bool may arrive as uint8, int32, or float32. Detect from byte patterns:
//   any byte > 1                      -> float32 (0x3F800000 pattern)
//   else any nonzero byte at i%4 != 0 -> uint8
//   else                              -> int32 (widened bool, high bytes 0)
__global__ void mask_prep(const unsigned char* __restrict__ m){
    __shared__ int s_big, s_odd;
    int tid = threadIdx.x;
    if (tid == 0){ s_big = 0; s_odd = 0; }
    __syncthreads();
    int big = 0, odd = 0;
    for (int i = tid; i < NN; i += blockDim.x){
        unsigned char v = m[i];
        if (v > 1) big = 1;
        if ((i & 3) && v) odd = 1;
    }
    if (big) s_big = 1;
    if (odd) s_odd = 1;
    __syncthreads();
    if (s_big){
        const float* mf = (const float*)m;
        for (int i = tid; i < NN; i += blockDim.x) g_mask[i] = (mf[i] != 0.f) ? 1 : 0;
    } else if (s_odd){
        for (int i = tid; i < NN; i += blockDim.x) g_mask[i] = m[i] ? 1 : 0;
    } else {
        const int* mi = (const int*)m;
        for (int i = tid; i < NN; i += blockDim.x) g_mask[i] = mi[i] ? 1 : 0;
    }
}

// ---------------- tiny setup kernels ----------------
__global__ void setup_offsets(const int* __restrict__ lengths){
    if (threadIdx.x == 0){
        int s = 0;
        for (int b = 0; b < BB; b++){ g_off[b] = s; s += lengths[b]; }
        g_off[BB] = s;
    }
}

// one block per node, 128 threads: build Hin = [H_t | cond | sin/cos t-embed], X_t
__global__ void node_prep(const float* __restrict__ H0, const float* __restrict__ X0,
                          const float* __restrict__ H1, const float* __restrict__ X1,
                          const float* __restrict__ cond, const float* __restrict__ tg)
{
    int i = blockIdx.x;
    int k = threadIdx.x;
    __shared__ float t_sh; __shared__ int m_sh;
    if (k == 0){
        int b = 0;
        while (b + 1 < BB && g_off[b+1] <= i) b++;
        t_sh = tg[b];
        m_sh = g_mask[i];
    }
    __syncthreads();
    float t = t_sh; int m = m_sh;
    if (k < 64){
        float h0 = H0[i*64+k], h1 = H1[i*64+k];
        g_Hin[i*320 + k] = m ? (1.f - t)*h0 + t*h1 : h1;
        float f = expf(-logf(10000.f) * (float)k / 63.f);
        float ang = t * f;
        g_Hin[i*320 + 192 + k] = sinf(ang);
        g_Hin[i*320 + 256 + k] = cosf(ang);
    }
    g_Hin[i*320 + 64 + k] = cond[i*128 + k];
    if (k < 3){
        float x0 = X0[i*3+k], x1 = X1[i*3+k];
        g_X[0][i*3+k] = m ? (1.f - t)*x0 + t*x1 : x1;
    }
}

// per-layer edge constants: wd2 = We1[256,:], etab[t] = be1 + edge_table[t]@We1[257:289,:]
__global__ void prep_edge(const float* __restrict__ We1, const float* __restrict__ be1,
                          const float* __restrict__ etable, int l)
{
    int k = threadIdx.x;  // 128
    const float* W = We1 + (size_t)l*289*128;
    g_wd2[k] = W[256*128 + k];
    for (int t = 0; t < 2; t++){
        float s = be1[l*128 + k];
        for (int e = 0; e < 32; e++) s += etable[t*32 + e] * W[(257 + e)*128 + k];
        g_etab[t*128 + k] = s;
    }
}

// ---------------- generic node GEMM: out = act(A@W + bias) (+resid) ----------------
// A = concat(A1[:, :K1], A2[:, :K2]) row-major. M rows tiled 32/CTA, 256 threads.
template<int NOUT>
__global__ void gemm_node(const float* __restrict__ A1, int K1,
                          const float* __restrict__ A2, int K2,
                          const float* __restrict__ W,
                          const float* __restrict__ bias,
                          const float* __restrict__ resid,
                          float* __restrict__ out,
                          int act)
{
    const int NPT = NOUT / 8;
    __shared__ float As[32][33];
    __shared__ float Ws[32*NOUT];
    int tid = threadIdx.x;
    int row = tid >> 3;
    int c0 = (tid & 7) * NPT;
    int r0 = blockIdx.x * 32;
    int K = K1 + K2;
    float acc[NPT];
#pragma unroll
    for (int c = 0; c < NPT; c++) acc[c] = 0.f;

    for (int k0 = 0; k0 < K; k0 += 32){
        for (int i = tid; i < 1024; i += 256){
            int rr = i >> 5, kk = i & 31;
            int k = k0 + kk, g = r0 + rr;
            As[rr][kk] = (k < K1) ? A1[(size_t)g*K1 + k] : A2[(size_t)g*K2 + (k - K1)];
        }
        for (int i = tid; i < 32*NOUT; i += 256){
            int kk = i / NOUT, cc = i - kk*NOUT;
            Ws[kk*NOUT + cc] = W[(size_t)(k0 + kk)*NOUT + cc];
        }
        __syncthreads();
#pragma unroll 8
        for (int kk = 0; kk < 32; kk++){
            float a = As[row][kk];
#pragma unroll
            for (int c = 0; c < NPT; c++) acc[c] += a * Ws[kk*NOUT + c0 + c];
        }
        __syncthreads();
    }
    int g = r0 + row;
#pragma unroll
    for (int c = 0; c < NPT; c++){
        float v = acc[c];
        if (bias) v += bias[c0 + c];
        if (act == 1) v = fmaxf(v, 0.f);
        else if (act == 2) v = __fdividef(v, 1.f + __expf(-v));
        if (resid) v += resid[(size_t)g*NOUT + c0 + c];
        out[(size_t)g*NOUT + c0 + c] = v;
    }
}

// ---------------- fused edge kernel: one CTA per row node ----------------
// smem float layout offsets
#define S_M1    0
#define S_W2    12288
#define S_AS    28672
#define S_WD2   28800
#define S_ETAB  28928
#define S_BE2   29184
#define S_WX    29312
#define S_REL   29440
#define S_COEF  29824
#define S_COL   29920
#define S_ET    30016
#define S_TOTF  30116
#define SMEM_BYTES (S_TOTF*4)

__global__ void __launch_bounds__(256, 1) edge_kernel(
    const float* __restrict__ aG, const float* __restrict__ bG,
    const float* __restrict__ Xin, float* __restrict__ Xout,
    float* __restrict__ aggG,
    const int* __restrict__ ecol, const int* __restrict__ chain,
    const float* __restrict__ W2g, const float* __restrict__ be2g,
    const float* __restrict__ Wxg)
{
    extern __shared__ float sm[];
    float* M1     = sm + S_M1;    // 96x128, reused as 16x128 aggbuf later
    float* W2     = sm + S_W2;    // 128x128
    float* a_s    = sm + S_AS;
    float* wd2_s  = sm + S_WD2;
    float* etab_s = sm + S_ETAB;
    float* be2_s  = sm + S_BE2;
    float* Wx_s   = sm + S_WX;
    float* rel_s  = sm + S_REL;   // 96 x {dx,dy,dz,d2}
    float* coef_s = sm + S_COEF;
    int*   col_s  = (int*)(sm + S_COL);
    int*   et_s   = (int*)(sm + S_ET);

    int r = blockIdx.x;
    int tid = threadIdx.x;

    // stage weights & per-row vectors
    for (int i = tid; i < 4096; i += 256)
        ((float4*)W2)[i] = ((const float4*)W2g)[i];
    if (tid < 128){
        a_s[tid]       = aG[r*128 + tid];
        wd2_s[tid]     = g_wd2[tid];
        etab_s[tid]    = g_etab[tid];
        etab_s[128+tid]= g_etab[128 + tid];
        be2_s[tid]     = be2g[tid];
        Wx_s[tid]      = Wxg[tid];
    }
    float xr0 = Xin[r*3], xr1 = Xin[r*3+1], xr2 = Xin[r*3+2];
    int chr = chain[r];
    if (tid < 96){
        int c = ecol[r*96 + tid];
        col_s[tid] = c;
        float dx = xr0 - Xin[c*3], dy = xr1 - Xin[c*3+1], dz = xr2 - Xin[c*3+2];
        rel_s[tid*4]   = dx;
        rel_s[tid*4+1] = dy;
        rel_s[tid*4+2] = dz;
        rel_s[tid*4+3] = dx*dx + dy*dy + dz*dz;
        et_s[tid] = (chain[c] != chr) ? 1 : 0;
    }
    __syncthreads();

    // phase 1: m1[j][k] = silu(a[r] + b[col] + d2*wd2 + etab[type])
    for (int idx = tid; idx < 96*32; idx += 256){
        int j = idx >> 5, k = (idx & 31) * 4;
        int c = col_s[j];
        float4 bn = *(const float4*)&bG[(size_t)c*128 + k];
        float d2 = rel_s[j*4+3];
        const float* et = etab_s + et_s[j]*128;
        float4 p;
        p.x = a_s[k+0] + bn.x + d2*wd2_s[k+0] + et[k+0];
        p.y = a_s[k+1] + bn.y + d2*wd2_s[k+1] + et[k+1];
        p.z = a_s[k+2] + bn.z + d2*wd2_s[k+2] + et[k+2];
        p.w = a_s[k+3] + bn.w + d2*wd2_s[k+3] + et[k+3];
        p.x = __fdividef(p.x, 1.f + __expf(-p.x));
        p.y = __fdividef(p.y, 1.f + __expf(-p.y));
        p.z = __fdividef(p.z, 1.f + __expf(-p.z));
        p.w = __fdividef(p.w, 1.f + __expf(-p.w));
        *(float4*)&M1[j*128 + k] = p;
    }
    __syncthreads();

    // phase 2: 96x128 @ 128x128 GEMM, 6x8 register tiles
    int tx = tid & 15, ty = tid >> 4;
    int j0 = ty*6, o0 = tx*8;
    float acc[6][8];
#pragma unroll
    for (int jj = 0; jj < 6; jj++)
#pragma unroll
        for (int oo = 0; oo < 8; oo++) acc[jj][oo] = 0.f;

    const float* m1p = M1 + j0*128;
#pragma unroll 2
    for (int k = 0; k < 128; k++){
        float4 w0 = *(const float4*)&W2[k*128 + o0];
        float4 w1 = *(const float4*)&W2[k*128 + o0 + 4];
#pragma unroll
        for (int jj = 0; jj < 6; jj++){
            float a = m1p[jj*128 + k];
            acc[jj][0] += a*w0.x; acc[jj][1] += a*w0.y;
            acc[jj][2] += a*w0.z; acc[jj][3] += a*w0.w;
            acc[jj][4] += a*w1.x; acc[jj][5] += a*w1.y;
            acc[jj][6] += a*w1.z; acc[jj][7] += a*w1.w;
        }
    }

    // m2 = silu(acc + be2), in place
#pragma unroll
    for (int jj = 0; jj < 6; jj++)
#pragma unroll
        for (int oo = 0; oo < 8; oo++){
            float v = acc[jj][oo] + be2_s[o0 + oo];
            acc[jj][oo] = __fdividef(v, 1.f + __expf(-v));
        }

    __syncthreads();            // all reads of M1 done; reuse as aggbuf[16][128]
    float* AB = M1;
#pragma unroll
    for (int oo = 0; oo < 8; oo++){
        float s = acc[0][oo] + acc[1][oo] + acc[2][oo]
                + acc[3][oo] + acc[4][oo] + acc[5][oo];
        AB[ty*128 + o0 + oo] = s;
    }
    // coef[j] = m2[j] @ Wx  (reduce over tx groups of 16 inside the warp)
#pragma unroll
    for (int jj = 0; jj < 6; jj++){
        float c = 0.f;
#pragma unroll
        for (int oo = 0; oo < 8; oo++) c += acc[jj][oo] * Wx_s[o0 + oo];
        c += __shfl_xor_sync(0xffffffffu, c, 1);
        c += __shfl_xor_sync(0xffffffffu, c, 2);
        c += __shfl_xor_sync(0xffffffffu, c, 4);
        c += __shfl_xor_sync(0xffffffffu, c, 8);
        if (tx == 0) coef_s[j0 + jj] = c;
    }
    __syncthreads();

    if (tid < 128){
        float s = 0.f;
#pragma unroll
        for (int g2 = 0; g2 < 16; g2++) s += AB[g2*128 + tid];
        aggG[(size_t)r*128 + tid] = s;
    }
    if (tid < 3){
        float s = 0.f;
        for (int j = 0; j < 96; j++) s += coef_s[j] * rel_s[j*4 + tid];
        Xout[r*3 + tid] = Xin[r*3 + tid] + s;
    }
}

// ---------------- losses ----------------
__global__ void loss_partial(const float* __restrict__ H0, const float* __restrict__ H1,
                             const float* __restrict__ X0, const float* __restrict__ X1,
                             const int* __restrict__ shiftp,
                             const float* __restrict__ Xf)
{
    __shared__ float red[256];
    float s[5] = {0,0,0,0,0};
    int shift = *shiftp;
    for (int i = blockIdx.x*blockDim.x + threadIdx.x; i < NN; i += gridDim.x*blockDim.x){
        if (!g_mask[i]) continue;
        int j = (i + shift) % NN; if (j < 0) j += NN;
        float hp = 0.f, hn = 0.f;
        for (int k = 0; k < 64; k++){
            float p = g_vH[i*64 + k];
            float d  = p - (H1[i*64+k] - H0[i*64+k]); hp += d*d;
            float dn = p - (H1[j*64+k] - H0[j*64+k]); hn += dn*dn;
        }
        float xp = 0.f, xn = 0.f;
        for (int k = 0; k < 3; k++){
            float p = Xf[i*3 + k];
            float d  = p - (X1[i*3+k] - X0[i*3+k]); xp += d*d;
            float dn = p - (X1[j*3+k] - X0[j*3+k]); xn += dn*dn;
        }
        s[0] += hp; s[1] += xp; s[2] += hn; s[3] += xn; s[4] += 1.f;
    }
    for (int q = 0; q < 5; q++){
        red[threadIdx.x] = s[q]; __syncthreads();
        for (int d = 128; d > 0; d >>= 1){
            if (threadIdx.x < d) red[threadIdx.x] += red[threadIdx.x + d];
            __syncthreads();
        }
        if (threadIdx.x == 0) g_lpart[blockIdx.x*5 + q] = red[0];
        __syncthreads();
    }
}

__global__ void loss_final(float* __restrict__ out, int nb){
    if (threadIdx.x == 0){
        float s[5] = {0,0,0,0,0};
        for (int b = 0; b < nb; b++)
            for (int q = 0; q < 5; q++) s[q] += g_lpart[b*5 + q];
        float msum = s[4] + 1e-8f;
        float lHp = s[0]/msum, lXp = s[1]/msum, lHn = s[2]/msum, lXn = s[3]/msum;
        out[0] = lHp - 0.05f*lHn;
        out[1] = lXp - 0.05f*lXn;
        out[2] = lHp; out[3] = lXp; out[4] = lHn; out[5] = lXn;
    }
}

// ---------------- host launch ----------------
extern "C" void kernel_launch(void* const* d_in, const int* in_sizes, int n_in,
                              void* d_out, int out_size)
{
    (void)in_sizes; (void)n_in; (void)out_size;
    const float* H0    = (const float*)d_in[0];
    const float* X0    = (const float*)d_in[1];
    const float* H1    = (const float*)d_in[2];
    const float* X1    = (const float*)d_in[3];
    const float* cond  = (const float*)d_in[4];
    const float* tg    = (const float*)d_in[5];
    const float* Wi1   = (const float*)d_in[6];
    const float* bi1   = (const float*)d_in[7];
    const float* Wi2   = (const float*)d_in[8];
    const float* bi2   = (const float*)d_in[9];
    const float* Wi3   = (const float*)d_in[10];
    const float* bi3   = (const float*)d_in[11];
    const float* etab  = (const float*)d_in[12];
    const float* We1   = (const float*)d_in[13];
    const float* be1   = (const float*)d_in[14];
    const float* We2   = (const float*)d_in[15];
    const float* be2   = (const float*)d_in[16];
    const float* Wx    = (const float*)d_in[17];
    const float* Wh1   = (const float*)d_in[18];
    const float* bh1   = (const float*)d_in[19];
    const float* Wh2   = (const float*)d_in[20];
    const float* bh2   = (const float*)d_in[21];
    const float* Wout  = (const float*)d_in[22];
    const float* bout  = (const float*)d_in[23];
    const int*   edges = (const int*)d_in[24];
    const int*   chain = (const int*)d_in[25];
    const unsigned char* mask = (const unsigned char*)d_in[26];
    const int*   lengths = (const int*)d_in[27];
    const int*   shiftp  = (const int*)d_in[28];
    const int*   ecol = edges + EE;

    float *p_Hin, *p_h, *p_tmp, *p_a, *p_bn, *p_agg, *p_X, *p_vH;
    cudaGetSymbolAddress((void**)&p_Hin, g_Hin);
    cudaGetSymbolAddress((void**)&p_h,   g_h);
    cudaGetSymbolAddress((void**)&p_tmp, g_tmp);
    cudaGetSymbolAddress((void**)&p_a,   g_a);
    cudaGetSymbolAddress((void**)&p_bn,  g_bn);
    cudaGetSymbolAddress((void**)&p_agg, g_agg);
    cudaGetSymbolAddress((void**)&p_X,   g_X);
    cudaGetSymbolAddress((void**)&p_vH,  g_vH);

    cudaFuncSetAttribute(edge_kernel,
                         cudaFuncAttributeMaxDynamicSharedMemorySize, SMEM_BYTES);

    mask_prep<<<1, 256>>>(mask);
    setup_offsets<<<1, 32>>>(lengths);
    node_prep<<<NN, 128>>>(H0, X0, H1, X1, cond, tg);

    // input MLP: 320 -> 128 (relu) -> 128 (relu) -> 128
    gemm_node<128><<<96, 256>>>(p_Hin, 320, nullptr, 0, Wi1, bi1, nullptr, p_h,   1);
    gemm_node<128><<<96, 256>>>(p_h,   128, nullptr, 0, Wi2, bi2, nullptr, p_tmp, 1);
    gemm_node<128><<<96, 256>>>(p_tmp, 128, nullptr, 0, Wi3, bi3, nullptr, p_h,   0);

    int cur = 0;
    for (int l = 0; l < 3; l++){
        const float* We1l = We1 + (size_t)l*289*128;
        prep_edge<<<1, 128>>>(We1, be1, etab, l);
        gemm_node<128><<<96, 256>>>(p_h, 128, nullptr, 0, We1l,           nullptr, nullptr, p_a,  0);
        gemm_node<128><<<96, 256>>>(p_h, 128, nullptr, 0, We1l + 128*128, nullptr, nullptr, p_bn, 0);
        edge_kernel<<<NN, 256, SMEM_BYTES>>>(p_a, p_bn,
                                             p_X + cur*NN*3, p_X + (1-cur)*NN*3,
                                             p_agg, ecol, chain,
                                             We2 + (size_t)l*128*128,
                                             be2 + l*128, Wx + l*128);
        cur = 1 - cur;
        // h = h + silu([h|agg]@Wh1 + bh1) @ Wh2 + bh2
        gemm_node<128><<<96, 256>>>(p_h,   128, p_agg, 128, Wh1 + (size_t)l*256*128,
                                    bh1 + l*128, nullptr, p_tmp, 2);
        gemm_node<128><<<96, 256>>>(p_tmp, 128, nullptr, 0,  Wh2 + (size_t)l*128*128,
                                    bh2 + l*128, p_h, p_h, 0);
    }

    gemm_node<64><<<96, 256>>>(p_h, 128, nullptr, 0, Wout, bout, nullptr, p_vH, 0);

    loss_partial<<<12, 256>>>(H0, H1, X0, X1, shiftp, p_X + cur*NN*3);
    loss_final<<<1, 32>>>((float*)d_out, 12);
}

// round 3
// speedup vs baseline: 1.5566x; 1.5566x over previous
#include <cuda_runtime.h>
#include <math.h>

#define NN 3072
#define BB 32
#define LL 96
#define EE (NN*LL)
#define HIDD 128
#define LATD 64

// ---------------- device scratch (no allocations allowed) ----------------
__device__ float g_Hin[NN*320];
__device__ float g_h[NN*HIDD];
__device__ float g_tmp[NN*HIDD];
__device__ float g_a[NN*HIDD];
__device__ float g_bn[NN*HIDD];
__device__ float g_agg[NN*HIDD];
__device__ float g_X[2][NN*3];
__device__ float g_vH[NN*LATD];
__device__ float g_wd2[HIDD];
__device__ float g_etab[2*HIDD];
__device__ int   g_off[BB+1];
__device__ int   g_mask[NN];
__device__ float g_lpart[64*5];

// ---------------- mask canonicalization (dtype auto-detect) ----------------
__global__ void mask_prep(const unsigned char* __restrict__ m){
    __shared__ int s_big, s_odd;
    int tid = threadIdx.x;
    if (tid == 0){ s_big = 0; s_odd = 0; }
    __syncthreads();
    int big = 0, odd = 0;
    for (int i = tid; i < NN; i += blockDim.x){
        unsigned char v = m[i];
        if (v > 1) big = 1;
        if ((i & 3) && v) odd = 1;
    }
    if (big) s_big = 1;
    if (odd) s_odd = 1;
    __syncthreads();
    if (s_big){
        const float* mf = (const float*)m;
        for (int i = tid; i < NN; i += blockDim.x) g_mask[i] = (mf[i] != 0.f) ? 1 : 0;
    } else if (s_odd){
        for (int i = tid; i < NN; i += blockDim.x) g_mask[i] = m[i] ? 1 : 0;
    } else {
        const int* mi = (const int*)m;
        for (int i = tid; i < NN; i += blockDim.x) g_mask[i] = mi[i] ? 1 : 0;
    }
}

// ---------------- tiny setup kernels ----------------
__global__ void setup_offsets(const int* __restrict__ lengths){
    if (threadIdx.x == 0){
        int s = 0;
        for (int b = 0; b < BB; b++){ g_off[b] = s; s += lengths[b]; }
        g_off[BB] = s;
    }
}

__global__ void node_prep(const float* __restrict__ H0, const float* __restrict__ X0,
                          const float* __restrict__ H1, const float* __restrict__ X1,
                          const float* __restrict__ cond, const float* __restrict__ tg)
{
    int i = blockIdx.x;
    int k = threadIdx.x;
    __shared__ float t_sh; __shared__ int m_sh;
    if (k == 0){
        int b = 0;
        while (b + 1 < BB && g_off[b+1] <= i) b++;
        t_sh = tg[b];
        m_sh = g_mask[i];
    }
    __syncthreads();
    float t = t_sh; int m = m_sh;
    if (k < 64){
        float h0 = H0[i*64+k], h1 = H1[i*64+k];
        g_Hin[i*320 + k] = m ? (1.f - t)*h0 + t*h1 : h1;
        float f = expf(-logf(10000.f) * (float)k / 63.f);
        float ang = t * f;
        g_Hin[i*320 + 192 + k] = sinf(ang);
        g_Hin[i*320 + 256 + k] = cosf(ang);
    }
    g_Hin[i*320 + 64 + k] = cond[i*128 + k];
    if (k < 3){
        float x0 = X0[i*3+k], x1 = X1[i*3+k];
        g_X[0][i*3+k] = m ? (1.f - t)*x0 + t*x1 : x1;
    }
}

__global__ void prep_edge(const float* __restrict__ We1, const float* __restrict__ be1,
                          const float* __restrict__ etable, int l)
{
    int k = threadIdx.x;  // 128
    const float* W = We1 + (size_t)l*289*128;
    g_wd2[k] = W[256*128 + k];
    for (int t = 0; t < 2; t++){
        float s = be1[l*128 + k];
        for (int e = 0; e < 32; e++) s += etable[t*32 + e] * W[(257 + e)*128 + k];
        g_etab[t*128 + k] = s;
    }
}

// ---------------- node GEMM v2: register-tiled, 16 rows/CTA, 128 threads ----
// out[16 x NOUT] = act(concat(A1,A2)[16 x K] @ W[K x NOUT] + bias) (+resid)
// thread tile: R rows x 4 cols. NOUT=128 -> R=4, NOUT=64 -> R=2.
template<int NOUT>
__global__ void __launch_bounds__(128, 8) gemm16(
    const float* __restrict__ A1, int K1,
    const float* __restrict__ A2, int K2,
    const float* __restrict__ W,
    const float* __restrict__ bias,
    const float* __restrict__ resid,
    float* __restrict__ out,
    int act)
{
    constexpr int NC4 = NOUT / 4;          // column groups of 4
    constexpr int TR  = 128 / NC4;         // thread-groups along rows
    constexpr int R   = 16 / TR;           // rows per thread
    __shared__ float As[16][33];           // conflict-free scalar STS
    __shared__ float Ws[32 * NOUT];

    int tid = threadIdx.x;
    int tx  = tid % NC4;                   // column group
    int ty  = tid / NC4;                   // row group
    int c0  = tx * 4;
    int r0  = ty * R;
    int gr0 = blockIdx.x * 16;             // global row base
    int K   = K1 + K2;

    float acc[R][4];
#pragma unroll
    for (int i = 0; i < R; i++)
#pragma unroll
        for (int j = 0; j < 4; j++) acc[i][j] = 0.f;

    // A staging mapping: row = tid>>3 (16 rows), kc = tid&7 (8 float4 chunks)
    int srow = tid >> 3;
    int skc  = tid & 7;

    for (int k0 = 0; k0 < K; k0 += 32){
        // stage A (float4 LDG, scalar STS transposed into [row][k])
        {
            int k = k0 + skc * 4;
            int g = gr0 + srow;
            float4 v;
            if (k < K1) v = *(const float4*)&A1[(size_t)g*K1 + k];
            else        v = *(const float4*)&A2[(size_t)g*K2 + (k - K1)];
            As[srow][skc*4 + 0] = v.x;
            As[srow][skc*4 + 1] = v.y;
            As[srow][skc*4 + 2] = v.z;
            As[srow][skc*4 + 3] = v.w;
        }
        // stage W: 32 x NOUT floats = 8*NC4 float4 per... total 32*NC4 float4
        {
            const float4* Wg = (const float4*)(W + (size_t)k0 * NOUT);
#pragma unroll
            for (int i = 0; i < (32*NC4)/128; i++){
                int idx = tid + i*128;          // float4 index within 32 x NC4
                ((float4*)Ws)[idx] = Wg[idx];
            }
        }
        __syncthreads();
#pragma unroll
        for (int kk = 0; kk < 32; kk++){
            float4 w = *(const float4*)&Ws[kk*NOUT + c0];
            float a[R];
#pragma unroll
            for (int i = 0; i < R; i++) a[i] = As[r0 + i][kk];
#pragma unroll
            for (int i = 0; i < R; i++){
                acc[i][0] += a[i]*w.x; acc[i][1] += a[i]*w.y;
                acc[i][2] += a[i]*w.z; acc[i][3] += a[i]*w.w;
            }
        }
        __syncthreads();
    }

    float4 bv = make_float4(0.f,0.f,0.f,0.f);
    if (bias) bv = *(const float4*)&bias[c0];
#pragma unroll
    for (int i = 0; i < R; i++){
        int g = gr0 + r0 + i;
        float4 v;
        v.x = acc[i][0] + bv.x; v.y = acc[i][1] + bv.y;
        v.z = acc[i][2] + bv.z; v.w = acc[i][3] + bv.w;
        if (act == 1){
            v.x = fmaxf(v.x,0.f); v.y = fmaxf(v.y,0.f);
            v.z = fmaxf(v.z,0.f); v.w = fmaxf(v.w,0.f);
        } else if (act == 2){
            v.x = __fdividef(v.x, 1.f + __expf(-v.x));
            v.y = __fdividef(v.y, 1.f + __expf(-v.y));
            v.z = __fdividef(v.z, 1.f + __expf(-v.z));
            v.w = __fdividef(v.w, 1.f + __expf(-v.w));
        }
        if (resid){
            float4 rv = *(const float4*)&resid[(size_t)g*NOUT + c0];
            v.x += rv.x; v.y += rv.y; v.z += rv.z; v.w += rv.w;
        }
        *(float4*)&out[(size_t)g*NOUT + c0] = v;
    }
}

// ---------------- fused edge kernel: one CTA per row node ----------------
#define S_M1    0
#define S_W2    12288
#define S_AS    28672
#define S_WD2   28800
#define S_ETAB  28928
#define S_BE2   29184
#define S_WX    29312
#define S_REL   29440
#define S_COEF  29824
#define S_COL   29920
#define S_ET    30016
#define S_TOTF  30116
#define SMEM_BYTES (S_TOTF*4)

__global__ void __launch_bounds__(256, 1) edge_kernel(
    const float* __restrict__ aG, const float* __restrict__ bG,
    const float* __restrict__ Xin, float* __restrict__ Xout,
    float* __restrict__ aggG,
    const int* __restrict__ ecol, const int* __restrict__ chain,
    const float* __restrict__ W2g, const float* __restrict__ be2g,
    const float* __restrict__ Wxg)
{
    extern __shared__ float sm[];
    float* M1     = sm + S_M1;
    float* W2     = sm + S_W2;
    float* a_s    = sm + S_AS;
    float* wd2_s  = sm + S_WD2;
    float* etab_s = sm + S_ETAB;
    float* be2_s  = sm + S_BE2;
    float* Wx_s   = sm + S_WX;
    float* rel_s  = sm + S_REL;
    float* coef_s = sm + S_COEF;
    int*   col_s  = (int*)(sm + S_COL);
    int*   et_s   = (int*)(sm + S_ET);

    int r = blockIdx.x;
    int tid = threadIdx.x;

    for (int i = tid; i < 4096; i += 256)
        ((float4*)W2)[i] = ((const float4*)W2g)[i];
    if (tid < 128){
        a_s[tid]       = aG[r*128 + tid];
        wd2_s[tid]     = g_wd2[tid];
        etab_s[tid]    = g_etab[tid];
        etab_s[128+tid]= g_etab[128 + tid];
        be2_s[tid]     = be2g[tid];
        Wx_s[tid]      = Wxg[tid];
    }
    float xr0 = Xin[r*3], xr1 = Xin[r*3+1], xr2 = Xin[r*3+2];
    int chr = chain[r];
    if (tid < 96){
        int c = ecol[r*96 + tid];
        col_s[tid] = c;
        float dx = xr0 - Xin[c*3], dy = xr1 - Xin[c*3+1], dz = xr2 - Xin[c*3+2];
        rel_s[tid*4]   = dx;
        rel_s[tid*4+1] = dy;
        rel_s[tid*4+2] = dz;
        rel_s[tid*4+3] = dx*dx + dy*dy + dz*dz;
        et_s[tid] = (chain[c] != chr) ? 1 : 0;
    }
    __syncthreads();

    for (int idx = tid; idx < 96*32; idx += 256){
        int j = idx >> 5, k = (idx & 31) * 4;
        int c = col_s[j];
        float4 bn = *(const float4*)&bG[(size_t)c*128 + k];
        float d2 = rel_s[j*4+3];
        const float* et = etab_s + et_s[j]*128;
        float4 p;
        p.x = a_s[k+0] + bn.x + d2*wd2_s[k+0] + et[k+0];
        p.y = a_s[k+1] + bn.y + d2*wd2_s[k+1] + et[k+1];
        p.z = a_s[k+2] + bn.z + d2*wd2_s[k+2] + et[k+2];
        p.w = a_s[k+3] + bn.w + d2*wd2_s[k+3] + et[k+3];
        p.x = __fdividef(p.x, 1.f + __expf(-p.x));
        p.y = __fdividef(p.y, 1.f + __expf(-p.y));
        p.z = __fdividef(p.z, 1.f + __expf(-p.z));
        p.w = __fdividef(p.w, 1.f + __expf(-p.w));
        *(float4*)&M1[j*128 + k] = p;
    }
    __syncthreads();

    int tx = tid & 15, ty = tid >> 4;
    int j0 = ty*6, o0 = tx*8;
    float acc[6][8];
#pragma unroll
    for (int jj = 0; jj < 6; jj++)
#pragma unroll
        for (int oo = 0; oo < 8; oo++) acc[jj][oo] = 0.f;

    const float* m1p = M1 + j0*128;
#pragma unroll 2
    for (int k = 0; k < 128; k++){
        float4 w0 = *(const float4*)&W2[k*128 + o0];
        float4 w1 = *(const float4*)&W2[k*128 + o0 + 4];
#pragma unroll
        for (int jj = 0; jj < 6; jj++){
            float a = m1p[jj*128 + k];
            acc[jj][0] += a*w0.x; acc[jj][1] += a*w0.y;
            acc[jj][2] += a*w0.z; acc[jj][3] += a*w0.w;
            acc[jj][4] += a*w1.x; acc[jj][5] += a*w1.y;
            acc[jj][6] += a*w1.z; acc[jj][7] += a*w1.w;
        }
    }

#pragma unroll
    for (int jj = 0; jj < 6; jj++)
#pragma unroll
        for (int oo = 0; oo < 8; oo++){
            float v = acc[jj][oo] + be2_s[o0 + oo];
            acc[jj][oo] = __fdividef(v, 1.f + __expf(-v));
        }

    __syncthreads();
    float* AB = M1;
#pragma unroll
    for (int oo = 0; oo < 8; oo++){
        float s = acc[0][oo] + acc[1][oo] + acc[2][oo]
                + acc[3][oo] + acc[4][oo] + acc[5][oo];
        AB[ty*128 + o0 + oo] = s;
    }
#pragma unroll
    for (int jj = 0; jj < 6; jj++){
        float c = 0.f;
#pragma unroll
        for (int oo = 0; oo < 8; oo++) c += acc[jj][oo] * Wx_s[o0 + oo];
        c += __shfl_xor_sync(0xffffffffu, c, 1);
        c += __shfl_xor_sync(0xffffffffu, c, 2);
        c += __shfl_xor_sync(0xffffffffu, c, 4);
        c += __shfl_xor_sync(0xffffffffu, c, 8);
        if (tx == 0) coef_s[j0 + jj] = c;
    }
    __syncthreads();

    if (tid < 128){
        float s = 0.f;
#pragma unroll
        for (int g2 = 0; g2 < 16; g2++) s += AB[g2*128 + tid];
        aggG[(size_t)r*128 + tid] = s;
    }
    if (tid < 3){
        float s = 0.f;
        for (int j = 0; j < 96; j++) s += coef_s[j] * rel_s[j*4 + tid];
        Xout[r*3 + tid] = Xin[r*3 + tid] + s;
    }
}

// ---------------- losses ----------------
__global__ void loss_partial(const float* __restrict__ H0, const float* __restrict__ H1,
                             const float* __restrict__ X0, const float* __restrict__ X1,
                             const int* __restrict__ shiftp,
                             const float* __restrict__ Xf)
{
    __shared__ float red[256];
    float s[5] = {0,0,0,0,0};
    int shift = *shiftp;
    for (int i = blockIdx.x*blockDim.x + threadIdx.x; i < NN; i += gridDim.x*blockDim.x){
        if (!g_mask[i]) continue;
        int j = (i + shift) % NN; if (j < 0) j += NN;
        float hp = 0.f, hn = 0.f;
        for (int k = 0; k < 64; k++){
            float p = g_vH[i*64 + k];
            float d  = p - (H1[i*64+k] - H0[i*64+k]); hp += d*d;
            float dn = p - (H1[j*64+k] - H0[j*64+k]); hn += dn*dn;
        }
        float xp = 0.f, xn = 0.f;
        for (int k = 0; k < 3; k++){
            float p = Xf[i*3 + k];
            float d  = p - (X1[i*3+k] - X0[i*3+k]); xp += d*d;
            float dn = p - (X1[j*3+k] - X0[j*3+k]); xn += dn*dn;
        }
        s[0] += hp; s[1] += xp; s[2] += hn; s[3] += xn; s[4] += 1.f;
    }
    for (int q = 0; q < 5; q++){
        red[threadIdx.x] = s[q]; __syncthreads();
        for (int d = 128; d > 0; d >>= 1){
            if (threadIdx.x < d) red[threadIdx.x] += red[threadIdx.x + d];
            __syncthreads();
        }
        if (threadIdx.x == 0) g_lpart[blockIdx.x*5 + q] = red[0];
        __syncthreads();
    }
}

__global__ void loss_final(float* __restrict__ out, int nb){
    if (threadIdx.x == 0){
        float s[5] = {0,0,0,0,0};
        for (int b = 0; b < nb; b++)
            for (int q = 0; q < 5; q++) s[q] += g_lpart[b*5 + q];
        float msum = s[4] + 1e-8f;
        float lHp = s[0]/msum, lXp = s[1]/msum, lHn = s[2]/msum, lXn = s[3]/msum;
        out[0] = lHp - 0.05f*lHn;
        out[1] = lXp - 0.05f*lXn;
        out[2] = lHp; out[3] = lXp; out[4] = lHn; out[5] = lXn;
    }
}

// ---------------- host launch ----------------
extern "C" void kernel_launch(void* const* d_in, const int* in_sizes, int n_in,
                              void* d_out, int out_size)
{
    (void)in_sizes; (void)n_in; (void)out_size;
    const float* H0    = (const float*)d_in[0];
    const float* X0    = (const float*)d_in[1];
    const float* H1    = (const float*)d_in[2];
    const float* X1    = (const float*)d_in[3];
    const float* cond  = (const float*)d_in[4];
    const float* tg    = (const float*)d_in[5];
    const float* Wi1   = (const float*)d_in[6];
    const float* bi1   = (const float*)d_in[7];
    const float* Wi2   = (const float*)d_in[8];
    const float* bi2   = (const float*)d_in[9];
    const float* Wi3   = (const float*)d_in[10];
    const float* bi3   = (const float*)d_in[11];
    const float* etab  = (const float*)d_in[12];
    const float* We1   = (const float*)d_in[13];
    const float* be1   = (const float*)d_in[14];
    const float* We2   = (const float*)d_in[15];
    const float* be2   = (const float*)d_in[16];
    const float* Wx    = (const float*)d_in[17];
    const float* Wh1   = (const float*)d_in[18];
    const float* bh1   = (const float*)d_in[19];
    const float* Wh2   = (const float*)d_in[20];
    const float* bh2   = (const float*)d_in[21];
    const float* Wout  = (const float*)d_in[22];
    const float* bout  = (const float*)d_in[23];
    const int*   edges = (const int*)d_in[24];
    const int*   chain = (const int*)d_in[25];
    const unsigned char* mask = (const unsigned char*)d_in[26];
    const int*   lengths = (const int*)d_in[27];
    const int*   shiftp  = (const int*)d_in[28];
    const int*   ecol = edges + EE;

    float *p_Hin, *p_h, *p_tmp, *p_a, *p_bn, *p_agg, *p_X, *p_vH;
    cudaGetSymbolAddress((void**)&p_Hin, g_Hin);
    cudaGetSymbolAddress((void**)&p_h,   g_h);
    cudaGetSymbolAddress((void**)&p_tmp, g_tmp);
    cudaGetSymbolAddress((void**)&p_a,   g_a);
    cudaGetSymbolAddress((void**)&p_bn,  g_bn);
    cudaGetSymbolAddress((void**)&p_agg, g_agg);
    cudaGetSymbolAddress((void**)&p_X,   g_X);
    cudaGetSymbolAddress((void**)&p_vH,  g_vH);

    cudaFuncSetAttribute(edge_kernel,
                         cudaFuncAttributeMaxDynamicSharedMemorySize, SMEM_BYTES);

    mask_prep<<<1, 256>>>(mask);
    setup_offsets<<<1, 32>>>(lengths);
    node_prep<<<NN, 128>>>(H0, X0, H1, X1, cond, tg);

    // input MLP: 320 -> 128 (relu) -> 128 (relu) -> 128
    gemm16<128><<<192, 128>>>(p_Hin, 320, nullptr, 0, Wi1, bi1, nullptr, p_h,   1);
    gemm16<128><<<192, 128>>>(p_h,   128, nullptr, 0, Wi2, bi2, nullptr, p_tmp, 1);
    gemm16<128><<<192, 128>>>(p_tmp, 128, nullptr, 0, Wi3, bi3, nullptr, p_h,   0);

    int cur = 0;
    for (int l = 0; l < 3; l++){
        const float* We1l = We1 + (size_t)l*289*128;
        prep_edge<<<1, 128>>>(We1, be1, etab, l);
        gemm16<128><<<192, 128>>>(p_h, 128, nullptr, 0, We1l,           nullptr, nullptr, p_a,  0);
        gemm16<128><<<192, 128>>>(p_h, 128, nullptr, 0, We1l + 128*128, nullptr, nullptr, p_bn, 0);
        edge_kernel<<<NN, 256, SMEM_BYTES>>>(p_a, p_bn,
                                             p_X + cur*NN*3, p_X + (1-cur)*NN*3,
                                             p_agg, ecol, chain,
                                             We2 + (size_t)l*128*128,
                                             be2 + l*128, Wx + l*128);
        cur = 1 - cur;
        gemm16<128><<<192, 128>>>(p_h,   128, p_agg, 128, Wh1 + (size_t)l*256*128,
                                  bh1 + l*128, nullptr, p_tmp, 2);
        gemm16<128><<<192, 128>>>(p_tmp, 128, nullptr, 0,  Wh2 + (size_t)l*128*128,
                                  bh2 + l*128, p_h, p_h, 0);
    }

    gemm16<64><<<192, 128>>>(p_h, 128, nullptr, 0, Wout, bout, nullptr, p_vH, 0);

    loss_partial<<<12, 256>>>(H0, H1, X0, X1, shiftp, p_X + cur*NN*3);
    loss_final<<<1, 32>>>((float*)d_out, 12);
}

// round 4
// speedup vs baseline: 2.5920x; 1.6652x over previous
#include <cuda_runtime.h>
#include <math.h>

#define NN 3072
#define BB 32
#define LL 96
#define EE (NN*LL)
#define HIDD 128
#define LATD 64

// ---------------- device scratch (no allocations allowed) ----------------
__device__ float g_Hin[NN*320];
__device__ float g_h[NN*HIDD];
__device__ float g_tmp[NN*HIDD];
__device__ float g_a[NN*HIDD];
__device__ float g_bn[NN*HIDD];
__device__ float g_agg[NN*HIDD];
__device__ float g_X[2][NN*3];
__device__ float g_vH[NN*LATD];
__device__ float g_wd2[HIDD];
__device__ float g_etab[2*HIDD];
__device__ int   g_off[BB+1];
__device__ int   g_mask[NN];
__device__ float g_lpart[64*5];

__device__ __forceinline__ float silu_f(float v){
    return __fdividef(v, 1.f + __expf(-v));
}
__device__ __forceinline__ unsigned f2tf32(float f){
    unsigned r; asm("cvt.rna.tf32.f32 %0, %1;" : "=r"(r) : "f"(f)); return r;
}
__device__ __forceinline__ void mma_tf32(float (&d)[4], const unsigned (&a)[4],
                                         unsigned b0, unsigned b1){
    asm volatile("mma.sync.aligned.m16n8k8.row.col.f32.tf32.tf32.f32 "
        "{%0,%1,%2,%3}, {%4,%5,%6,%7}, {%8,%9}, {%0,%1,%2,%3};\n"
        : "+f"(d[0]), "+f"(d[1]), "+f"(d[2]), "+f"(d[3])
        : "r"(a[0]), "r"(a[1]), "r"(a[2]), "r"(a[3]), "r"(b0), "r"(b1));
}

// ---------------- mask canonicalization (dtype auto-detect) ----------------
__global__ void mask_prep(const unsigned char* __restrict__ m){
    __shared__ int s_big, s_odd;
    int tid = threadIdx.x;
    if (tid == 0){ s_big = 0; s_odd = 0; }
    __syncthreads();
    int big = 0, odd = 0;
    for (int i = tid; i < NN; i += blockDim.x){
        unsigned char v = m[i];
        if (v > 1) big = 1;
        if ((i & 3) && v) odd = 1;
    }
    if (big) s_big = 1;
    if (odd) s_odd = 1;
    __syncthreads();
    if (s_big){
        const float* mf = (const float*)m;
        for (int i = tid; i < NN; i += blockDim.x) g_mask[i] = (mf[i] != 0.f) ? 1 : 0;
    } else if (s_odd){
        for (int i = tid; i < NN; i += blockDim.x) g_mask[i] = m[i] ? 1 : 0;
    } else {
        const int* mi = (const int*)m;
        for (int i = tid; i < NN; i += blockDim.x) g_mask[i] = mi[i] ? 1 : 0;
    }
}

// ---------------- tiny setup kernels ----------------
__global__ void setup_offsets(const int* __restrict__ lengths){
    if (threadIdx.x == 0){
        int s = 0;
        for (int b = 0; b < BB; b++){ g_off[b] = s; s += lengths[b]; }
        g_off[BB] = s;
    }
}

__global__ void node_prep(const float* __restrict__ H0, const float* __restrict__ X0,
                          const float* __restrict__ H1, const float* __restrict__ X1,
                          const float* __restrict__ cond, const float* __restrict__ tg)
{
    int i = blockIdx.x;
    int k = threadIdx.x;
    __shared__ float t_sh; __shared__ int m_sh;
    if (k == 0){
        int b = 0;
        while (b + 1 < BB && g_off[b+1] <= i) b++;
        t_sh = tg[b];
        m_sh = g_mask[i];
    }
    __syncthreads();
    float t = t_sh; int m = m_sh;
    if (k < 64){
        float h0 = H0[i*64+k], h1 = H1[i*64+k];
        g_Hin[i*320 + k] = m ? (1.f - t)*h0 + t*h1 : h1;
        float f = expf(-logf(10000.f) * (float)k / 63.f);
        float ang = t * f;
        g_Hin[i*320 + 192 + k] = sinf(ang);
        g_Hin[i*320 + 256 + k] = cosf(ang);
    }
    g_Hin[i*320 + 64 + k] = cond[i*128 + k];
    if (k < 3){
        float x0 = X0[i*3+k], x1 = X1[i*3+k];
        g_X[0][i*3+k] = m ? (1.f - t)*x0 + t*x1 : x1;
    }
}

__global__ void prep_edge(const float* __restrict__ We1, const float* __restrict__ be1,
                          const float* __restrict__ etable, int l)
{
    int k = threadIdx.x;  // 128
    const float* W = We1 + (size_t)l*289*128;
    g_wd2[k] = W[256*128 + k];
    for (int t = 0; t < 2; t++){
        float s = be1[l*128 + k];
        for (int e = 0; e < 32; e++) s += etable[t*32 + e] * W[(257 + e)*128 + k];
        g_etab[t*128 + k] = s;
    }
}

// ---------------- node GEMM: register-tiled + software pipelined ----------
template<int NOUT>
__global__ void __launch_bounds__(128, 4) gemm16(
    const float* __restrict__ A1, int K1,
    const float* __restrict__ A2, int K2,
    const float* __restrict__ W,
    const float* __restrict__ bias,
    const float* __restrict__ resid,
    float* __restrict__ out,
    int act)
{
    constexpr int NC4 = NOUT / 4;
    constexpr int TR  = 128 / NC4;
    constexpr int R   = 16 / TR;
    constexpr int WV  = (32 * NC4) / 128;     // float4 per thread for W tile
    __shared__ float As[16][33];
    __shared__ float Ws[32 * NOUT];

    int tid = threadIdx.x;
    int tx  = tid % NC4;
    int ty  = tid / NC4;
    int c0  = tx * 4;
    int r0  = ty * R;
    int gr0 = blockIdx.x * 16;
    int K   = K1 + K2;

    float acc[R][4];
#pragma unroll
    for (int i = 0; i < R; i++)
#pragma unroll
        for (int j = 0; j < 4; j++) acc[i][j] = 0.f;

    int srow = tid >> 3;
    int skc  = tid & 7;

    float4 aReg;
    float4 wReg[WV];
    {
        int k = skc * 4;
        int g = gr0 + srow;
        aReg = (k < K1) ? *(const float4*)&A1[(size_t)g*K1 + k]
                        : *(const float4*)&A2[(size_t)g*K2 + (k - K1)];
        const float4* Wg = (const float4*)W;
#pragma unroll
        for (int i = 0; i < WV; i++) wReg[i] = Wg[tid + i*128];
    }

    for (int k0 = 0; k0 < K; k0 += 32){
        As[srow][skc*4 + 0] = aReg.x;
        As[srow][skc*4 + 1] = aReg.y;
        As[srow][skc*4 + 2] = aReg.z;
        As[srow][skc*4 + 3] = aReg.w;
#pragma unroll
        for (int i = 0; i < WV; i++) ((float4*)Ws)[tid + i*128] = wReg[i];
        __syncthreads();

        if (k0 + 32 < K){
            int k = k0 + 32 + skc * 4;
            int g = gr0 + srow;
            aReg = (k < K1) ? *(const float4*)&A1[(size_t)g*K1 + k]
                            : *(const float4*)&A2[(size_t)g*K2 + (k - K1)];
            const float4* Wg = (const float4*)(W + (size_t)(k0 + 32) * NOUT);
#pragma unroll
            for (int i = 0; i < WV; i++) wReg[i] = Wg[tid + i*128];
        }

#pragma unroll
        for (int kk = 0; kk < 32; kk++){
            float4 w = *(const float4*)&Ws[kk*NOUT + c0];
            float a[R];
#pragma unroll
            for (int i = 0; i < R; i++) a[i] = As[r0 + i][kk];
#pragma unroll
            for (int i = 0; i < R; i++){
                acc[i][0] += a[i]*w.x; acc[i][1] += a[i]*w.y;
                acc[i][2] += a[i]*w.z; acc[i][3] += a[i]*w.w;
            }
        }
        __syncthreads();
    }

    float4 bv = make_float4(0.f,0.f,0.f,0.f);
    if (bias) bv = *(const float4*)&bias[c0];
#pragma unroll
    for (int i = 0; i < R; i++){
        int g = gr0 + r0 + i;
        float4 v;
        v.x = acc[i][0] + bv.x; v.y = acc[i][1] + bv.y;
        v.z = acc[i][2] + bv.z; v.w = acc[i][3] + bv.w;
        if (act == 1){
            v.x = fmaxf(v.x,0.f); v.y = fmaxf(v.y,0.f);
            v.z = fmaxf(v.z,0.f); v.w = fmaxf(v.w,0.f);
        } else if (act == 2){
            v.x = silu_f(v.x); v.y = silu_f(v.y);
            v.z = silu_f(v.z); v.w = silu_f(v.w);
        }
        if (resid){
            float4 rv = *(const float4*)&resid[(size_t)g*NOUT + c0];
            v.x += rv.x; v.y += rv.y; v.z += rv.z; v.w += rv.w;
        }
        *(float4*)&out[(size_t)g*NOUT + c0] = v;
    }
}

// ---------------- fused edge kernel (tensor-core tf32 GEMM) ----------------
// smem float offsets
#define S_M1    0                 // 96 x 132 (m1 tf32, reused as m2 fp32)
#define S_W2    (96*132)          // 128 x 136 (W2 tf32)
#define S_AS    (S_W2 + 128*136)  // 128
#define S_WD2   (S_AS + 128)
#define S_ETAB  (S_WD2 + 128)     // 256
#define S_BE2   (S_ETAB + 256)
#define S_WX    (S_BE2 + 128)
#define S_REL   (S_WX + 128)      // 96*4
#define S_COEF  (S_REL + 384)     // 96
#define S_COEFP (S_COEF + 96)     // 4*96
#define S_COL   (S_COEFP + 384)   // 96 ints
#define S_ET    (S_COL + 96)      // 96 ints
#define S_TOTF  (S_ET + 96)
#define SMEM_BYTES (S_TOTF*4)

__global__ void __launch_bounds__(256, 1) edge_kernel(
    const float* __restrict__ aG, const float* __restrict__ bG,
    const float* __restrict__ Xin, float* __restrict__ Xout,
    float* __restrict__ aggG,
    const int* __restrict__ ecol, const int* __restrict__ chain,
    const float* __restrict__ W2g, const float* __restrict__ be2g,
    const float* __restrict__ Wxg)
{
    extern __shared__ float sm[];
    float* M1     = sm + S_M1;    // stride 132
    float* W2     = sm + S_W2;    // stride 136
    float* a_s    = sm + S_AS;
    float* wd2_s  = sm + S_WD2;
    float* etab_s = sm + S_ETAB;
    float* be2_s  = sm + S_BE2;
    float* Wx_s   = sm + S_WX;
    float* rel_s  = sm + S_REL;
    float* coef_s = sm + S_COEF;
    float* coefp  = sm + S_COEFP;
    int*   col_s  = (int*)(sm + S_COL);
    int*   et_s   = (int*)(sm + S_ET);

    int r = blockIdx.x;
    int tid = threadIdx.x;

    // stage W2 -> smem as tf32, stride 136
    for (int i = tid; i < 128*32; i += 256){
        int row = i >> 5, cg = (i & 31);
        float4 v = ((const float4*)W2g)[row*32 + cg];
        float* dst = &W2[row*136 + cg*4];
        float4 p;
        p.x = __uint_as_float(f2tf32(v.x));
        p.y = __uint_as_float(f2tf32(v.y));
        p.z = __uint_as_float(f2tf32(v.z));
        p.w = __uint_as_float(f2tf32(v.w));
        *(float4*)dst = p;
    }
    if (tid < 128){
        a_s[tid]       = aG[r*128 + tid];
        wd2_s[tid]     = g_wd2[tid];
        etab_s[tid]    = g_etab[tid];
        etab_s[128+tid]= g_etab[128 + tid];
        be2_s[tid]     = be2g[tid];
        Wx_s[tid]      = Wxg[tid];
    }
    float xr0 = Xin[r*3], xr1 = Xin[r*3+1], xr2 = Xin[r*3+2];
    int chr = chain[r];
    if (tid < 96){
        int c = ecol[r*96 + tid];
        col_s[tid] = c;
        float dx = xr0 - Xin[c*3], dy = xr1 - Xin[c*3+1], dz = xr2 - Xin[c*3+2];
        rel_s[tid*4]   = dx;
        rel_s[tid*4+1] = dy;
        rel_s[tid*4+2] = dz;
        rel_s[tid*4+3] = dx*dx + dy*dy + dz*dz;
        et_s[tid] = (chain[c] != chr) ? 1 : 0;
    }
    __syncthreads();

    // phase 1: m1[j][k] = silu(a[r]+b[col]+d2*wd2+etab[type]) -> tf32 smem
    for (int idx = tid; idx < 96*32; idx += 256){
        int j = idx >> 5, k = (idx & 31) * 4;
        int c = col_s[j];
        float4 bn = *(const float4*)&bG[(size_t)c*128 + k];
        float d2 = rel_s[j*4+3];
        const float* et = etab_s + et_s[j]*128;
        float4 p;
        p.x = silu_f(a_s[k+0] + bn.x + d2*wd2_s[k+0] + et[k+0]);
        p.y = silu_f(a_s[k+1] + bn.y + d2*wd2_s[k+1] + et[k+1]);
        p.z = silu_f(a_s[k+2] + bn.z + d2*wd2_s[k+2] + et[k+2]);
        p.w = silu_f(a_s[k+3] + bn.w + d2*wd2_s[k+3] + et[k+3]);
        p.x = __uint_as_float(f2tf32(p.x));
        p.y = __uint_as_float(f2tf32(p.y));
        p.z = __uint_as_float(f2tf32(p.z));
        p.w = __uint_as_float(f2tf32(p.w));
        *(float4*)&M1[j*132 + k] = p;
    }
    __syncthreads();

    // phase 2: 96x128 @ 128x128 on tensor pipe (m16n8k8 tf32)
    // warp grid 2(m) x 4(n): warp tile 48x32
    int w  = tid >> 5, lane = tid & 31;
    int wr = w >> 2, wc = w & 3;
    int mr = wr * 48, nc0 = wc * 32;
    int gq = lane >> 2, lq = lane & 3;

    float acc[3][4][4];
#pragma unroll
    for (int mt = 0; mt < 3; mt++)
#pragma unroll
        for (int nt = 0; nt < 4; nt++)
#pragma unroll
            for (int q = 0; q < 4; q++) acc[mt][nt][q] = 0.f;

#pragma unroll 4
    for (int k0 = 0; k0 < 128; k0 += 8){
        unsigned afr[3][4];
#pragma unroll
        for (int mt = 0; mt < 3; mt++){
            int rr = mr + mt*16 + gq;
            afr[mt][0] = __float_as_uint(M1[rr*132      + k0 + lq]);
            afr[mt][1] = __float_as_uint(M1[(rr+8)*132  + k0 + lq]);
            afr[mt][2] = __float_as_uint(M1[rr*132      + k0 + lq + 4]);
            afr[mt][3] = __float_as_uint(M1[(rr+8)*132  + k0 + lq + 4]);
        }
#pragma unroll
        for (int nt = 0; nt < 4; nt++){
            int n = nc0 + nt*8 + gq;
            unsigned b0 = __float_as_uint(W2[(k0 + lq)*136 + n]);
            unsigned b1 = __float_as_uint(W2[(k0 + lq + 4)*136 + n]);
#pragma unroll
            for (int mt = 0; mt < 3; mt++)
                mma_tf32(acc[mt][nt], afr[mt], b0, b1);
        }
    }
    __syncthreads();   // all A/B smem reads complete before m2 overwrite

    // epilogue: bias + silu, write m2 to smem (reuse M1), coef partials
    float cf[3][2] = {{0.f,0.f},{0.f,0.f},{0.f,0.f}};
#pragma unroll
    for (int mt = 0; mt < 3; mt++){
        int rr = mr + mt*16 + gq;
#pragma unroll
        for (int nt = 0; nt < 4; nt++){
            int col = nc0 + nt*8 + lq*2;
            float wx0 = Wx_s[col], wx1 = Wx_s[col+1];
            float b0 = be2_s[col], b1 = be2_s[col+1];
            float v0 = silu_f(acc[mt][nt][0] + b0);
            float v1 = silu_f(acc[mt][nt][1] + b1);
            float v2 = silu_f(acc[mt][nt][2] + b0);
            float v3 = silu_f(acc[mt][nt][3] + b1);
            M1[rr*132 + col]       = v0;
            M1[rr*132 + col + 1]   = v1;
            M1[(rr+8)*132 + col]   = v2;
            M1[(rr+8)*132 + col+1] = v3;
            cf[mt][0] += v0*wx0 + v1*wx1;
            cf[mt][1] += v2*wx0 + v3*wx1;
        }
    }
#pragma unroll
    for (int mt = 0; mt < 3; mt++){
#pragma unroll
        for (int h = 0; h < 2; h++){
            float c = cf[mt][h];
            c += __shfl_xor_sync(0xffffffffu, c, 1);
            c += __shfl_xor_sync(0xffffffffu, c, 2);
            if (lq == 0) coefp[wc*96 + mr + mt*16 + h*8 + gq] = c;
        }
    }
    __syncthreads();

    if (tid < 96)
        coef_s[tid] = coefp[tid] + coefp[96+tid] + coefp[192+tid] + coefp[288+tid];
    __syncthreads();

    if (tid < 128){
        float s = 0.f;
#pragma unroll 8
        for (int j = 0; j < 96; j++) s += M1[j*132 + tid];
        aggG[(size_t)r*128 + tid] = s;
    }
    if (tid < 3){
        float s = 0.f;
        for (int j = 0; j < 96; j++) s += coef_s[j] * rel_s[j*4 + tid];
        Xout[r*3 + tid] = Xin[r*3 + tid] + s;
    }
}

// ---------------- losses ----------------
__global__ void loss_partial(const float* __restrict__ H0, const float* __restrict__ H1,
                             const float* __restrict__ X0, const float* __restrict__ X1,
                             const int* __restrict__ shiftp,
                             const float* __restrict__ Xf)
{
    __shared__ float red[256];
    float s[5] = {0,0,0,0,0};
    int shift = *shiftp;
    for (int i = blockIdx.x*blockDim.x + threadIdx.x; i < NN; i += gridDim.x*blockDim.x){
        if (!g_mask[i]) continue;
        int j = (i + shift) % NN; if (j < 0) j += NN;
        float hp = 0.f, hn = 0.f;
        for (int k = 0; k < 64; k++){
            float p = g_vH[i*64 + k];
            float d  = p - (H1[i*64+k] - H0[i*64+k]); hp += d*d;
            float dn = p - (H1[j*64+k] - H0[j*64+k]); hn += dn*dn;
        }
        float xp = 0.f, xn = 0.f;
        for (int k = 0; k < 3; k++){
            float p = Xf[i*3 + k];
            float d  = p - (X1[i*3+k] - X0[i*3+k]); xp += d*d;
            float dn = p - (X1[j*3+k] - X0[j*3+k]); xn += dn*dn;
        }
        s[0] += hp; s[1] += xp; s[2] += hn; s[3] += xn; s[4] += 1.f;
    }
    for (int q = 0; q < 5; q++){
        red[threadIdx.x] = s[q]; __syncthreads();
        for (int d = 128; d > 0; d >>= 1){
            if (threadIdx.x < d) red[threadIdx.x] += red[threadIdx.x + d];
            __syncthreads();
        }
        if (threadIdx.x == 0) g_lpart[blockIdx.x*5 + q] = red[0];
        __syncthreads();
    }
}

__global__ void loss_final(float* __restrict__ out, int nb){
    if (threadIdx.x == 0){
        float s[5] = {0,0,0,0,0};
        for (int b = 0; b < nb; b++)
            for (int q = 0; q < 5; q++) s[q] += g_lpart[b*5 + q];
        float msum = s[4] + 1e-8f;
        float lHp = s[0]/msum, lXp = s[1]/msum, lHn = s[2]/msum, lXn = s[3]/msum;
        out[0] = lHp - 0.05f*lHn;
        out[1] = lXp - 0.05f*lXn;
        out[2] = lHp; out[3] = lXp; out[4] = lHn; out[5] = lXn;
    }
}

// ---------------- host launch ----------------
extern "C" void kernel_launch(void* const* d_in, const int* in_sizes, int n_in,
                              void* d_out, int out_size)
{
    (void)in_sizes; (void)n_in; (void)out_size;
    const float* H0    = (const float*)d_in[0];
    const float* X0    = (const float*)d_in[1];
    const float* H1    = (const float*)d_in[2];
    const float* X1    = (const float*)d_in[3];
    const float* cond  = (const float*)d_in[4];
    const float* tg    = (const float*)d_in[5];
    const float* Wi1   = (const float*)d_in[6];
    const float* bi1   = (const float*)d_in[7];
    const float* Wi2   = (const float*)d_in[8];
    const float* bi2   = (const float*)d_in[9];
    const float* Wi3   = (const float*)d_in[10];
    const float* bi3   = (const float*)d_in[11];
    const float* etab  = (const float*)d_in[12];
    const float* We1   = (const float*)d_in[13];
    const float* be1   = (const float*)d_in[14];
    const float* We2   = (const float*)d_in[15];
    const float* be2   = (const float*)d_in[16];
    const float* Wx    = (const float*)d_in[17];
    const float* Wh1   = (const float*)d_in[18];
    const float* bh1   = (const float*)d_in[19];
    const float* Wh2   = (const float*)d_in[20];
    const float* bh2   = (const float*)d_in[21];
    const float* Wout  = (const float*)d_in[22];
    const float* bout  = (const float*)d_in[23];
    const int*   edges = (const int*)d_in[24];
    const int*   chain = (const int*)d_in[25];
    const unsigned char* mask = (const unsigned char*)d_in[26];
    const int*   lengths = (const int*)d_in[27];
    const int*   shiftp  = (const int*)d_in[28];
    const int*   ecol = edges + EE;

    float *p_Hin, *p_h, *p_tmp, *p_a, *p_bn, *p_agg, *p_X, *p_vH;
    cudaGetSymbolAddress((void**)&p_Hin, g_Hin);
    cudaGetSymbolAddress((void**)&p_h,   g_h);
    cudaGetSymbolAddress((void**)&p_tmp, g_tmp);
    cudaGetSymbolAddress((void**)&p_a,   g_a);
    cudaGetSymbolAddress((void**)&p_bn,  g_bn);
    cudaGetSymbolAddress((void**)&p_agg, g_agg);
    cudaGetSymbolAddress((void**)&p_X,   g_X);
    cudaGetSymbolAddress((void**)&p_vH,  g_vH);

    cudaFuncSetAttribute(edge_kernel,
                         cudaFuncAttributeMaxDynamicSharedMemorySize, SMEM_BYTES);

    mask_prep<<<1, 256>>>(mask);
    setup_offsets<<<1, 32>>>(lengths);
    node_prep<<<NN, 128>>>(H0, X0, H1, X1, cond, tg);

    // input MLP: 320 -> 128 (relu) -> 128 (relu) -> 128
    gemm16<128><<<192, 128>>>(p_Hin, 320, nullptr, 0, Wi1, bi1, nullptr, p_h,   1);
    gemm16<128><<<192, 128>>>(p_h,   128, nullptr, 0, Wi2, bi2, nullptr, p_tmp, 1);
    gemm16<128><<<192, 128>>>(p_tmp, 128, nullptr, 0, Wi3, bi3, nullptr, p_h,   0);

    int cur = 0;
    for (int l = 0; l < 3; l++){
        const float* We1l = We1 + (size_t)l*289*128;
        prep_edge<<<1, 128>>>(We1, be1, etab, l);
        gemm16<128><<<192, 128>>>(p_h, 128, nullptr, 0, We1l,           nullptr, nullptr, p_a,  0);
        gemm16<128><<<192, 128>>>(p_h, 128, nullptr, 0, We1l + 128*128, nullptr, nullptr, p_bn, 0);
        edge_kernel<<<NN, 256, SMEM_BYTES>>>(p_a, p_bn,
                                             p_X + cur*NN*3, p_X + (1-cur)*NN*3,
                                             p_agg, ecol, chain,
                                             We2 + (size_t)l*128*128,
                                             be2 + l*128, Wx + l*128);
        cur = 1 - cur;
        gemm16<128><<<192, 128>>>(p_h,   128, p_agg, 128, Wh1 + (size_t)l*256*128,
                                  bh1 + l*128, nullptr, p_tmp, 2);
        gemm16<128><<<192, 128>>>(p_tmp, 128, nullptr, 0,  Wh2 + (size_t)l*128*128,
                                  bh2 + l*128, p_h, p_h, 0);
    }

    gemm16<64><<<192, 128>>>(p_h, 128, nullptr, 0, Wout, bout, nullptr, p_vH, 0);

    loss_partial<<<12, 256>>>(H0, H1, X0, X1, shiftp, p_X + cur*NN*3);
    loss_final<<<1, 32>>>((float*)d_out, 12);
}

// round 5
// speedup vs baseline: 3.1881x; 1.2299x over previous
#include <cuda_runtime.h>
#include <math.h>

#define NN 3072
#define BB 32
#define LL 96
#define EE (NN*LL)
#define HIDD 128
#define LATD 64

// ---------------- device scratch (no allocations allowed) ----------------
__device__ float g_Hin[NN*320];
__device__ float g_h[NN*HIDD];
__device__ float g_tmp[NN*HIDD];
__device__ float g_a[NN*HIDD];
__device__ float g_bn[NN*HIDD];
__device__ float g_agg[NN*HIDD];
__device__ float g_X[2][NN*3];
__device__ float g_vH[NN*LATD];
__device__ float g_wd2[HIDD];
__device__ float g_etab[2*HIDD];
__device__ int   g_off[BB+1];
__device__ int   g_mask[NN];
__device__ float g_lpart[64*5];

__device__ __forceinline__ float silu_f(float v){
    return __fdividef(v, 1.f + __expf(-v));
}
__device__ __forceinline__ unsigned f2tf32(float f){
    unsigned r; asm("cvt.rna.tf32.f32 %0, %1;" : "=r"(r) : "f"(f)); return r;
}
__device__ __forceinline__ void mma_tf32(float (&d)[4], const unsigned (&a)[4],
                                         unsigned b0, unsigned b1){
    asm volatile("mma.sync.aligned.m16n8k8.row.col.f32.tf32.tf32.f32 "
        "{%0,%1,%2,%3}, {%4,%5,%6,%7}, {%8,%9}, {%0,%1,%2,%3};\n"
        : "+f"(d[0]), "+f"(d[1]), "+f"(d[2]), "+f"(d[3])
        : "r"(a[0]), "r"(a[1]), "r"(a[2]), "r"(a[3]), "r"(b0), "r"(b1));
}
__device__ __forceinline__ unsigned sptr(const void* p){
    return (unsigned)__cvta_generic_to_shared(p);
}
__device__ __forceinline__ void cpa16(unsigned dst, const void* src){
    asm volatile("cp.async.cg.shared.global [%0], [%1], 16;\n" :: "r"(dst), "l"(src));
}
__device__ __forceinline__ void cpa_commit(){
    asm volatile("cp.async.commit_group;\n" ::: "memory");
}
template<int N> __device__ __forceinline__ void cpa_wait(){
    asm volatile("cp.async.wait_group %0;\n" :: "n"(N) : "memory");
}

// ---------------- mask canonicalization (dtype auto-detect) ----------------
__global__ void mask_prep(const unsigned char* __restrict__ m){
    __shared__ int s_big, s_odd;
    int tid = threadIdx.x;
    if (tid == 0){ s_big = 0; s_odd = 0; }
    __syncthreads();
    int big = 0, odd = 0;
    for (int i = tid; i < NN; i += blockDim.x){
        unsigned char v = m[i];
        if (v > 1) big = 1;
        if ((i & 3) && v) odd = 1;
    }
    if (big) s_big = 1;
    if (odd) s_odd = 1;
    __syncthreads();
    if (s_big){
        const float* mf = (const float*)m;
        for (int i = tid; i < NN; i += blockDim.x) g_mask[i] = (mf[i] != 0.f) ? 1 : 0;
    } else if (s_odd){
        for (int i = tid; i < NN; i += blockDim.x) g_mask[i] = m[i] ? 1 : 0;
    } else {
        const int* mi = (const int*)m;
        for (int i = tid; i < NN; i += blockDim.x) g_mask[i] = mi[i] ? 1 : 0;
    }
}

// ---------------- tiny setup kernels ----------------
__global__ void setup_offsets(const int* __restrict__ lengths){
    if (threadIdx.x == 0){
        int s = 0;
        for (int b = 0; b < BB; b++){ g_off[b] = s; s += lengths[b]; }
        g_off[BB] = s;
    }
}

__global__ void node_prep(const float* __restrict__ H0, const float* __restrict__ X0,
                          const float* __restrict__ H1, const float* __restrict__ X1,
                          const float* __restrict__ cond, const float* __restrict__ tg)
{
    int i = blockIdx.x;
    int k = threadIdx.x;
    __shared__ float t_sh; __shared__ int m_sh;
    if (k == 0){
        int b = 0;
        while (b + 1 < BB && g_off[b+1] <= i) b++;
        t_sh = tg[b];
        m_sh = g_mask[i];
    }
    __syncthreads();
    float t = t_sh; int m = m_sh;
    if (k < 64){
        float h0 = H0[i*64+k], h1 = H1[i*64+k];
        g_Hin[i*320 + k] = m ? (1.f - t)*h0 + t*h1 : h1;
        float f = expf(-logf(10000.f) * (float)k / 63.f);
        float ang = t * f;
        g_Hin[i*320 + 192 + k] = sinf(ang);
        g_Hin[i*320 + 256 + k] = cosf(ang);
    }
    g_Hin[i*320 + 64 + k] = cond[i*128 + k];
    if (k < 3){
        float x0 = X0[i*3+k], x1 = X1[i*3+k];
        g_X[0][i*3+k] = m ? (1.f - t)*x0 + t*x1 : x1;
    }
}

__global__ void prep_edge(const float* __restrict__ We1, const float* __restrict__ be1,
                          const float* __restrict__ etable, int l)
{
    int k = threadIdx.x;  // 128
    const float* W = We1 + (size_t)l*289*128;
    g_wd2[k] = W[256*128 + k];
    for (int t = 0; t < 2; t++){
        float s = be1[l*128 + k];
        for (int e = 0; e < 32; e++) s += etable[t*32 + e] * W[(257 + e)*128 + k];
        g_etab[t*128 + k] = s;
    }
}

// ---------------- node GEMM: 24 rows/CTA, cp.async pipelined -------------
// out[24 x NOUT] = act(concat(A1,A2)[24 x K] @ W[K x NOUT] + bias) (+resid)
template<int NOUT>
__global__ void __launch_bounds__(128, 4) gemm16(
    const float* __restrict__ A1, int K1,
    const float* __restrict__ A2, int K2,
    const float* __restrict__ W,
    const float* __restrict__ bias,
    const float* __restrict__ resid,
    float* __restrict__ out, int act)
{
    constexpr int ROWS = 24;
    constexpr int NC4  = NOUT / 4;
    constexpr int TR   = 128 / NC4;
    constexpr int R    = ROWS / TR;
    __shared__ float As[2][ROWS*32];
    __shared__ float Ws[2][32*NOUT];

    int tid = threadIdx.x;
    int tx = tid % NC4, ty = tid / NC4;
    int c0 = tx*4, r0 = ty*R;
    int gr0 = blockIdx.x * ROWS;
    int K = K1 + K2;
    int ntiles = K >> 5;

    float acc[R][4];
#pragma unroll
    for (int i = 0; i < R; i++)
#pragma unroll
        for (int j = 0; j < 4; j++) acc[i][j] = 0.f;

    // issue tile 0
    {
        for (int i = tid; i < ROWS*8; i += 128){
            int row = i >> 3, kc = i & 7;
            int k = kc*4;
            int g = gr0 + row;
            const float* src = (k < K1) ? A1 + (size_t)g*K1 + k
                                        : A2 + (size_t)g*K2 + (k - K1);
            cpa16(sptr(&As[0][row*32 + kc*4]), src);
        }
        for (int i = tid; i < 8*NOUT; i += 128)
            cpa16(sptr(&Ws[0][i*4]), W + (size_t)i*4);
        cpa_commit();
    }

    for (int t = 0; t < ntiles; t++){
        int b = t & 1;
        if (t + 1 < ntiles){
            int nb = b ^ 1;
            for (int i = tid; i < ROWS*8; i += 128){
                int row = i >> 3, kc = i & 7;
                int k = (t+1)*32 + kc*4;
                int g = gr0 + row;
                const float* src = (k < K1) ? A1 + (size_t)g*K1 + k
                                            : A2 + (size_t)g*K2 + (k - K1);
                cpa16(sptr(&As[nb][row*32 + kc*4]), src);
            }
            const float* Wt = W + (size_t)(t+1)*32*NOUT;
            for (int i = tid; i < 8*NOUT; i += 128)
                cpa16(sptr(&Ws[nb][i*4]), Wt + (size_t)i*4);
            cpa_commit();
            cpa_wait<1>();
        } else {
            cpa_wait<0>();
        }
        __syncthreads();
        const float* as = As[b];
        const float* ws = Ws[b];
#pragma unroll
        for (int kk = 0; kk < 32; kk++){
            float4 w = *(const float4*)&ws[kk*NOUT + c0];
            float a[R];
#pragma unroll
            for (int i = 0; i < R; i++) a[i] = as[(r0+i)*32 + kk];
#pragma unroll
            for (int i = 0; i < R; i++){
                acc[i][0] += a[i]*w.x; acc[i][1] += a[i]*w.y;
                acc[i][2] += a[i]*w.z; acc[i][3] += a[i]*w.w;
            }
        }
        __syncthreads();
    }

    float4 bv = make_float4(0.f,0.f,0.f,0.f);
    if (bias) bv = *(const float4*)&bias[c0];
#pragma unroll
    for (int i = 0; i < R; i++){
        int g = gr0 + r0 + i;
        float4 v;
        v.x = acc[i][0] + bv.x; v.y = acc[i][1] + bv.y;
        v.z = acc[i][2] + bv.z; v.w = acc[i][3] + bv.w;
        if (act == 1){
            v.x = fmaxf(v.x,0.f); v.y = fmaxf(v.y,0.f);
            v.z = fmaxf(v.z,0.f); v.w = fmaxf(v.w,0.f);
        } else if (act == 2){
            v.x = silu_f(v.x); v.y = silu_f(v.y);
            v.z = silu_f(v.z); v.w = silu_f(v.w);
        }
        if (resid){
            float4 rv = *(const float4*)&resid[(size_t)g*NOUT + c0];
            v.x += rv.x; v.y += rv.y; v.z += rv.z; v.w += rv.w;
        }
        *(float4*)&out[(size_t)g*NOUT + c0] = v;
    }
}

// dual-output node GEMM: outA = A@WA, outB = A@WB (K=128, NOUT=128, no bias/act)
__global__ void __launch_bounds__(128, 2) gemm16_dual(
    const float* __restrict__ A,
    const float* __restrict__ WA, const float* __restrict__ WB,
    float* __restrict__ outA, float* __restrict__ outB)
{
    constexpr int ROWS = 24;
    __shared__ float As[2][ROWS*32];
    __shared__ float WsA[2][32*128];
    __shared__ float WsB[2][32*128];

    int tid = threadIdx.x;
    int tx = tid % 32, ty = tid / 32;
    int c0 = tx*4, r0 = ty*6;
    int gr0 = blockIdx.x * ROWS;

    float accA[6][4], accB[6][4];
#pragma unroll
    for (int i = 0; i < 6; i++)
#pragma unroll
        for (int j = 0; j < 4; j++){ accA[i][j] = 0.f; accB[i][j] = 0.f; }

    {
        for (int i = tid; i < ROWS*8; i += 128){
            int row = i >> 3, kc = i & 7;
            cpa16(sptr(&As[0][row*32 + kc*4]), A + (size_t)(gr0+row)*128 + kc*4);
        }
        for (int i = tid; i < 1024; i += 128){
            cpa16(sptr(&WsA[0][i*4]), WA + (size_t)i*4);
            cpa16(sptr(&WsB[0][i*4]), WB + (size_t)i*4);
        }
        cpa_commit();
    }

    for (int t = 0; t < 4; t++){
        int b = t & 1;
        if (t + 1 < 4){
            int nb = b ^ 1;
            for (int i = tid; i < ROWS*8; i += 128){
                int row = i >> 3, kc = i & 7;
                cpa16(sptr(&As[nb][row*32 + kc*4]),
                      A + (size_t)(gr0+row)*128 + (t+1)*32 + kc*4);
            }
            const float* wa = WA + (size_t)(t+1)*32*128;
            const float* wb = WB + (size_t)(t+1)*32*128;
            for (int i = tid; i < 1024; i += 128){
                cpa16(sptr(&WsA[nb][i*4]), wa + (size_t)i*4);
                cpa16(sptr(&WsB[nb][i*4]), wb + (size_t)i*4);
            }
            cpa_commit();
            cpa_wait<1>();
        } else {
            cpa_wait<0>();
        }
        __syncthreads();
        const float* as = As[b];
        const float* wsa = WsA[b];
        const float* wsb = WsB[b];
#pragma unroll
        for (int kk = 0; kk < 32; kk++){
            float4 wa = *(const float4*)&wsa[kk*128 + c0];
            float4 wb = *(const float4*)&wsb[kk*128 + c0];
            float a[6];
#pragma unroll
            for (int i = 0; i < 6; i++) a[i] = as[(r0+i)*32 + kk];
#pragma unroll
            for (int i = 0; i < 6; i++){
                accA[i][0] += a[i]*wa.x; accA[i][1] += a[i]*wa.y;
                accA[i][2] += a[i]*wa.z; accA[i][3] += a[i]*wa.w;
                accB[i][0] += a[i]*wb.x; accB[i][1] += a[i]*wb.y;
                accB[i][2] += a[i]*wb.z; accB[i][3] += a[i]*wb.w;
            }
        }
        __syncthreads();
    }
#pragma unroll
    for (int i = 0; i < 6; i++){
        int g = gr0 + r0 + i;
        *(float4*)&outA[(size_t)g*128 + c0] = make_float4(accA[i][0],accA[i][1],accA[i][2],accA[i][3]);
        *(float4*)&outB[(size_t)g*128 + c0] = make_float4(accB[i][0],accB[i][1],accB[i][2],accB[i][3]);
    }
}

// ---------------- persistent fused edge kernel ----------------------------
#define S_M1    0                 // 96 x 132 (m1 tf32, reused as m2 fp32)
#define S_W2    (96*132)          // 128 x 136 (W2 tf32)
#define S_AS    (S_W2 + 128*136)  // 128
#define S_WD2   (S_AS + 128)
#define S_ETAB  (S_WD2 + 128)     // 256
#define S_BE2   (S_ETAB + 256)
#define S_WX    (S_BE2 + 128)
#define S_REL   (S_WX + 128)      // 96*4
#define S_COEF  (S_REL + 384)     // 96
#define S_COEFP (S_COEF + 96)     // 4*96
#define S_AGGP  (S_COEFP + 384)   // 2*128
#define S_COL   (S_AGGP + 256)    // 96 ints
#define S_ET    (S_COL + 96)      // 96 ints
#define S_TOTF  (S_ET + 96)
#define SMEM_BYTES (S_TOTF*4)

__global__ void __launch_bounds__(256, 1) edge_kernel(
    const float* __restrict__ aG, const float* __restrict__ bG,
    const float* __restrict__ Xin, float* __restrict__ Xout,
    float* __restrict__ aggG,
    const int* __restrict__ ecol, const int* __restrict__ chain,
    const float* __restrict__ W2g, const float* __restrict__ be2g,
    const float* __restrict__ Wxg)
{
    extern __shared__ float sm[];
    float* M1     = sm + S_M1;    // stride 132
    float* W2     = sm + S_W2;    // stride 136
    float* a_s    = sm + S_AS;
    float* wd2_s  = sm + S_WD2;
    float* etab_s = sm + S_ETAB;
    float* be2_s  = sm + S_BE2;
    float* Wx_s   = sm + S_WX;
    float* rel_s  = sm + S_REL;
    float* coef_s = sm + S_COEF;
    float* coefp  = sm + S_COEFP;
    float* aggp   = sm + S_AGGP;
    int*   col_s  = (int*)(sm + S_COL);
    int*   et_s   = (int*)(sm + S_ET);

    int tid = threadIdx.x;

    // ---- one-time staging: W2 (tf32, stride 136) + per-layer constants ----
    for (int i = tid; i < 128*32; i += 256){
        int row = i >> 5, cg = (i & 31);
        float4 v = ((const float4*)W2g)[row*32 + cg];
        float4 p;
        p.x = __uint_as_float(f2tf32(v.x));
        p.y = __uint_as_float(f2tf32(v.y));
        p.z = __uint_as_float(f2tf32(v.z));
        p.w = __uint_as_float(f2tf32(v.w));
        *(float4*)&W2[row*136 + cg*4] = p;
    }
    if (tid < 128){
        wd2_s[tid]     = g_wd2[tid];
        etab_s[tid]    = g_etab[tid];
        etab_s[128+tid]= g_etab[128 + tid];
        be2_s[tid]     = be2g[tid];
        Wx_s[tid]      = Wxg[tid];
    }

    int w  = tid >> 5, lane = tid & 31;
    int wr = w >> 2, wc = w & 3;
    int mr = wr * 48, nc0 = wc * 32;
    int gq = lane >> 2, lq = lane & 3;

    for (int r = blockIdx.x; r < NN; r += gridDim.x){
        // ---- per-node loads ----
        if (tid < 128) a_s[tid] = aG[(size_t)r*128 + tid];
        if (tid < 96){
            int c = ecol[r*96 + tid];
            col_s[tid] = c;
            float dx = Xin[r*3]   - Xin[c*3];
            float dy = Xin[r*3+1] - Xin[c*3+1];
            float dz = Xin[r*3+2] - Xin[c*3+2];
            rel_s[tid*4]   = dx;
            rel_s[tid*4+1] = dy;
            rel_s[tid*4+2] = dz;
            rel_s[tid*4+3] = dx*dx + dy*dy + dz*dz;
            et_s[tid] = (chain[c] != chain[r]) ? 1 : 0;
        }
        __syncthreads();

        // ---- phase 1: m1 = silu(a + b[col] + d2*wd2 + etab[type]) -> tf32 ----
        for (int idx = tid; idx < 96*32; idx += 256){
            int j = idx >> 5, k = (idx & 31) * 4;
            int c = col_s[j];
            float4 bn = *(const float4*)&bG[(size_t)c*128 + k];
            float d2 = rel_s[j*4+3];
            const float* et = etab_s + et_s[j]*128;
            float4 p;
            p.x = silu_f(a_s[k+0] + bn.x + d2*wd2_s[k+0] + et[k+0]);
            p.y = silu_f(a_s[k+1] + bn.y + d2*wd2_s[k+1] + et[k+1]);
            p.z = silu_f(a_s[k+2] + bn.z + d2*wd2_s[k+2] + et[k+2]);
            p.w = silu_f(a_s[k+3] + bn.w + d2*wd2_s[k+3] + et[k+3]);
            p.x = __uint_as_float(f2tf32(p.x));
            p.y = __uint_as_float(f2tf32(p.y));
            p.z = __uint_as_float(f2tf32(p.z));
            p.w = __uint_as_float(f2tf32(p.w));
            *(float4*)&M1[j*132 + k] = p;
        }
        __syncthreads();

        // ---- phase 2: tensor GEMM 96x128 @ 128x128, warp tile 48x32 ----
        float acc[3][4][4];
#pragma unroll
        for (int mt = 0; mt < 3; mt++)
#pragma unroll
            for (int nt = 0; nt < 4; nt++)
#pragma unroll
                for (int q = 0; q < 4; q++) acc[mt][nt][q] = 0.f;

#pragma unroll 4
        for (int k0 = 0; k0 < 128; k0 += 8){
            unsigned afr[3][4];
#pragma unroll
            for (int mt = 0; mt < 3; mt++){
                int rr = mr + mt*16 + gq;
                afr[mt][0] = __float_as_uint(M1[rr*132      + k0 + lq]);
                afr[mt][1] = __float_as_uint(M1[(rr+8)*132  + k0 + lq]);
                afr[mt][2] = __float_as_uint(M1[rr*132      + k0 + lq + 4]);
                afr[mt][3] = __float_as_uint(M1[(rr+8)*132  + k0 + lq + 4]);
            }
#pragma unroll
            for (int nt = 0; nt < 4; nt++){
                int n = nc0 + nt*8 + gq;
                unsigned b0 = __float_as_uint(W2[(k0 + lq)*136 + n]);
                unsigned b1 = __float_as_uint(W2[(k0 + lq + 4)*136 + n]);
#pragma unroll
                for (int mt = 0; mt < 3; mt++)
                    mma_tf32(acc[mt][nt], afr[mt], b0, b1);
            }
        }
        __syncthreads();   // M1 reads done before m2 overwrite

        // ---- epilogue: m2 = silu(acc + be2) -> M1; coef partials ----
        float cf[3][2] = {{0.f,0.f},{0.f,0.f},{0.f,0.f}};
#pragma unroll
        for (int mt = 0; mt < 3; mt++){
            int rr = mr + mt*16 + gq;
#pragma unroll
            for (int nt = 0; nt < 4; nt++){
                int col = nc0 + nt*8 + lq*2;
                float wx0 = Wx_s[col], wx1 = Wx_s[col+1];
                float b0 = be2_s[col], b1 = be2_s[col+1];
                float v0 = silu_f(acc[mt][nt][0] + b0);
                float v1 = silu_f(acc[mt][nt][1] + b1);
                float v2 = silu_f(acc[mt][nt][2] + b0);
                float v3 = silu_f(acc[mt][nt][3] + b1);
                M1[rr*132 + col]       = v0;
                M1[rr*132 + col + 1]   = v1;
                M1[(rr+8)*132 + col]   = v2;
                M1[(rr+8)*132 + col+1] = v3;
                cf[mt][0] += v0*wx0 + v1*wx1;
                cf[mt][1] += v2*wx0 + v3*wx1;
            }
        }
#pragma unroll
        for (int mt = 0; mt < 3; mt++){
#pragma unroll
            for (int h = 0; h < 2; h++){
                float c = cf[mt][h];
                c += __shfl_xor_sync(0xffffffffu, c, 1);
                c += __shfl_xor_sync(0xffffffffu, c, 2);
                if (lq == 0) coefp[wc*96 + mr + mt*16 + h*8 + gq] = c;
            }
        }
        __syncthreads();

        // ---- coef combine + agg partials ----
        if (tid < 96)
            coef_s[tid] = coefp[tid] + coefp[96+tid] + coefp[192+tid] + coefp[288+tid];
        {
            int col = tid & 127, grp = tid >> 7;  // 2 groups of 48 rows
            float s = 0.f;
#pragma unroll 8
            for (int j = grp*48; j < grp*48 + 48; j++) s += M1[j*132 + col];
            aggp[grp*128 + col] = s;
        }
        __syncthreads();

        if (tid < 128)
            aggG[(size_t)r*128 + tid] = aggp[tid] + aggp[128 + tid];
        if (w < 3){
            float s = coef_s[lane]    * rel_s[lane*4 + w]
                    + coef_s[lane+32] * rel_s[(lane+32)*4 + w]
                    + coef_s[lane+64] * rel_s[(lane+64)*4 + w];
            s += __shfl_xor_sync(0xffffffffu, s, 16);
            s += __shfl_xor_sync(0xffffffffu, s, 8);
            s += __shfl_xor_sync(0xffffffffu, s, 4);
            s += __shfl_xor_sync(0xffffffffu, s, 2);
            s += __shfl_xor_sync(0xffffffffu, s, 1);
            if (lane == 0) Xout[r*3 + w] = Xin[r*3 + w] + s;
        }
        __syncthreads();   // protect rel_s/coef_s/M1 before next iteration
    }
}

// ---------------- losses ----------------
__global__ void loss_partial(const float* __restrict__ H0, const float* __restrict__ H1,
                             const float* __restrict__ X0, const float* __restrict__ X1,
                             const int* __restrict__ shiftp,
                             const float* __restrict__ Xf)
{
    __shared__ float red[64];
    float s[5] = {0,0,0,0,0};
    int shift = *shiftp;
    for (int i = blockIdx.x*blockDim.x + threadIdx.x; i < NN; i += gridDim.x*blockDim.x){
        if (!g_mask[i]) continue;
        int j = (i + shift) % NN; if (j < 0) j += NN;
        float hp = 0.f, hn = 0.f;
        const float4* vp = (const float4*)(g_vH + (size_t)i*64);
        const float4* a1 = (const float4*)(H1 + (size_t)i*64);
        const float4* a0 = (const float4*)(H0 + (size_t)i*64);
        const float4* b1 = (const float4*)(H1 + (size_t)j*64);
        const float4* b0 = (const float4*)(H0 + (size_t)j*64);
#pragma unroll
        for (int k = 0; k < 16; k++){
            float4 p = vp[k], x1 = a1[k], x0 = a0[k], y1 = b1[k], y0 = b0[k];
            float d;
            d = p.x - (x1.x - x0.x); hp += d*d;
            d = p.y - (x1.y - x0.y); hp += d*d;
            d = p.z - (x1.z - x0.z); hp += d*d;
            d = p.w - (x1.w - x0.w); hp += d*d;
            d = p.x - (y1.x - y0.x); hn += d*d;
            d = p.y - (y1.y - y0.y); hn += d*d;
            d = p.z - (y1.z - y0.z); hn += d*d;
            d = p.w - (y1.w - y0.w); hn += d*d;
        }
        float xp = 0.f, xn = 0.f;
        for (int k = 0; k < 3; k++){
            float p = Xf[i*3 + k];
            float d  = p - (X1[i*3+k] - X0[i*3+k]); xp += d*d;
            float dn = p - (X1[j*3+k] - X0[j*3+k]); xn += dn*dn;
        }
        s[0] += hp; s[1] += xp; s[2] += hn; s[3] += xn; s[4] += 1.f;
    }
    for (int q = 0; q < 5; q++){
        red[threadIdx.x] = s[q]; __syncthreads();
        for (int d = 32; d > 0; d >>= 1){
            if (threadIdx.x < d) red[threadIdx.x] += red[threadIdx.x + d];
            __syncthreads();
        }
        if (threadIdx.x == 0) g_lpart[blockIdx.x*5 + q] = red[0];
        __syncthreads();
    }
}

__global__ void loss_final(float* __restrict__ out, int nb){
    if (threadIdx.x == 0){
        float s[5] = {0,0,0,0,0};
        for (int b = 0; b < nb; b++)
            for (int q = 0; q < 5; q++) s[q] += g_lpart[b*5 + q];
        float msum = s[4] + 1e-8f;
        float lHp = s[0]/msum, lXp = s[1]/msum, lHn = s[2]/msum, lXn = s[3]/msum;
        out[0] = lHp - 0.05f*lHn;
        out[1] = lXp - 0.05f*lXn;
        out[2] = lHp; out[3] = lXp; out[4] = lHn; out[5] = lXn;
    }
}

// ---------------- host launch ----------------
extern "C" void kernel_launch(void* const* d_in, const int* in_sizes, int n_in,
                              void* d_out, int out_size)
{
    (void)in_sizes; (void)n_in; (void)out_size;
    const float* H0    = (const float*)d_in[0];
    const float* X0    = (const float*)d_in[1];
    const float* H1    = (const float*)d_in[2];
    const float* X1    = (const float*)d_in[3];
    const float* cond  = (const float*)d_in[4];
    const float* tg    = (const float*)d_in[5];
    const float* Wi1   = (const float*)d_in[6];
    const float* bi1   = (const float*)d_in[7];
    const float* Wi2   = (const float*)d_in[8];
    const float* bi2   = (const float*)d_in[9];
    const float* Wi3   = (const float*)d_in[10];
    const float* bi3   = (const float*)d_in[11];
    const float* etab  = (const float*)d_in[12];
    const float* We1   = (const float*)d_in[13];
    const float* be1   = (const float*)d_in[14];
    const float* We2   = (const float*)d_in[15];
    const float* be2   = (const float*)d_in[16];
    const float* Wx    = (const float*)d_in[17];
    const float* Wh1   = (const float*)d_in[18];
    const float* bh1   = (const float*)d_in[19];
    const float* Wh2   = (const float*)d_in[20];
    const float* bh2   = (const float*)d_in[21];
    const float* Wout  = (const float*)d_in[22];
    const float* bout  = (const float*)d_in[23];
    const int*   edges = (const int*)d_in[24];
    const int*   chain = (const int*)d_in[25];
    const unsigned char* mask = (const unsigned char*)d_in[26];
    const int*   lengths = (const int*)d_in[27];
    const int*   shiftp  = (const int*)d_in[28];
    const int*   ecol = edges + EE;

    float *p_Hin, *p_h, *p_tmp, *p_a, *p_bn, *p_agg, *p_X, *p_vH;
    cudaGetSymbolAddress((void**)&p_Hin, g_Hin);
    cudaGetSymbolAddress((void**)&p_h,   g_h);
    cudaGetSymbolAddress((void**)&p_tmp, g_tmp);
    cudaGetSymbolAddress((void**)&p_a,   g_a);
    cudaGetSymbolAddress((void**)&p_bn,  g_bn);
    cudaGetSymbolAddress((void**)&p_agg, g_agg);
    cudaGetSymbolAddress((void**)&p_X,   g_X);
    cudaGetSymbolAddress((void**)&p_vH,  g_vH);

    int nsm = 148;
    cudaDeviceGetAttribute(&nsm, cudaDevAttrMultiProcessorCount, 0);
    if (nsm <= 0) nsm = 148;

    cudaFuncSetAttribute(edge_kernel,
                         cudaFuncAttributeMaxDynamicSharedMemorySize, SMEM_BYTES);

    mask_prep<<<1, 256>>>(mask);
    setup_offsets<<<1, 32>>>(lengths);
    node_prep<<<NN, 128>>>(H0, X0, H1, X1, cond, tg);

    // input MLP: 320 -> 128 (relu) -> 128 (relu) -> 128
    gemm16<128><<<128, 128>>>(p_Hin, 320, nullptr, 0, Wi1, bi1, nullptr, p_h,   1);
    gemm16<128><<<128, 128>>>(p_h,   128, nullptr, 0, Wi2, bi2, nullptr, p_tmp, 1);
    gemm16<128><<<128, 128>>>(p_tmp, 128, nullptr, 0, Wi3, bi3, nullptr, p_h,   0);

    int cur = 0;
    for (int l = 0; l < 3; l++){
        const float* We1l = We1 + (size_t)l*289*128;
        prep_edge<<<1, 128>>>(We1, be1, etab, l);
        gemm16_dual<<<128, 128>>>(p_h, We1l, We1l + 128*128, p_a, p_bn);
        edge_kernel<<<nsm, 256, SMEM_BYTES>>>(p_a, p_bn,
                                             p_X + cur*NN*3, p_X + (1-cur)*NN*3,
                                             p_agg, ecol, chain,
                                             We2 + (size_t)l*128*128,
                                             be2 + l*128, Wx + l*128);
        cur = 1 - cur;
        gemm16<128><<<128, 128>>>(p_h,   128, p_agg, 128, Wh1 + (size_t)l*256*128,
                                  bh1 + l*128, nullptr, p_tmp, 2);
        gemm16<128><<<128, 128>>>(p_tmp, 128, nullptr, 0,  Wh2 + (size_t)l*128*128,
                                  bh2 + l*128, p_h, p_h, 0);
    }

    gemm16<64><<<128, 128>>>(p_h, 128, nullptr, 0, Wout, bout, nullptr, p_vH, 0);

    loss_partial<<<48, 64>>>(H0, H1, X0, X1, shiftp, p_X + cur*NN*3);
    loss_final<<<1, 32>>>((float*)d_out, 48);
}

// round 6
// speedup vs baseline: 3.2392x; 1.0160x over previous
#include <cuda_runtime.h>
#include <math.h>

#define NN 3072
#define BB 32
#define LL 96
#define EE (NN*LL)
#define HIDD 128
#define LATD 64

// ---------------- device scratch (no allocations allowed) ----------------
__device__ float g_Hin[NN*320];
__device__ float g_h[NN*HIDD];
__device__ float g_tmp[NN*HIDD];
__device__ float g_a[NN*HIDD];
__device__ float g_bn[NN*HIDD];
__device__ float g_agg[NN*HIDD];
__device__ float g_X[2][NN*3];
__device__ float g_vH[NN*LATD];
__device__ float g_wd2[3*HIDD];
__device__ float g_etab[3*2*HIDD];
__device__ int   g_off[BB+1];
__device__ int   g_mask[NN];
__device__ float g_lpart[64*5];

__device__ __forceinline__ float silu_f(float v){
    return __fdividef(v, 1.f + __expf(-v));
}
__device__ __forceinline__ unsigned f2tf32(float f){
    unsigned r; asm("cvt.rna.tf32.f32 %0, %1;" : "=r"(r) : "f"(f)); return r;
}
__device__ __forceinline__ void mma_tf32(float (&d)[4], const unsigned (&a)[4],
                                         unsigned b0, unsigned b1){
    asm volatile("mma.sync.aligned.m16n8k8.row.col.f32.tf32.tf32.f32 "
        "{%0,%1,%2,%3}, {%4,%5,%6,%7}, {%8,%9}, {%0,%1,%2,%3};\n"
        : "+f"(d[0]), "+f"(d[1]), "+f"(d[2]), "+f"(d[3])
        : "r"(a[0]), "r"(a[1]), "r"(a[2]), "r"(a[3]), "r"(b0), "r"(b1));
}
__device__ __forceinline__ unsigned sptr(const void* p){
    return (unsigned)__cvta_generic_to_shared(p);
}
__device__ __forceinline__ void cpa16(unsigned dst, const void* src){
    asm volatile("cp.async.cg.shared.global [%0], [%1], 16;\n" :: "r"(dst), "l"(src));
}
__device__ __forceinline__ void cpa_commit(){
    asm volatile("cp.async.commit_group;\n" ::: "memory");
}
template<int N> __device__ __forceinline__ void cpa_wait(){
    asm volatile("cp.async.wait_group %0;\n" :: "n"(N) : "memory");
}

// ---------------- setup: mask dtype auto-detect + offsets ----------------
__global__ void setup_all(const unsigned char* __restrict__ m,
                          const int* __restrict__ lengths){
    __shared__ int s_big, s_odd;
    int tid = threadIdx.x;
    if (tid == 0){
        s_big = 0; s_odd = 0;
        int s = 0;
        for (int b = 0; b < BB; b++){ g_off[b] = s; s += lengths[b]; }
        g_off[BB] = s;
    }
    __syncthreads();
    int big = 0, odd = 0;
    for (int i = tid; i < NN; i += blockDim.x){
        unsigned char v = m[i];
        if (v > 1) big = 1;
        if ((i & 3) && v) odd = 1;
    }
    if (big) s_big = 1;
    if (odd) s_odd = 1;
    __syncthreads();
    if (s_big){
        const float* mf = (const float*)m;
        for (int i = tid; i < NN; i += blockDim.x) g_mask[i] = (mf[i] != 0.f) ? 1 : 0;
    } else if (s_odd){
        for (int i = tid; i < NN; i += blockDim.x) g_mask[i] = m[i] ? 1 : 0;
    } else {
        const int* mi = (const int*)m;
        for (int i = tid; i < NN; i += blockDim.x) g_mask[i] = mi[i] ? 1 : 0;
    }
}

__global__ void node_prep(const float* __restrict__ H0, const float* __restrict__ X0,
                          const float* __restrict__ H1, const float* __restrict__ X1,
                          const float* __restrict__ cond, const float* __restrict__ tg)
{
    int i = blockIdx.x;
    int k = threadIdx.x;
    __shared__ float t_sh; __shared__ int m_sh;
    if (k == 0){
        int b = 0;
        while (b + 1 < BB && g_off[b+1] <= i) b++;
        t_sh = tg[b];
        m_sh = g_mask[i];
    }
    __syncthreads();
    float t = t_sh; int m = m_sh;
    if (k < 64){
        float h0 = H0[i*64+k], h1 = H1[i*64+k];
        g_Hin[i*320 + k] = m ? (1.f - t)*h0 + t*h1 : h1;
        float f = expf(-logf(10000.f) * (float)k / 63.f);
        float ang = t * f;
        g_Hin[i*320 + 192 + k] = sinf(ang);
        g_Hin[i*320 + 256 + k] = cosf(ang);
    }
    g_Hin[i*320 + 64 + k] = cond[i*128 + k];
    if (k < 3){
        float x0 = X0[i*3+k], x1 = X1[i*3+k];
        g_X[0][i*3+k] = m ? (1.f - t)*x0 + t*x1 : x1;
    }
}

// all 3 layers at once (independent of the layer loop)
__global__ void prep_edge_all(const float* __restrict__ We1, const float* __restrict__ be1,
                              const float* __restrict__ etable)
{
    int l = blockIdx.x;
    int k = threadIdx.x;  // 128
    const float* W = We1 + (size_t)l*289*128;
    g_wd2[l*128 + k] = W[256*128 + k];
    for (int t = 0; t < 2; t++){
        float s = be1[l*128 + k];
        for (int e = 0; e < 32; e++) s += etable[t*32 + e] * W[(257 + e)*128 + k];
        g_etab[l*256 + t*128 + k] = s;
    }
}

// ---------------- tensor-core node GEMM (NOUT=128) ------------------------
// 32 rows/CTA, 256 threads, warp grid 2x4 (warp tile 16x32), tf32 mma.
// A = concat(A1[:,:K1], A2[:,:K2]); out = act(A@W + bias) (+resid)
struct TG {
    float As[2][32*36];
    float Ws[2][32*136];
};

__device__ __forceinline__ void tgemm_core(
    const float* __restrict__ A1, int K1,
    const float* __restrict__ A2, int K2,
    const float* __restrict__ W,
    const float* __restrict__ bias,
    const float* __restrict__ resid,
    float* __restrict__ out, int act, TG& S, int gr0)
{
    int tid = threadIdx.x;
    int w = tid >> 5, lane = tid & 31;
    int wr = w >> 2, wc = w & 3;
    int gq = lane >> 2, lq = lane & 3;
    int K = K1 + K2;
    int ntiles = K >> 5;

    int srow = tid >> 3, skc = tid & 7;

    float acc[4][4];
#pragma unroll
    for (int nt = 0; nt < 4; nt++)
#pragma unroll
        for (int q = 0; q < 4; q++) acc[nt][q] = 0.f;

    // stage tile 0
    {
        int k = skc*4;
        const float* src = (k < K1) ? A1 + (size_t)(gr0+srow)*K1 + k
                                    : A2 + (size_t)(gr0+srow)*K2 + (k - K1);
        cpa16(sptr(&S.As[0][srow*36 + skc*4]), src);
#pragma unroll
        for (int i = 0; i < 4; i++){
            int idx = tid + i*256;
            int kk = idx >> 5, c = idx & 31;
            cpa16(sptr(&S.Ws[0][kk*136 + c*4]), W + (size_t)kk*128 + c*4);
        }
        cpa_commit();
    }

    for (int t = 0; t < ntiles; t++){
        int b = t & 1;
        if (t + 1 < ntiles){
            int nb = b ^ 1;
            int k = (t+1)*32 + skc*4;
            const float* src = (k < K1) ? A1 + (size_t)(gr0+srow)*K1 + k
                                        : A2 + (size_t)(gr0+srow)*K2 + (k - K1);
            cpa16(sptr(&S.As[nb][srow*36 + skc*4]), src);
            const float* Wt = W + (size_t)(t+1)*32*128;
#pragma unroll
            for (int i = 0; i < 4; i++){
                int idx = tid + i*256;
                int kk = idx >> 5, c = idx & 31;
                cpa16(sptr(&S.Ws[nb][kk*136 + c*4]), Wt + (size_t)kk*128 + c*4);
            }
            cpa_commit();
            cpa_wait<1>();
        } else {
            cpa_wait<0>();
        }
        __syncthreads();
        const float* as = S.As[b];
        const float* ws = S.Ws[b];
#pragma unroll
        for (int ks = 0; ks < 4; ks++){
            int k0 = ks*8;
            int rr = wr*16 + gq;
            unsigned afr[4];
            afr[0] = f2tf32(as[rr*36     + k0 + lq]);
            afr[1] = f2tf32(as[(rr+8)*36 + k0 + lq]);
            afr[2] = f2tf32(as[rr*36     + k0 + lq + 4]);
            afr[3] = f2tf32(as[(rr+8)*36 + k0 + lq + 4]);
#pragma unroll
            for (int nt = 0; nt < 4; nt++){
                int n = wc*32 + nt*8 + gq;
                unsigned b0 = f2tf32(ws[(k0 + lq)*136 + n]);
                unsigned b1 = f2tf32(ws[(k0 + lq + 4)*136 + n]);
                mma_tf32(acc[nt], afr, b0, b1);
            }
        }
        __syncthreads();
    }

    int r0 = gr0 + wr*16 + gq;
#pragma unroll
    for (int nt = 0; nt < 4; nt++){
        int col = wc*32 + nt*8 + lq*2;
        float b0 = bias ? bias[col] : 0.f;
        float b1 = bias ? bias[col+1] : 0.f;
        float v0 = acc[nt][0] + b0, v1 = acc[nt][1] + b1;
        float v2 = acc[nt][2] + b0, v3 = acc[nt][3] + b1;
        if (act == 1){
            v0 = fmaxf(v0,0.f); v1 = fmaxf(v1,0.f);
            v2 = fmaxf(v2,0.f); v3 = fmaxf(v3,0.f);
        } else if (act == 2){
            v0 = silu_f(v0); v1 = silu_f(v1);
            v2 = silu_f(v2); v3 = silu_f(v3);
        }
        if (resid){
            float2 r0v = *(const float2*)&resid[(size_t)r0*128 + col];
            float2 r1v = *(const float2*)&resid[(size_t)(r0+8)*128 + col];
            v0 += r0v.x; v1 += r0v.y; v2 += r1v.x; v3 += r1v.y;
        }
        *(float2*)&out[(size_t)r0*128 + col]     = make_float2(v0, v1);
        *(float2*)&out[(size_t)(r0+8)*128 + col] = make_float2(v2, v3);
    }
}

__global__ void __launch_bounds__(256, 1) tgemm(
    const float* __restrict__ A1, int K1,
    const float* __restrict__ A2, int K2,
    const float* __restrict__ W,
    const float* __restrict__ bias,
    const float* __restrict__ resid,
    float* __restrict__ out, int act)
{
    __shared__ TG S;
    tgemm_core(A1, K1, A2, K2, W, bias, resid, out, act, S, blockIdx.x*32);
}

// dual: gridDim.y=2 selects (WA->outA)/(WB->outB), shared A
__global__ void __launch_bounds__(256, 1) tgemm_dual(
    const float* __restrict__ A,
    const float* __restrict__ WA, const float* __restrict__ WB,
    float* __restrict__ outA, float* __restrict__ outB)
{
    __shared__ TG S;
    const float* W  = blockIdx.y ? WB : WA;
    float* out      = blockIdx.y ? outB : outA;
    tgemm_core(A, 128, nullptr, 0, W, nullptr, nullptr, out, 0, S, blockIdx.x*32);
}

// ---------------- fp32 node GEMM for NOUT=64 (Wout, keeps output precision)
template<int NOUT>
__global__ void __launch_bounds__(128, 4) gemm16(
    const float* __restrict__ A1, int K1,
    const float* __restrict__ W,
    const float* __restrict__ bias,
    float* __restrict__ out)
{
    constexpr int ROWS = 24;
    constexpr int NC4  = NOUT / 4;
    constexpr int TR   = 128 / NC4;
    constexpr int R    = ROWS / TR;
    __shared__ float As[2][ROWS*32];
    __shared__ float Ws[2][32*NOUT];

    int tid = threadIdx.x;
    int tx = tid % NC4, ty = tid / NC4;
    int c0 = tx*4, r0 = ty*R;
    int gr0 = blockIdx.x * ROWS;
    int K = K1;
    int ntiles = K >> 5;

    float acc[R][4];
#pragma unroll
    for (int i = 0; i < R; i++)
#pragma unroll
        for (int j = 0; j < 4; j++) acc[i][j] = 0.f;

    {
        for (int i = tid; i < ROWS*8; i += 128){
            int row = i >> 3, kc = i & 7;
            cpa16(sptr(&As[0][row*32 + kc*4]), A1 + (size_t)(gr0+row)*K + kc*4);
        }
        for (int i = tid; i < 8*NOUT; i += 128)
            cpa16(sptr(&Ws[0][i*4]), W + (size_t)i*4);
        cpa_commit();
    }

    for (int t = 0; t < ntiles; t++){
        int b = t & 1;
        if (t + 1 < ntiles){
            int nb = b ^ 1;
            for (int i = tid; i < ROWS*8; i += 128){
                int row = i >> 3, kc = i & 7;
                cpa16(sptr(&As[nb][row*32 + kc*4]),
                      A1 + (size_t)(gr0+row)*K + (t+1)*32 + kc*4);
            }
            const float* Wt = W + (size_t)(t+1)*32*NOUT;
            for (int i = tid; i < 8*NOUT; i += 128)
                cpa16(sptr(&Ws[nb][i*4]), Wt + (size_t)i*4);
            cpa_commit();
            cpa_wait<1>();
        } else {
            cpa_wait<0>();
        }
        __syncthreads();
        const float* as = As[b];
        const float* ws = Ws[b];
#pragma unroll
        for (int kk = 0; kk < 32; kk++){
            float4 w = *(const float4*)&ws[kk*NOUT + c0];
            float a[R];
#pragma unroll
            for (int i = 0; i < R; i++) a[i] = as[(r0+i)*32 + kk];
#pragma unroll
            for (int i = 0; i < R; i++){
                acc[i][0] += a[i]*w.x; acc[i][1] += a[i]*w.y;
                acc[i][2] += a[i]*w.z; acc[i][3] += a[i]*w.w;
            }
        }
        __syncthreads();
    }

    float4 bv = make_float4(0.f,0.f,0.f,0.f);
    if (bias) bv = *(const float4*)&bias[c0];
#pragma unroll
    for (int i = 0; i < R; i++){
        int g = gr0 + r0 + i;
        float4 v;
        v.x = acc[i][0] + bv.x; v.y = acc[i][1] + bv.y;
        v.z = acc[i][2] + bv.z; v.w = acc[i][3] + bv.w;
        *(float4*)&out[(size_t)g*NOUT + c0] = v;
    }
}

// ---------------- persistent fused edge kernel ----------------------------
#define S_M1    0                 // 96 x 132 (m1 tf32, reused as m2 fp32)
#define S_W2    (96*132)          // 128 x 136 (W2 tf32)
#define S_AS    (S_W2 + 128*136)  // 128
#define S_WD2   (S_AS + 128)
#define S_ETAB  (S_WD2 + 128)     // 256
#define S_BE2   (S_ETAB + 256)
#define S_WX    (S_BE2 + 128)
#define S_REL   (S_WX + 128)      // 96*4
#define S_COEF  (S_REL + 384)     // 96
#define S_COEFP (S_COEF + 96)     // 4*96
#define S_AGGP  (S_COEFP + 384)   // 2*128
#define S_COL   (S_AGGP + 256)    // 96 ints
#define S_ET    (S_COL + 96)      // 96 ints
#define S_TOTF  (S_ET + 96)
#define SMEM_BYTES (S_TOTF*4)

__global__ void __launch_bounds__(256, 1) edge_kernel(
    const float* __restrict__ aG, const float* __restrict__ bG,
    const float* __restrict__ Xin, float* __restrict__ Xout,
    float* __restrict__ aggG,
    const int* __restrict__ ecol, const int* __restrict__ chain,
    const float* __restrict__ W2g, const float* __restrict__ be2g,
    const float* __restrict__ Wxg, int layer)
{
    extern __shared__ float sm[];
    float* M1     = sm + S_M1;    // stride 132
    float* W2     = sm + S_W2;    // stride 136
    float* a_s    = sm + S_AS;
    float* wd2_s  = sm + S_WD2;
    float* etab_s = sm + S_ETAB;
    float* be2_s  = sm + S_BE2;
    float* Wx_s   = sm + S_WX;
    float* rel_s  = sm + S_REL;
    float* coef_s = sm + S_COEF;
    float* coefp  = sm + S_COEFP;
    float* aggp   = sm + S_AGGP;
    int*   col_s  = (int*)(sm + S_COL);
    int*   et_s   = (int*)(sm + S_ET);

    int tid = threadIdx.x;

    for (int i = tid; i < 128*32; i += 256){
        int row = i >> 5, cg = (i & 31);
        float4 v = ((const float4*)W2g)[row*32 + cg];
        float4 p;
        p.x = __uint_as_float(f2tf32(v.x));
        p.y = __uint_as_float(f2tf32(v.y));
        p.z = __uint_as_float(f2tf32(v.z));
        p.w = __uint_as_float(f2tf32(v.w));
        *(float4*)&W2[row*136 + cg*4] = p;
    }
    if (tid < 128){
        wd2_s[tid]     = g_wd2[layer*128 + tid];
        etab_s[tid]    = g_etab[layer*256 + tid];
        etab_s[128+tid]= g_etab[layer*256 + 128 + tid];
        be2_s[tid]     = be2g[tid];
        Wx_s[tid]      = Wxg[tid];
    }

    int w  = tid >> 5, lane = tid & 31;
    int wr = w >> 2, wc = w & 3;
    int mr = wr * 48, nc0 = wc * 32;
    int gq = lane >> 2, lq = lane & 3;

    for (int r = blockIdx.x; r < NN; r += gridDim.x){
        if (tid < 128) a_s[tid] = aG[(size_t)r*128 + tid];
        if (tid < 96){
            int c = ecol[r*96 + tid];
            col_s[tid] = c;
            float dx = Xin[r*3]   - Xin[c*3];
            float dy = Xin[r*3+1] - Xin[c*3+1];
            float dz = Xin[r*3+2] - Xin[c*3+2];
            rel_s[tid*4]   = dx;
            rel_s[tid*4+1] = dy;
            rel_s[tid*4+2] = dz;
            rel_s[tid*4+3] = dx*dx + dy*dy + dz*dz;
            et_s[tid] = (chain[c] != chain[r]) ? 1 : 0;
        }
        __syncthreads();

        for (int idx = tid; idx < 96*32; idx += 256){
            int j = idx >> 5, k = (idx & 31) * 4;
            int c = col_s[j];
            float4 bn = *(const float4*)&bG[(size_t)c*128 + k];
            float d2 = rel_s[j*4+3];
            const float* et = etab_s + et_s[j]*128;
            float4 p;
            p.x = silu_f(a_s[k+0] + bn.x + d2*wd2_s[k+0] + et[k+0]);
            p.y = silu_f(a_s[k+1] + bn.y + d2*wd2_s[k+1] + et[k+1]);
            p.z = silu_f(a_s[k+2] + bn.z + d2*wd2_s[k+2] + et[k+2]);
            p.w = silu_f(a_s[k+3] + bn.w + d2*wd2_s[k+3] + et[k+3]);
            p.x = __uint_as_float(f2tf32(p.x));
            p.y = __uint_as_float(f2tf32(p.y));
            p.z = __uint_as_float(f2tf32(p.z));
            p.w = __uint_as_float(f2tf32(p.w));
            *(float4*)&M1[j*132 + k] = p;
        }
        __syncthreads();

        float acc[3][4][4];
#pragma unroll
        for (int mt = 0; mt < 3; mt++)
#pragma unroll
            for (int nt = 0; nt < 4; nt++)
#pragma unroll
                for (int q = 0; q < 4; q++) acc[mt][nt][q] = 0.f;

#pragma unroll 4
        for (int k0 = 0; k0 < 128; k0 += 8){
            unsigned afr[3][4];
#pragma unroll
            for (int mt = 0; mt < 3; mt++){
                int rr = mr + mt*16 + gq;
                afr[mt][0] = __float_as_uint(M1[rr*132      + k0 + lq]);
                afr[mt][1] = __float_as_uint(M1[(rr+8)*132  + k0 + lq]);
                afr[mt][2] = __float_as_uint(M1[rr*132      + k0 + lq + 4]);
                afr[mt][3] = __float_as_uint(M1[(rr+8)*132  + k0 + lq + 4]);
            }
#pragma unroll
            for (int nt = 0; nt < 4; nt++){
                int n = nc0 + nt*8 + gq;
                unsigned b0 = __float_as_uint(W2[(k0 + lq)*136 + n]);
                unsigned b1 = __float_as_uint(W2[(k0 + lq + 4)*136 + n]);
#pragma unroll
                for (int mt = 0; mt < 3; mt++)
                    mma_tf32(acc[mt][nt], afr[mt], b0, b1);
            }
        }
        __syncthreads();

        float cf[3][2] = {{0.f,0.f},{0.f,0.f},{0.f,0.f}};
#pragma unroll
        for (int mt = 0; mt < 3; mt++){
            int rr = mr + mt*16 + gq;
#pragma unroll
            for (int nt = 0; nt < 4; nt++){
                int col = nc0 + nt*8 + lq*2;
                float wx0 = Wx_s[col], wx1 = Wx_s[col+1];
                float b0 = be2_s[col], b1 = be2_s[col+1];
                float v0 = silu_f(acc[mt][nt][0] + b0);
                float v1 = silu_f(acc[mt][nt][1] + b1);
                float v2 = silu_f(acc[mt][nt][2] + b0);
                float v3 = silu_f(acc[mt][nt][3] + b1);
                M1[rr*132 + col]       = v0;
                M1[rr*132 + col + 1]   = v1;
                M1[(rr+8)*132 + col]   = v2;
                M1[(rr+8)*132 + col+1] = v3;
                cf[mt][0] += v0*wx0 + v1*wx1;
                cf[mt][1] += v2*wx0 + v3*wx1;
            }
        }
#pragma unroll
        for (int mt = 0; mt < 3; mt++){
#pragma unroll
            for (int h = 0; h < 2; h++){
                float c = cf[mt][h];
                c += __shfl_xor_sync(0xffffffffu, c, 1);
                c += __shfl_xor_sync(0xffffffffu, c, 2);
                if (lq == 0) coefp[wc*96 + mr + mt*16 + h*8 + gq] = c;
            }
        }
        __syncthreads();

        if (tid < 96)
            coef_s[tid] = coefp[tid] + coefp[96+tid] + coefp[192+tid] + coefp[288+tid];
        {
            int col = tid & 127, grp = tid >> 7;
            float s = 0.f;
#pragma unroll 8
            for (int j = grp*48; j < grp*48 + 48; j++) s += M1[j*132 + col];
            aggp[grp*128 + col] = s;
        }
        __syncthreads();

        if (tid < 128)
            aggG[(size_t)r*128 + tid] = aggp[tid] + aggp[128 + tid];
        if (w < 3){
            float s = coef_s[lane]    * rel_s[lane*4 + w]
                    + coef_s[lane+32] * rel_s[(lane+32)*4 + w]
                    + coef_s[lane+64] * rel_s[(lane+64)*4 + w];
            s += __shfl_xor_sync(0xffffffffu, s, 16);
            s += __shfl_xor_sync(0xffffffffu, s, 8);
            s += __shfl_xor_sync(0xffffffffu, s, 4);
            s += __shfl_xor_sync(0xffffffffu, s, 2);
            s += __shfl_xor_sync(0xffffffffu, s, 1);
            if (lane == 0) Xout[r*3 + w] = Xin[r*3 + w] + s;
        }
        __syncthreads();
    }
}

// ---------------- losses ----------------
__global__ void loss_partial(const float* __restrict__ H0, const float* __restrict__ H1,
                             const float* __restrict__ X0, const float* __restrict__ X1,
                             const int* __restrict__ shiftp,
                             const float* __restrict__ Xf)
{
    __shared__ float red[64];
    float s[5] = {0,0,0,0,0};
    int shift = *shiftp;
    for (int i = blockIdx.x*blockDim.x + threadIdx.x; i < NN; i += gridDim.x*blockDim.x){
        if (!g_mask[i]) continue;
        int j = (i + shift) % NN; if (j < 0) j += NN;
        float hp = 0.f, hn = 0.f;
        const float4* vp = (const float4*)(g_vH + (size_t)i*64);
        const float4* a1 = (const float4*)(H1 + (size_t)i*64);
        const float4* a0 = (const float4*)(H0 + (size_t)i*64);
        const float4* b1 = (const float4*)(H1 + (size_t)j*64);
        const float4* b0 = (const float4*)(H0 + (size_t)j*64);
#pragma unroll
        for (int k = 0; k < 16; k++){
            float4 p = vp[k], x1 = a1[k], x0 = a0[k], y1 = b1[k], y0 = b0[k];
            float d;
            d = p.x - (x1.x - x0.x); hp += d*d;
            d = p.y - (x1.y - x0.y); hp += d*d;
            d = p.z - (x1.z - x0.z); hp += d*d;
            d = p.w - (x1.w - x0.w); hp += d*d;
            d = p.x - (y1.x - y0.x); hn += d*d;
            d = p.y - (y1.y - y0.y); hn += d*d;
            d = p.z - (y1.z - y0.z); hn += d*d;
            d = p.w - (y1.w - y0.w); hn += d*d;
        }
        float xp = 0.f, xn = 0.f;
        for (int k = 0; k < 3; k++){
            float p = Xf[i*3 + k];
            float d  = p - (X1[i*3+k] - X0[i*3+k]); xp += d*d;
            float dn = p - (X1[j*3+k] - X0[j*3+k]); xn += dn*dn;
        }
        s[0] += hp; s[1] += xp; s[2] += hn; s[3] += xn; s[4] += 1.f;
    }
    for (int q = 0; q < 5; q++){
        red[threadIdx.x] = s[q]; __syncthreads();
        for (int d = 32; d > 0; d >>= 1){
            if (threadIdx.x < d) red[threadIdx.x] += red[threadIdx.x + d];
            __syncthreads();
        }
        if (threadIdx.x == 0) g_lpart[blockIdx.x*5 + q] = red[0];
        __syncthreads();
    }
}

__global__ void loss_final(float* __restrict__ out, int nb){
    if (threadIdx.x == 0){
        float s[5] = {0,0,0,0,0};
        for (int b = 0; b < nb; b++)
            for (int q = 0; q < 5; q++) s[q] += g_lpart[b*5 + q];
        float msum = s[4] + 1e-8f;
        float lHp = s[0]/msum, lXp = s[1]/msum, lHn = s[2]/msum, lXn = s[3]/msum;
        out[0] = lHp - 0.05f*lHn;
        out[1] = lXp - 0.05f*lXn;
        out[2] = lHp; out[3] = lXp; out[4] = lHn; out[5] = lXn;
    }
}

// ---------------- host launch ----------------
extern "C" void kernel_launch(void* const* d_in, const int* in_sizes, int n_in,
                              void* d_out, int out_size)
{
    (void)in_sizes; (void)n_in; (void)out_size;
    const float* H0    = (const float*)d_in[0];
    const float* X0    = (const float*)d_in[1];
    const float* H1    = (const float*)d_in[2];
    const float* X1    = (const float*)d_in[3];
    const float* cond  = (const float*)d_in[4];
    const float* tg    = (const float*)d_in[5];
    const float* Wi1   = (const float*)d_in[6];
    const float* bi1   = (const float*)d_in[7];
    const float* Wi2   = (const float*)d_in[8];
    const float* bi2   = (const float*)d_in[9];
    const float* Wi3   = (const float*)d_in[10];
    const float* bi3   = (const float*)d_in[11];
    const float* etab  = (const float*)d_in[12];
    const float* We1   = (const float*)d_in[13];
    const float* be1   = (const float*)d_in[14];
    const float* We2   = (const float*)d_in[15];
    const float* be2   = (const float*)d_in[16];
    const float* Wx    = (const float*)d_in[17];
    const float* Wh1   = (const float*)d_in[18];
    const float* bh1   = (const float*)d_in[19];
    const float* Wh2   = (const float*)d_in[20];
    const float* bh2   = (const float*)d_in[21];
    const float* Wout  = (const float*)d_in[22];
    const float* bout  = (const float*)d_in[23];
    const int*   edges = (const int*)d_in[24];
    const int*   chain = (const int*)d_in[25];
    const unsigned char* mask = (const unsigned char*)d_in[26];
    const int*   lengths = (const int*)d_in[27];
    const int*   shiftp  = (const int*)d_in[28];
    const int*   ecol = edges + EE;

    float *p_Hin, *p_h, *p_tmp, *p_a, *p_bn, *p_agg, *p_X, *p_vH;
    cudaGetSymbolAddress((void**)&p_Hin, g_Hin);
    cudaGetSymbolAddress((void**)&p_h,   g_h);
    cudaGetSymbolAddress((void**)&p_tmp, g_tmp);
    cudaGetSymbolAddress((void**)&p_a,   g_a);
    cudaGetSymbolAddress((void**)&p_bn,  g_bn);
    cudaGetSymbolAddress((void**)&p_agg, g_agg);
    cudaGetSymbolAddress((void**)&p_X,   g_X);
    cudaGetSymbolAddress((void**)&p_vH,  g_vH);

    int nsm = 148;
    cudaDeviceGetAttribute(&nsm, cudaDevAttrMultiProcessorCount, 0);
    if (nsm <= 0) nsm = 148;

    cudaFuncSetAttribute(edge_kernel,
                         cudaFuncAttributeMaxDynamicSharedMemorySize, SMEM_BYTES);

    setup_all<<<1, 256>>>(mask, lengths);
    node_prep<<<NN, 128>>>(H0, X0, H1, X1, cond, tg);
    prep_edge_all<<<3, 128>>>(We1, be1, etab);

    // input MLP: 320 -> 128 (relu) -> 128 (relu) -> 128
    tgemm<<<96, 256>>>(p_Hin, 320, nullptr, 0, Wi1, bi1, nullptr, p_h,   1);
    tgemm<<<96, 256>>>(p_h,   128, nullptr, 0, Wi2, bi2, nullptr, p_tmp, 1);
    tgemm<<<96, 256>>>(p_tmp, 128, nullptr, 0, Wi3, bi3, nullptr, p_h,   0);

    int cur = 0;
    for (int l = 0; l < 3; l++){
        const float* We1l = We1 + (size_t)l*289*128;
        tgemm_dual<<<dim3(96,2), 256>>>(p_h, We1l, We1l + 128*128, p_a, p_bn);
        edge_kernel<<<nsm, 256, SMEM_BYTES>>>(p_a, p_bn,
                                             p_X + cur*NN*3, p_X + (1-cur)*NN*3,
                                             p_agg, ecol, chain,
                                             We2 + (size_t)l*128*128,
                                             be2 + l*128, Wx + l*128, l);
        cur = 1 - cur;
        tgemm<<<96, 256>>>(p_h,   128, p_agg, 128, Wh1 + (size_t)l*256*128,
                           bh1 + l*128, nullptr, p_tmp, 2);
        tgemm<<<96, 256>>>(p_tmp, 128, nullptr, 0,  Wh2 + (size_t)l*128*128,
                           bh2 + l*128, p_h, p_h, 0);
    }

    gemm16<64><<<128, 128>>>(p_h, 128, Wout, bout, p_vH);

    loss_partial<<<48, 64>>>(H0, H1, X0, X1, shiftp, p_X + cur*NN*3);
    loss_final<<<1, 32>>>((float*)d_out, 48);
}

// round 10
// speedup vs baseline: 3.2613x; 1.0068x over previous
#include <cuda_runtime.h>
#include <math.h>

#define NN 3072
#define BB 32
#define LL 96
#define EE (NN*LL)
#define HIDD 128
#define LATD 64

// ---------------- device scratch (no allocations allowed) ----------------
__device__ float g_Hin[NN*320];
__device__ float g_h[NN*HIDD];
__device__ float g_tmp[NN*HIDD];
__device__ float g_a[NN*HIDD];
__device__ float g_bn[NN*HIDD];
__device__ float g_agg[NN*HIDD];
__device__ float g_X[2][NN*3];
__device__ float g_vH[NN*LATD];
__device__ float g_wd2[3*HIDD];
__device__ float g_etab[3*2*HIDD];
__device__ int   g_off[BB+1];
__device__ int   g_mask[NN];
__device__ float g_lpart[64*5];

// tf32 pre-converted weights (offsets in floats)
#define OFF_I1 0
#define OFF_I2 40960
#define OFF_I3 57344
#define OFF_EA 73728
#define OFF_EB 122880
#define OFF_H1 172032
#define OFF_H2 270336
__device__ float g_tw[319488];

__device__ __forceinline__ float silu_f(float v){
    return __fdividef(v, 1.f + __expf(-v));
}
__device__ __forceinline__ unsigned f2tf32(float f){
    unsigned r; asm("cvt.rna.tf32.f32 %0, %1;" : "=r"(r) : "f"(f)); return r;
}
__device__ __forceinline__ float f2tf32f(float f){
    return __uint_as_float(f2tf32(f));
}
__device__ __forceinline__ void mma_tf32(float (&d)[4], const unsigned (&a)[4],
                                         unsigned b0, unsigned b1){
    asm volatile("mma.sync.aligned.m16n8k8.row.col.f32.tf32.tf32.f32 "
        "{%0,%1,%2,%3}, {%4,%5,%6,%7}, {%8,%9}, {%0,%1,%2,%3};\n"
        : "+f"(d[0]), "+f"(d[1]), "+f"(d[2]), "+f"(d[3])
        : "r"(a[0]), "r"(a[1]), "r"(a[2]), "r"(a[3]), "r"(b0), "r"(b1));
}
__device__ __forceinline__ unsigned sptr(const void* p){
    return (unsigned)__cvta_generic_to_shared(p);
}
__device__ __forceinline__ void cpa16(unsigned dst, const void* src){
    asm volatile("cp.async.cg.shared.global [%0], [%1], 16;\n" :: "r"(dst), "l"(src));
}
__device__ __forceinline__ void cpa_commit(){
    asm volatile("cp.async.commit_group;\n" ::: "memory");
}
template<int N> __device__ __forceinline__ void cpa_wait(){
    asm volatile("cp.async.wait_group %0;\n" :: "n"(N) : "memory");
}

// ---------------- setup: mask dtype auto-detect + offsets ----------------
__global__ void setup_all(const unsigned char* __restrict__ m,
                          const int* __restrict__ lengths){
    __shared__ int s_big, s_odd;
    int tid = threadIdx.x;
    if (tid == 0){
        s_big = 0; s_odd = 0;
        int s = 0;
        for (int b = 0; b < BB; b++){ g_off[b] = s; s += lengths[b]; }
        g_off[BB] = s;
    }
    __syncthreads();
    int big = 0, odd = 0;
    for (int i = tid; i < NN; i += blockDim.x){
        unsigned char v = m[i];
        if (v > 1) big = 1;
        if ((i & 3) && v) odd = 1;
    }
    if (big) s_big = 1;
    if (odd) s_odd = 1;
    __syncthreads();
    if (s_big){
        const float* mf = (const float*)m;
        for (int i = tid; i < NN; i += blockDim.x) g_mask[i] = (mf[i] != 0.f) ? 1 : 0;
    } else if (s_odd){
        for (int i = tid; i < NN; i += blockDim.x) g_mask[i] = m[i] ? 1 : 0;
    } else {
        const int* mi = (const int*)m;
        for (int i = tid; i < NN; i += blockDim.x) g_mask[i] = mi[i] ? 1 : 0;
    }
}

__global__ void node_prep(const float* __restrict__ H0, const float* __restrict__ X0,
                          const float* __restrict__ H1, const float* __restrict__ X1,
                          const float* __restrict__ cond, const float* __restrict__ tg)
{
    int i = blockIdx.x;
    int k = threadIdx.x;
    __shared__ float t_sh; __shared__ int m_sh;
    if (k == 0){
        int b = 0;
        while (b + 1 < BB && g_off[b+1] <= i) b++;
        t_sh = tg[b];
        m_sh = g_mask[i];
    }
    __syncthreads();
    float t = t_sh; int m = m_sh;
    if (k < 64){
        float h0 = H0[i*64+k], h1 = H1[i*64+k];
        g_Hin[i*320 + k] = m ? (1.f - t)*h0 + t*h1 : h1;
        float f = expf(-logf(10000.f) * (float)k / 63.f);
        float ang = t * f;
        g_Hin[i*320 + 192 + k] = sinf(ang);
        g_Hin[i*320 + 256 + k] = cosf(ang);
    }
    g_Hin[i*320 + 64 + k] = cond[i*128 + k];
    if (k < 3){
        float x0 = X0[i*3+k], x1 = X1[i*3+k];
        g_X[0][i*3+k] = m ? (1.f - t)*x0 + t*x1 : x1;
    }
}

// all 3 layers at once
__global__ void prep_edge_all(const float* __restrict__ We1, const float* __restrict__ be1,
                              const float* __restrict__ etable)
{
    int l = blockIdx.x;
    int k = threadIdx.x;  // 128
    const float* W = We1 + (size_t)l*289*128;
    g_wd2[l*128 + k] = W[256*128 + k];
    for (int t = 0; t < 2; t++){
        float s = be1[l*128 + k];
        for (int e = 0; e < 32; e++) s += etable[t*32 + e] * W[(257 + e)*128 + k];
        g_etab[l*256 + t*128 + k] = s;
    }
}

// tf32 weight pre-conversion (bit-identical to converting at read time)
__global__ void prep_w(const float* __restrict__ Wi1, const float* __restrict__ Wi2,
                       const float* __restrict__ Wi3, const float* __restrict__ We1,
                       const float* __restrict__ Wh1, const float* __restrict__ Wh2)
{
    int i0 = blockIdx.x*blockDim.x + threadIdx.x;
    int st = gridDim.x*blockDim.x;
    for (int i = i0; i < 40960; i += st) g_tw[OFF_I1+i] = f2tf32f(Wi1[i]);
    for (int i = i0; i < 16384; i += st) g_tw[OFF_I2+i] = f2tf32f(Wi2[i]);
    for (int i = i0; i < 16384; i += st) g_tw[OFF_I3+i] = f2tf32f(Wi3[i]);
    for (int i = i0; i < 49152; i += st){
        int l = i >> 14, r = i & 16383;
        g_tw[OFF_EA+i] = f2tf32f(We1[(size_t)l*36992 + r]);
        g_tw[OFF_EB+i] = f2tf32f(We1[(size_t)l*36992 + 16384 + r]);
    }
    for (int i = i0; i < 98304; i += st) g_tw[OFF_H1+i] = f2tf32f(Wh1[i]);
    for (int i = i0; i < 49152; i += st) g_tw[OFF_H2+i] = f2tf32f(Wh2[i]);
}

// ---------------- tensor-core node GEMM (NOUT=128) ------------------------
// 32 rows/CTA, 256 threads, warp grid 2x4 (warp tile 16x32), tf32 mma.
// A = concat(A1[:,:K1], A2[:,:K2]); W is PRE-CONVERTED tf32 bits.
struct TG {
    float As[2][32*36];
    float Ws[2][32*136];
};

__device__ __forceinline__ void tgemm_core(
    const float* __restrict__ A1, int K1,
    const float* __restrict__ A2, int K2,
    const float* __restrict__ W,
    const float* __restrict__ bias,
    const float* __restrict__ resid,
    float* __restrict__ out, int act, TG& S, int gr0)
{
    int tid = threadIdx.x;
    int w = tid >> 5, lane = tid & 31;
    int wr = w >> 2, wc = w & 3;
    int gq = lane >> 2, lq = lane & 3;
    int K = K1 + K2;
    int ntiles = K >> 5;

    int srow = tid >> 3, skc = tid & 7;

    float acc[4][4];
#pragma unroll
    for (int nt = 0; nt < 4; nt++)
#pragma unroll
        for (int q = 0; q < 4; q++) acc[nt][q] = 0.f;

    // stage tile 0
    {
        int k = skc*4;
        const float* src = (k < K1) ? A1 + (size_t)(gr0+srow)*K1 + k
                                    : A2 + (size_t)(gr0+srow)*K2 + (k - K1);
        cpa16(sptr(&S.As[0][srow*36 + skc*4]), src);
#pragma unroll
        for (int i = 0; i < 4; i++){
            int idx = tid + i*256;
            int kk = idx >> 5, c = idx & 31;
            cpa16(sptr(&S.Ws[0][kk*136 + c*4]), W + (size_t)kk*128 + c*4);
        }
        cpa_commit();
    }

    for (int t = 0; t < ntiles; t++){
        int b = t & 1;
        if (t + 1 < ntiles){
            int nb = b ^ 1;
            int k = (t+1)*32 + skc*4;
            const float* src = (k < K1) ? A1 + (size_t)(gr0+srow)*K1 + k
                                        : A2 + (size_t)(gr0+srow)*K2 + (k - K1);
            cpa16(sptr(&S.As[nb][srow*36 + skc*4]), src);
            const float* Wt = W + (size_t)(t+1)*32*128;
#pragma unroll
            for (int i = 0; i < 4; i++){
                int idx = tid + i*256;
                int kk = idx >> 5, c = idx & 31;
                cpa16(sptr(&S.Ws[nb][kk*136 + c*4]), Wt + (size_t)kk*128 + c*4);
            }
            cpa_commit();
            cpa_wait<1>();
        } else {
            cpa_wait<0>();
        }
        __syncthreads();
        const float* as = S.As[b];
        const float* ws = S.Ws[b];
#pragma unroll
        for (int ks = 0; ks < 4; ks++){
            int k0 = ks*8;
            int rr = wr*16 + gq;
            unsigned afr[4];
            afr[0] = f2tf32(as[rr*36     + k0 + lq]);
            afr[1] = f2tf32(as[(rr+8)*36 + k0 + lq]);
            afr[2] = f2tf32(as[rr*36     + k0 + lq + 4]);
            afr[3] = f2tf32(as[(rr+8)*36 + k0 + lq + 4]);
#pragma unroll
            for (int nt = 0; nt < 4; nt++){
                int n = wc*32 + nt*8 + gq;
                unsigned b0 = __float_as_uint(ws[(k0 + lq)*136 + n]);
                unsigned b1 = __float_as_uint(ws[(k0 + lq + 4)*136 + n]);
                mma_tf32(acc[nt], afr, b0, b1);
            }
        }
        __syncthreads();
    }

    int r0 = gr0 + wr*16 + gq;
#pragma unroll
    for (int nt = 0; nt < 4; nt++){
        int col = wc*32 + nt*8 + lq*2;
        float b0 = bias ? bias[col] : 0.f;
        float b1 = bias ? bias[col+1] : 0.f;
        float v0 = acc[nt][0] + b0, v1 = acc[nt][1] + b1;
        float v2 = acc[nt][2] + b0, v3 = acc[nt][3] + b1;
        if (act == 1){
            v0 = fmaxf(v0,0.f); v1 = fmaxf(v1,0.f);
            v2 = fmaxf(v2,0.f); v3 = fmaxf(v3,0.f);
        } else if (act == 2){
            v0 = silu_f(v0); v1 = silu_f(v1);
            v2 = silu_f(v2); v3 = silu_f(v3);
        }
        if (resid){
            float2 r0v = *(const float2*)&resid[(size_t)r0*128 + col];
            float2 r1v = *(const float2*)&resid[(size_t)(r0+8)*128 + col];
            v0 += r0v.x; v1 += r0v.y; v2 += r1v.x; v3 += r1v.y;
        }
        *(float2*)&out[(size_t)r0*128 + col]     = make_float2(v0, v1);
        *(float2*)&out[(size_t)(r0+8)*128 + col] = make_float2(v2, v3);
    }
}

__global__ void __launch_bounds__(256, 1) tgemm(
    const float* __restrict__ A1, int K1,
    const float* __restrict__ A2, int K2,
    const float* __restrict__ W,
    const float* __restrict__ bias,
    const float* __restrict__ resid,
    float* __restrict__ out, int act)
{
    __shared__ TG S;
    tgemm_core(A1, K1, A2, K2, W, bias, resid, out, act, S, blockIdx.x*32);
}

// dual: gridDim.y=2 selects (WA->outA)/(WB->outB), shared A
__global__ void __launch_bounds__(256, 1) tgemm_dual(
    const float* __restrict__ A,
    const float* __restrict__ WA, const float* __restrict__ WB,
    float* __restrict__ outA, float* __restrict__ outB)
{
    __shared__ TG S;
    const float* W  = blockIdx.y ? WB : WA;
    float* out      = blockIdx.y ? outB : outA;
    tgemm_core(A, 128, nullptr, 0, W, nullptr, nullptr, out, 0, S, blockIdx.x*32);
}

// ---------------- fp32 node GEMM for NOUT=64 (Wout, output precision) -----
template<int NOUT>
__global__ void __launch_bounds__(128, 4) gemm16(
    const float* __restrict__ A1, int K1,
    const float* __restrict__ W,
    const float* __restrict__ bias,
    float* __restrict__ out)
{
    constexpr int ROWS = 24;
    constexpr int NC4  = NOUT / 4;
    constexpr int TR   = 128 / NC4;
    constexpr int R    = ROWS / TR;
    __shared__ float As[2][ROWS*32];
    __shared__ float Ws[2][32*NOUT];

    int tid = threadIdx.x;
    int tx = tid % NC4, ty = tid / NC4;
    int c0 = tx*4, r0 = ty*R;
    int gr0 = blockIdx.x * ROWS;
    int K = K1;
    int ntiles = K >> 5;

    float acc[R][4];
#pragma unroll
    for (int i = 0; i < R; i++)
#pragma unroll
        for (int j = 0; j < 4; j++) acc[i][j] = 0.f;

    {
        for (int i = tid; i < ROWS*8; i += 128){
            int row = i >> 3, kc = i & 7;
            cpa16(sptr(&As[0][row*32 + kc*4]), A1 + (size_t)(gr0+row)*K + kc*4);
        }
        for (int i = tid; i < 8*NOUT; i += 128)
            cpa16(sptr(&Ws[0][i*4]), W + (size_t)i*4);
        cpa_commit();
    }

    for (int t = 0; t < ntiles; t++){
        int b = t & 1;
        if (t + 1 < ntiles){
            int nb = b ^ 1;
            for (int i = tid; i < ROWS*8; i += 128){
                int row = i >> 3, kc = i & 7;
                cpa16(sptr(&As[nb][row*32 + kc*4]),
                      A1 + (size_t)(gr0+row)*K + (t+1)*32 + kc*4);
            }
            const float* Wt = W + (size_t)(t+1)*32*NOUT;
            for (int i = tid; i < 8*NOUT; i += 128)
                cpa16(sptr(&Ws[nb][i*4]), Wt + (size_t)i*4);
            cpa_commit();
            cpa_wait<1>();
        } else {
            cpa_wait<0>();
        }
        __syncthreads();
        const float* as = As[b];
        const float* ws = Ws[b];
#pragma unroll
        for (int kk = 0; kk < 32; kk++){
            float4 w = *(const float4*)&ws[kk*NOUT + c0];
            float a[R];
#pragma unroll
            for (int i = 0; i < R; i++) a[i] = as[(r0+i)*32 + kk];
#pragma unroll
            for (int i = 0; i < R; i++){
                acc[i][0] += a[i]*w.x; acc[i][1] += a[i]*w.y;
                acc[i][2] += a[i]*w.z; acc[i][3] += a[i]*w.w;
            }
        }
        __syncthreads();
    }

    float4 bv = make_float4(0.f,0.f,0.f,0.f);
    if (bias) bv = *(const float4*)&bias[c0];
#pragma unroll
    for (int i = 0; i < R; i++){
        int g = gr0 + r0 + i;
        float4 v;
        v.x = acc[i][0] + bv.x; v.y = acc[i][1] + bv.y;
        v.z = acc[i][2] + bv.z; v.w = acc[i][3] + bv.w;
        *(float4*)&out[(size_t)g*NOUT + c0] = v;
    }
}

// ---------------- persistent fused edge kernel ----------------------------
#define S_M1    0                 // 96 x 132 (m1 tf32, reused as m2 fp32)
#define S_W2    (96*132)          // 128 x 136 (W2 tf32)
#define S_AS    (S_W2 + 128*136)  // 128
#define S_WD2   (S_AS + 128)
#define S_ETAB  (S_WD2 + 128)     // 256
#define S_BE2   (S_ETAB + 256)
#define S_WX    (S_BE2 + 128)
#define S_REL   (S_WX + 128)      // 96*4
#define S_COEF  (S_REL + 384)     // 96
#define S_COEFP (S_COEF + 96)     // 4*96
#define S_AGGP  (S_COEFP + 384)   // 2*128
#define S_COL   (S_AGGP + 256)    // 96 ints
#define S_ET    (S_COL + 96)      // 96 ints
#define S_TOTF  (S_ET + 96)
#define SMEM_BYTES (S_TOTF*4)

__global__ void __launch_bounds__(256, 1) edge_kernel(
    const float* __restrict__ aG, const float* __restrict__ bG,
    const float* __restrict__ Xin, float* __restrict__ Xout,
    float* __restrict__ aggG,
    const int* __restrict__ ecol, const int* __restrict__ chain,
    const float* __restrict__ W2g, const float* __restrict__ be2g,
    const float* __restrict__ Wxg, int layer)
{
    extern __shared__ float sm[];
    float* M1     = sm + S_M1;    // stride 132
    float* W2     = sm + S_W2;    // stride 136
    float* a_s    = sm + S_AS;
    float* wd2_s  = sm + S_WD2;
    float* etab_s = sm + S_ETAB;
    float* be2_s  = sm + S_BE2;
    float* Wx_s   = sm + S_WX;
    float* rel_s  = sm + S_REL;
    float* coef_s = sm + S_COEF;
    float* coefp  = sm + S_COEFP;
    float* aggp   = sm + S_AGGP;
    int*   col_s  = (int*)(sm + S_COL);
    int*   et_s   = (int*)(sm + S_ET);

    int tid = threadIdx.x;

    for (int i = tid; i < 128*32; i += 256){
        int row = i >> 5, cg = (i & 31);
        float4 v = ((const float4*)W2g)[row*32 + cg];
        float4 p;
        p.x = f2tf32f(v.x);
        p.y = f2tf32f(v.y);
        p.z = f2tf32f(v.z);
        p.w = f2tf32f(v.w);
        *(float4*)&W2[row*136 + cg*4] = p;
    }
    if (tid < 128){
        wd2_s[tid]     = g_wd2[layer*128 + tid];
        etab_s[tid]    = g_etab[layer*256 + tid];
        etab_s[128+tid]= g_etab[layer*256 + 128 + tid];
        be2_s[tid]     = be2g[tid];
        Wx_s[tid]      = Wxg[tid];
    }

    int w  = tid >> 5, lane = tid & 31;
    int wr = w >> 2, wc = w & 3;
    int mr = wr * 48, nc0 = wc * 32;
    int gq = lane >> 2, lq = lane & 3;

    for (int r = blockIdx.x; r < NN; r += gridDim.x){
        if (tid < 128) a_s[tid] = aG[(size_t)r*128 + tid];
        if (tid < 96){
            int c = ecol[r*96 + tid];
            col_s[tid] = c;
            float dx = Xin[r*3]   - Xin[c*3];
            float dy = Xin[r*3+1] - Xin[c*3+1];
            float dz = Xin[r*3+2] - Xin[c*3+2];
            rel_s[tid*4]   = dx;
            rel_s[tid*4+1] = dy;
            rel_s[tid*4+2] = dz;
            rel_s[tid*4+3] = dx*dx + dy*dy + dz*dz;
            et_s[tid] = (chain[c] != chain[r]) ? 1 : 0;
        }
        __syncthreads();

        for (int idx = tid; idx < 96*32; idx += 256){
            int j = idx >> 5, k = (idx & 31) * 4;
            int c = col_s[j];
            float4 bn = *(const float4*)&bG[(size_t)c*128 + k];
            float d2 = rel_s[j*4+3];
            const float* et = etab_s + et_s[j]*128;
            float4 p;
            p.x = silu_f(a_s[k+0] + bn.x + d2*wd2_s[k+0] + et[k+0]);
            p.y = silu_f(a_s[k+1] + bn.y + d2*wd2_s[k+1] + et[k+1]);
            p.z = silu_f(a_s[k+2] + bn.z + d2*wd2_s[k+2] + et[k+2]);
            p.w = silu_f(a_s[k+3] + bn.w + d2*wd2_s[k+3] + et[k+3]);
            p.x = f2tf32f(p.x);
            p.y = f2tf32f(p.y);
            p.z = f2tf32f(p.z);
            p.w = f2tf32f(p.w);
            *(float4*)&M1[j*132 + k] = p;
        }
        __syncthreads();

        float acc[3][4][4];
#pragma unroll
        for (int mt = 0; mt < 3; mt++)
#pragma unroll
            for (int nt = 0; nt < 4; nt++)
#pragma unroll
                for (int q = 0; q < 4; q++) acc[mt][nt][q] = 0.f;

#pragma unroll 4
        for (int k0 = 0; k0 < 128; k0 += 8){
            unsigned afr[3][4];
#pragma unroll
            for (int mt = 0; mt < 3; mt++){
                int rr = mr + mt*16 + gq;
                afr[mt][0] = __float_as_uint(M1[rr*132      + k0 + lq]);
                afr[mt][1] = __float_as_uint(M1[(rr+8)*132  + k0 + lq]);
                afr[mt][2] = __float_as_uint(M1[rr*132      + k0 + lq + 4]);
                afr[mt][3] = __float_as_uint(M1[(rr+8)*132  + k0 + lq + 4]);
            }
#pragma unroll
            for (int nt = 0; nt < 4; nt++){
                int n = nc0 + nt*8 + gq;
                unsigned b0 = __float_as_uint(W2[(k0 + lq)*136 + n]);
                unsigned b1 = __float_as_uint(W2[(k0 + lq + 4)*136 + n]);
#pragma unroll
                for (int mt = 0; mt < 3; mt++)
                    mma_tf32(acc[mt][nt], afr[mt], b0, b1);
            }
        }
        __syncthreads();

        float cf[3][2] = {{0.f,0.f},{0.f,0.f},{0.f,0.f}};
#pragma unroll
        for (int mt = 0; mt < 3; mt++){
            int rr = mr + mt*16 + gq;
#pragma unroll
            for (int nt = 0; nt < 4; nt++){
                int col = nc0 + nt*8 + lq*2;
                float wx0 = Wx_s[col], wx1 = Wx_s[col+1];
                float b0 = be2_s[col], b1 = be2_s[col+1];
                float v0 = silu_f(acc[mt][nt][0] + b0);
                float v1 = silu_f(acc[mt][nt][1] + b1);
                float v2 = silu_f(acc[mt][nt][2] + b0);
                float v3 = silu_f(acc[mt][nt][3] + b1);
                M1[rr*132 + col]       = v0;
                M1[rr*132 + col + 1]   = v1;
                M1[(rr+8)*132 + col]   = v2;
                M1[(rr+8)*132 + col+1] = v3;
                cf[mt][0] += v0*wx0 + v1*wx1;
                cf[mt][1] += v2*wx0 + v3*wx1;
            }
        }
#pragma unroll
        for (int mt = 0; mt < 3; mt++){
#pragma unroll
            for (int h = 0; h < 2; h++){
                float c = cf[mt][h];
                c += __shfl_xor_sync(0xffffffffu, c, 1);
                c += __shfl_xor_sync(0xffffffffu, c, 2);
                if (lq == 0) coefp[wc*96 + mr + mt*16 + h*8 + gq] = c;
            }
        }
        __syncthreads();

        if (tid < 96)
            coef_s[tid] = coefp[tid] + coefp[96+tid] + coefp[192+tid] + coefp[288+tid];
        {
            int col = tid & 127, grp = tid >> 7;
            float s = 0.f;
#pragma unroll 8
            for (int j = grp*48; j < grp*48 + 48; j++) s += M1[j*132 + col];
            aggp[grp*128 + col] = s;
        }
        __syncthreads();

        if (tid < 128)
            aggG[(size_t)r*128 + tid] = aggp[tid] + aggp[128 + tid];
        if (w < 3){
            float s = coef_s[lane]    * rel_s[lane*4 + w]
                    + coef_s[lane+32] * rel_s[(lane+32)*4 + w]
                    + coef_s[lane+64] * rel_s[(lane+64)*4 + w];
            s += __shfl_xor_sync(0xffffffffu, s, 16);
            s += __shfl_xor_sync(0xffffffffu, s, 8);
            s += __shfl_xor_sync(0xffffffffu, s, 4);
            s += __shfl_xor_sync(0xffffffffu, s, 2);
            s += __shfl_xor_sync(0xffffffffu, s, 1);
            if (lane == 0) Xout[r*3 + w] = Xin[r*3 + w] + s;
        }
        __syncthreads();
    }
}

// ---------------- losses ----------------
__global__ void loss_partial(const float* __restrict__ H0, const float* __restrict__ H1,
                             const float* __restrict__ X0, const float* __restrict__ X1,
                             const int* __restrict__ shiftp,
                             const float* __restrict__ Xf)
{
    __shared__ float red[64];
    float s[5] = {0,0,0,0,0};
    int shift = *shiftp;
    for (int i = blockIdx.x*blockDim.x + threadIdx.x; i < NN; i += gridDim.x*blockDim.x){
        if (!g_mask[i]) continue;
        int j = (i + shift) % NN; if (j < 0) j += NN;
        float hp = 0.f, hn = 0.f;
        const float4* vp = (const float4*)(g_vH + (size_t)i*64);
        const float4* a1 = (const float4*)(H1 + (size_t)i*64);
        const float4* a0 = (const float4*)(H0 + (size_t)i*64);
        const float4* b1 = (const float4*)(H1 + (size_t)j*64);
        const float4* b0 = (const float4*)(H0 + (size_t)j*64);
#pragma unroll
        for (int k = 0; k < 16; k++){
            float4 p = vp[k], x1 = a1[k], x0 = a0[k], y1 = b1[k], y0 = b0[k];
            float d;
            d = p.x - (x1.x - x0.x); hp += d*d;
            d = p.y - (x1.y - x0.y); hp += d*d;
            d = p.z - (x1.z - x0.z); hp += d*d;
            d = p.w - (x1.w - x0.w); hp += d*d;
            d = p.x - (y1.x - y0.x); hn += d*d;
            d = p.y - (y1.y - y0.y); hn += d*d;
            d = p.z - (y1.z - y0.z); hn += d*d;
            d = p.w - (y1.w - y0.w); hn += d*d;
        }
        float xp = 0.f, xn = 0.f;
        for (int k = 0; k < 3; k++){
            float p = Xf[i*3 + k];
            float d  = p - (X1[i*3+k] - X0[i*3+k]); xp += d*d;
            float dn = p - (X1[j*3+k] - X0[j*3+k]); xn += dn*dn;
        }
        s[0] += hp; s[1] += xp; s[2] += hn; s[3] += xn; s[4] += 1.f;
    }
    for (int q = 0; q < 5; q++){
        red[threadIdx.x] = s[q]; __syncthreads();
        for (int d = 32; d > 0; d >>= 1){
            if (threadIdx.x < d) red[threadIdx.x] += red[threadIdx.x + d];
            __syncthreads();
        }
        if (threadIdx.x == 0) g_lpart[blockIdx.x*5 + q] = red[0];
        __syncthreads();
    }
}

__global__ void loss_final(float* __restrict__ out, int nb){
    if (threadIdx.x == 0){
        float s[5] = {0,0,0,0,0};
        for (int b = 0; b < nb; b++)
            for (int q = 0; q < 5; q++) s[q] += g_lpart[b*5 + q];
        float msum = s[4] + 1e-8f;
        float lHp = s[0]/msum, lXp = s[1]/msum, lHn = s[2]/msum, lXn = s[3]/msum;
        out[0] = lHp - 0.05f*lHn;
        out[1] = lXp - 0.05f*lXn;
        out[2] = lHp; out[3] = lXp; out[4] = lHn; out[5] = lXn;
    }
}

// ---------------- host launch ----------------
extern "C" void kernel_launch(void* const* d_in, const int* in_sizes, int n_in,
                              void* d_out, int out_size)
{
    (void)in_sizes; (void)n_in; (void)out_size;
    const float* H0    = (const float*)d_in[0];
    const float* X0    = (const float*)d_in[1];
    const float* H1    = (const float*)d_in[2];
    const float* X1    = (const float*)d_in[3];
    const float* cond  = (const float*)d_in[4];
    const float* tg    = (const float*)d_in[5];
    const float* Wi1   = (const float*)d_in[6];
    const float* bi1   = (const float*)d_in[7];
    const float* Wi2   = (const float*)d_in[8];
    const float* bi2   = (const float*)d_in[9];
    const float* Wi3   = (const float*)d_in[10];
    const float* bi3   = (const float*)d_in[11];
    const float* etab  = (const float*)d_in[12];
    const float* We1   = (const float*)d_in[13];
    const float* be1   = (const float*)d_in[14];
    const float* We2   = (const float*)d_in[15];
    const float* be2   = (const float*)d_in[16];
    const float* Wx    = (const float*)d_in[17];
    const float* Wh1   = (const float*)d_in[18];
    const float* bh1   = (const float*)d_in[19];
    const float* Wh2   = (const float*)d_in[20];
    const float* bh2   = (const float*)d_in[21];
    const float* Wout  = (const float*)d_in[22];
    const float* bout  = (const float*)d_in[23];
    const int*   edges = (const int*)d_in[24];
    const int*   chain = (const int*)d_in[25];
    const unsigned char* mask = (const unsigned char*)d_in[26];
    const int*   lengths = (const int*)d_in[27];
    const int*   shiftp  = (const int*)d_in[28];
    const int*   ecol = edges + EE;

    float *p_Hin, *p_h, *p_tmp, *p_a, *p_bn, *p_agg, *p_X, *p_vH, *p_tw;
    cudaGetSymbolAddress((void**)&p_Hin, g_Hin);
    cudaGetSymbolAddress((void**)&p_h,   g_h);
    cudaGetSymbolAddress((void**)&p_tmp, g_tmp);
    cudaGetSymbolAddress((void**)&p_a,   g_a);
    cudaGetSymbolAddress((void**)&p_bn,  g_bn);
    cudaGetSymbolAddress((void**)&p_agg, g_agg);
    cudaGetSymbolAddress((void**)&p_X,   g_X);
    cudaGetSymbolAddress((void**)&p_vH,  g_vH);
    cudaGetSymbolAddress((void**)&p_tw,  g_tw);

    int nsm = 148;
    cudaDeviceGetAttribute(&nsm, cudaDevAttrMultiProcessorCount, 0);
    if (nsm <= 0) nsm = 148;

    cudaFuncSetAttribute(edge_kernel,
                         cudaFuncAttributeMaxDynamicSharedMemorySize, SMEM_BYTES);

    setup_all<<<1, 256>>>(mask, lengths);
    node_prep<<<NN, 128>>>(H0, X0, H1, X1, cond, tg);
    prep_edge_all<<<3, 128>>>(We1, be1, etab);
    prep_w<<<128, 256>>>(Wi1, Wi2, Wi3, We1, Wh1, Wh2);

    // input MLP: 320 -> 128 (relu) -> 128 (relu) -> 128
    tgemm<<<96, 256>>>(p_Hin, 320, nullptr, 0, p_tw + OFF_I1, bi1, nullptr, p_h,   1);
    tgemm<<<96, 256>>>(p_h,   128, nullptr, 0, p_tw + OFF_I2, bi2, nullptr, p_tmp, 1);
    tgemm<<<96, 256>>>(p_tmp, 128, nullptr, 0, p_tw + OFF_I3, bi3, nullptr, p_h,   0);

    int cur = 0;
    for (int l = 0; l < 3; l++){
        tgemm_dual<<<dim3(96,2), 256>>>(p_h, p_tw + OFF_EA + l*16384,
                                        p_tw + OFF_EB + l*16384, p_a, p_bn);
        edge_kernel<<<nsm, 256, SMEM_BYTES>>>(p_a, p_bn,
                                             p_X + cur*NN*3, p_X + (1-cur)*NN*3,
                                             p_agg, ecol, chain,
                                             We2 + (size_t)l*128*128,
                                             be2 + l*128, Wx + l*128, l);
        cur = 1 - cur;
        tgemm<<<96, 256>>>(p_h,   128, p_agg, 128, p_tw + OFF_H1 + l*32768,
                           bh1 + l*128, nullptr, p_tmp, 2);
        tgemm<<<96, 256>>>(p_tmp, 128, nullptr, 0,  p_tw + OFF_H2 + l*16384,
                           bh2 + l*128, p_h, p_h, 0);
    }

    gemm16<64><<<128, 128>>>(p_h, 128, Wout, bout, p_vH);

    loss_partial<<<48, 64>>>(H0, H1, X0, X1, shiftp, p_X + cur*NN*3);
    loss_final<<<1, 32>>>((float*)d_out, 48);
}

// round 11
// speedup vs baseline: 3.4173x; 1.0478x over previous
#include <cuda_runtime.h>
#include <math.h>

#define NN 3072
#define BB 32
#define LL 96
#define EE (NN*LL)
#define HIDD 128
#define LATD 64

// ---------------- device scratch (no allocations allowed) ----------------
__device__ float g_Hin[NN*320];
__device__ float g_h[NN*HIDD];
__device__ float g_tmp[NN*HIDD];
__device__ float g_a[NN*HIDD];
__device__ float g_bn[NN*HIDD];
__device__ float g_agg[NN*HIDD];
__device__ float g_X[2][NN*3];
__device__ float g_vH[NN*LATD];
__device__ float g_wd2[3*HIDD];
__device__ float g_etab[3*2*HIDD];
__device__ int   g_off[BB+1];
__device__ int   g_mask[NN];
__device__ float g_lpart[64*5];

// tf32 pre-converted weights (offsets in floats)
#define OFF_I1 0
#define OFF_I2 40960
#define OFF_I3 57344
#define OFF_EA 73728
#define OFF_EB 122880
#define OFF_H1 172032
#define OFF_H2 270336
__device__ float g_tw[319488];

// silu via hardware tanh: silu(x) = 0.5x * (1 + tanh(0.5x))  -- 1 MUFU not 2
__device__ __forceinline__ float silu_f(float v){
    float h = 0.5f * v;
    float t;
    asm("tanh.approx.f32 %0, %1;" : "=f"(t) : "f"(h));
    return h * (1.f + t);
}
__device__ __forceinline__ unsigned f2tf32(float f){
    unsigned r; asm("cvt.rna.tf32.f32 %0, %1;" : "=r"(r) : "f"(f)); return r;
}
__device__ __forceinline__ float f2tf32f(float f){
    return __uint_as_float(f2tf32(f));
}
__device__ __forceinline__ void mma_tf32(float (&d)[4], const unsigned (&a)[4],
                                         unsigned b0, unsigned b1){
    asm volatile("mma.sync.aligned.m16n8k8.row.col.f32.tf32.tf32.f32 "
        "{%0,%1,%2,%3}, {%4,%5,%6,%7}, {%8,%9}, {%0,%1,%2,%3};\n"
        : "+f"(d[0]), "+f"(d[1]), "+f"(d[2]), "+f"(d[3])
        : "r"(a[0]), "r"(a[1]), "r"(a[2]), "r"(a[3]), "r"(b0), "r"(b1));
}
__device__ __forceinline__ unsigned sptr(const void* p){
    return (unsigned)__cvta_generic_to_shared(p);
}
__device__ __forceinline__ void cpa16(unsigned dst, const void* src){
    asm volatile("cp.async.cg.shared.global [%0], [%1], 16;\n" :: "r"(dst), "l"(src));
}
__device__ __forceinline__ void cpa_commit(){
    asm volatile("cp.async.commit_group;\n" ::: "memory");
}
template<int N> __device__ __forceinline__ void cpa_wait(){
    asm volatile("cp.async.wait_group %0;\n" :: "n"(N) : "memory");
}

// ---------------- setup: mask dtype auto-detect + offsets ----------------
__global__ void setup_all(const unsigned char* __restrict__ m,
                          const int* __restrict__ lengths){
    __shared__ int s_big, s_odd;
    int tid = threadIdx.x;
    if (tid == 0){
        s_big = 0; s_odd = 0;
        int s = 0;
        for (int b = 0; b < BB; b++){ g_off[b] = s; s += lengths[b]; }
        g_off[BB] = s;
    }
    __syncthreads();
    int big = 0, odd = 0;
    for (int i = tid; i < NN; i += blockDim.x){
        unsigned char v = m[i];
        if (v > 1) big = 1;
        if ((i & 3) && v) odd = 1;
    }
    if (big) s_big = 1;
    if (odd) s_odd = 1;
    __syncthreads();
    if (s_big){
        const float* mf = (const float*)m;
        for (int i = tid; i < NN; i += blockDim.x) g_mask[i] = (mf[i] != 0.f) ? 1 : 0;
    } else if (s_odd){
        for (int i = tid; i < NN; i += blockDim.x) g_mask[i] = m[i] ? 1 : 0;
    } else {
        const int* mi = (const int*)m;
        for (int i = tid; i < NN; i += blockDim.x) g_mask[i] = mi[i] ? 1 : 0;
    }
}

__global__ void node_prep(const float* __restrict__ H0, const float* __restrict__ X0,
                          const float* __restrict__ H1, const float* __restrict__ X1,
                          const float* __restrict__ cond, const float* __restrict__ tg)
{
    int i = blockIdx.x;
    int k = threadIdx.x;
    __shared__ float t_sh; __shared__ int m_sh;
    if (k == 0){
        int b = 0;
        while (b + 1 < BB && g_off[b+1] <= i) b++;
        t_sh = tg[b];
        m_sh = g_mask[i];
    }
    __syncthreads();
    float t = t_sh; int m = m_sh;
    if (k < 64){
        float h0 = H0[i*64+k], h1 = H1[i*64+k];
        g_Hin[i*320 + k] = m ? (1.f - t)*h0 + t*h1 : h1;
        float f = expf(-logf(10000.f) * (float)k / 63.f);
        float ang = t * f;
        g_Hin[i*320 + 192 + k] = sinf(ang);
        g_Hin[i*320 + 256 + k] = cosf(ang);
    }
    g_Hin[i*320 + 64 + k] = cond[i*128 + k];
    if (k < 3){
        float x0 = X0[i*3+k], x1 = X1[i*3+k];
        g_X[0][i*3+k] = m ? (1.f - t)*x0 + t*x1 : x1;
    }
}

// all 3 layers at once
__global__ void prep_edge_all(const float* __restrict__ We1, const float* __restrict__ be1,
                              const float* __restrict__ etable)
{
    int l = blockIdx.x;
    int k = threadIdx.x;  // 128
    const float* W = We1 + (size_t)l*289*128;
    g_wd2[l*128 + k] = W[256*128 + k];
    for (int t = 0; t < 2; t++){
        float s = be1[l*128 + k];
        for (int e = 0; e < 32; e++) s += etable[t*32 + e] * W[(257 + e)*128 + k];
        g_etab[l*256 + t*128 + k] = s;
    }
}

// tf32 weight pre-conversion (bit-identical to converting at read time)
__global__ void prep_w(const float* __restrict__ Wi1, const float* __restrict__ Wi2,
                       const float* __restrict__ Wi3, const float* __restrict__ We1,
                       const float* __restrict__ Wh1, const float* __restrict__ Wh2)
{
    int i0 = blockIdx.x*blockDim.x + threadIdx.x;
    int st = gridDim.x*blockDim.x;
    for (int i = i0; i < 40960; i += st) g_tw[OFF_I1+i] = f2tf32f(Wi1[i]);
    for (int i = i0; i < 16384; i += st) g_tw[OFF_I2+i] = f2tf32f(Wi2[i]);
    for (int i = i0; i < 16384; i += st) g_tw[OFF_I3+i] = f2tf32f(Wi3[i]);
    for (int i = i0; i < 49152; i += st){
        int l = i >> 14, r = i & 16383;
        g_tw[OFF_EA+i] = f2tf32f(We1[(size_t)l*36992 + r]);
        g_tw[OFF_EB+i] = f2tf32f(We1[(size_t)l*36992 + 16384 + r]);
    }
    for (int i = i0; i < 98304; i += st) g_tw[OFF_H1+i] = f2tf32f(Wh1[i]);
    for (int i = i0; i < 49152; i += st) g_tw[OFF_H2+i] = f2tf32f(Wh2[i]);
}

// ---------------- tensor-core node GEMM (NOUT=128) ------------------------
struct TG {
    float As[2][32*36];
    float Ws[2][32*136];
};

__device__ __forceinline__ void tgemm_core(
    const float* __restrict__ A1, int K1,
    const float* __restrict__ A2, int K2,
    const float* __restrict__ W,
    const float* __restrict__ bias,
    const float* __restrict__ resid,
    float* __restrict__ out, int act, TG& S, int gr0)
{
    int tid = threadIdx.x;
    int w = tid >> 5, lane = tid & 31;
    int wr = w >> 2, wc = w & 3;
    int gq = lane >> 2, lq = lane & 3;
    int K = K1 + K2;
    int ntiles = K >> 5;

    int srow = tid >> 3, skc = tid & 7;

    float acc[4][4];
#pragma unroll
    for (int nt = 0; nt < 4; nt++)
#pragma unroll
        for (int q = 0; q < 4; q++) acc[nt][q] = 0.f;

    {
        int k = skc*4;
        const float* src = (k < K1) ? A1 + (size_t)(gr0+srow)*K1 + k
                                    : A2 + (size_t)(gr0+srow)*K2 + (k - K1);
        cpa16(sptr(&S.As[0][srow*36 + skc*4]), src);
#pragma unroll
        for (int i = 0; i < 4; i++){
            int idx = tid + i*256;
            int kk = idx >> 5, c = idx & 31;
            cpa16(sptr(&S.Ws[0][kk*136 + c*4]), W + (size_t)kk*128 + c*4);
        }
        cpa_commit();
    }

    for (int t = 0; t < ntiles; t++){
        int b = t & 1;
        if (t + 1 < ntiles){
            int nb = b ^ 1;
            int k = (t+1)*32 + skc*4;
            const float* src = (k < K1) ? A1 + (size_t)(gr0+srow)*K1 + k
                                        : A2 + (size_t)(gr0+srow)*K2 + (k - K1);
            cpa16(sptr(&S.As[nb][srow*36 + skc*4]), src);
            const float* Wt = W + (size_t)(t+1)*32*128;
#pragma unroll
            for (int i = 0; i < 4; i++){
                int idx = tid + i*256;
                int kk = idx >> 5, c = idx & 31;
                cpa16(sptr(&S.Ws[nb][kk*136 + c*4]), Wt + (size_t)kk*128 + c*4);
            }
            cpa_commit();
            cpa_wait<1>();
        } else {
            cpa_wait<0>();
        }
        __syncthreads();
        const float* as = S.As[b];
        const float* ws = S.Ws[b];
#pragma unroll
        for (int ks = 0; ks < 4; ks++){
            int k0 = ks*8;
            int rr = wr*16 + gq;
            unsigned afr[4];
            afr[0] = f2tf32(as[rr*36     + k0 + lq]);
            afr[1] = f2tf32(as[(rr+8)*36 + k0 + lq]);
            afr[2] = f2tf32(as[rr*36     + k0 + lq + 4]);
            afr[3] = f2tf32(as[(rr+8)*36 + k0 + lq + 4]);
#pragma unroll
            for (int nt = 0; nt < 4; nt++){
                int n = wc*32 + nt*8 + gq;
                unsigned b0 = __float_as_uint(ws[(k0 + lq)*136 + n]);
                unsigned b1 = __float_as_uint(ws[(k0 + lq + 4)*136 + n]);
                mma_tf32(acc[nt], afr, b0, b1);
            }
        }
        __syncthreads();
    }

    int r0 = gr0 + wr*16 + gq;
#pragma unroll
    for (int nt = 0; nt < 4; nt++){
        int col = wc*32 + nt*8 + lq*2;
        float b0 = bias ? bias[col] : 0.f;
        float b1 = bias ? bias[col+1] : 0.f;
        float v0 = acc[nt][0] + b0, v1 = acc[nt][1] + b1;
        float v2 = acc[nt][2] + b0, v3 = acc[nt][3] + b1;
        if (act == 1){
            v0 = fmaxf(v0,0.f); v1 = fmaxf(v1,0.f);
            v2 = fmaxf(v2,0.f); v3 = fmaxf(v3,0.f);
        } else if (act == 2){
            v0 = silu_f(v0); v1 = silu_f(v1);
            v2 = silu_f(v2); v3 = silu_f(v3);
        }
        if (resid){
            float2 r0v = *(const float2*)&resid[(size_t)r0*128 + col];
            float2 r1v = *(const float2*)&resid[(size_t)(r0+8)*128 + col];
            v0 += r0v.x; v1 += r0v.y; v2 += r1v.x; v3 += r1v.y;
        }
        *(float2*)&out[(size_t)r0*128 + col]     = make_float2(v0, v1);
        *(float2*)&out[(size_t)(r0+8)*128 + col] = make_float2(v2, v3);
    }
}

__global__ void __launch_bounds__(256, 1) tgemm(
    const float* __restrict__ A1, int K1,
    const float* __restrict__ A2, int K2,
    const float* __restrict__ W,
    const float* __restrict__ bias,
    const float* __restrict__ resid,
    float* __restrict__ out, int act)
{
    __shared__ TG S;
    tgemm_core(A1, K1, A2, K2, W, bias, resid, out, act, S, blockIdx.x*32);
}

__global__ void __launch_bounds__(256, 1) tgemm_dual(
    const float* __restrict__ A,
    const float* __restrict__ WA, const float* __restrict__ WB,
    float* __restrict__ outA, float* __restrict__ outB)
{
    __shared__ TG S;
    const float* W  = blockIdx.y ? WB : WA;
    float* out      = blockIdx.y ? outB : outA;
    tgemm_core(A, 128, nullptr, 0, W, nullptr, nullptr, out, 0, S, blockIdx.x*32);
}

// ---------------- fp32 node GEMM for NOUT=64 (Wout, output precision) -----
template<int NOUT>
__global__ void __launch_bounds__(128, 4) gemm16(
    const float* __restrict__ A1, int K1,
    const float* __restrict__ W,
    const float* __restrict__ bias,
    float* __restrict__ out)
{
    constexpr int ROWS = 24;
    constexpr int NC4  = NOUT / 4;
    constexpr int TR   = 128 / NC4;
    constexpr int R    = ROWS / TR;
    __shared__ float As[2][ROWS*32];
    __shared__ float Ws[2][32*NOUT];

    int tid = threadIdx.x;
    int tx = tid % NC4, ty = tid / NC4;
    int c0 = tx*4, r0 = ty*R;
    int gr0 = blockIdx.x * ROWS;
    int K = K1;
    int ntiles = K >> 5;

    float acc[R][4];
#pragma unroll
    for (int i = 0; i < R; i++)
#pragma unroll
        for (int j = 0; j < 4; j++) acc[i][j] = 0.f;

    {
        for (int i = tid; i < ROWS*8; i += 128){
            int row = i >> 3, kc = i & 7;
            cpa16(sptr(&As[0][row*32 + kc*4]), A1 + (size_t)(gr0+row)*K + kc*4);
        }
        for (int i = tid; i < 8*NOUT; i += 128)
            cpa16(sptr(&Ws[0][i*4]), W + (size_t)i*4);
        cpa_commit();
    }

    for (int t = 0; t < ntiles; t++){
        int b = t & 1;
        if (t + 1 < ntiles){
            int nb = b ^ 1;
            for (int i = tid; i < ROWS*8; i += 128){
                int row = i >> 3, kc = i & 7;
                cpa16(sptr(&As[nb][row*32 + kc*4]),
                      A1 + (size_t)(gr0+row)*K + (t+1)*32 + kc*4);
            }
            const float* Wt = W + (size_t)(t+1)*32*NOUT;
            for (int i = tid; i < 8*NOUT; i += 128)
                cpa16(sptr(&Ws[nb][i*4]), Wt + (size_t)i*4);
            cpa_commit();
            cpa_wait<1>();
        } else {
            cpa_wait<0>();
        }
        __syncthreads();
        const float* as = As[b];
        const float* ws = Ws[b];
#pragma unroll
        for (int kk = 0; kk < 32; kk++){
            float4 w = *(const float4*)&ws[kk*NOUT + c0];
            float a[R];
#pragma unroll
            for (int i = 0; i < R; i++) a[i] = as[(r0+i)*32 + kk];
#pragma unroll
            for (int i = 0; i < R; i++){
                acc[i][0] += a[i]*w.x; acc[i][1] += a[i]*w.y;
                acc[i][2] += a[i]*w.z; acc[i][3] += a[i]*w.w;
            }
        }
        __syncthreads();
    }

    float4 bv = make_float4(0.f,0.f,0.f,0.f);
    if (bias) bv = *(const float4*)&bias[c0];
#pragma unroll
    for (int i = 0; i < R; i++){
        int g = gr0 + r0 + i;
        float4 v;
        v.x = acc[i][0] + bv.x; v.y = acc[i][1] + bv.y;
        v.z = acc[i][2] + bv.z; v.w = acc[i][3] + bv.w;
        *(float4*)&out[(size_t)g*NOUT + c0] = v;
    }
}

// ---------------- persistent fused edge kernel ----------------------------
#define S_M1    0                 // 96 x 132 (m1 tf32, reused as m2 fp32)
#define S_W2    (96*132)          // 128 x 136 (W2 tf32)
#define S_AS    (S_W2 + 128*136)  // 128
#define S_WD2   (S_AS + 128)
#define S_ETAB  (S_WD2 + 128)     // 256
#define S_BE2   (S_ETAB + 256)
#define S_WX    (S_BE2 + 128)
#define S_REL   (S_WX + 128)      // 96*4
#define S_COEF  (S_REL + 384)     // 96
#define S_COEFP (S_COEF + 96)     // 4*96
#define S_AGGP  (S_COEFP + 384)   // 2*128
#define S_COL   (S_AGGP + 256)    // 96 ints
#define S_ET    (S_COL + 96)      // 96 ints
#define S_TOTF  (S_ET + 96)
#define SMEM_BYTES (S_TOTF*4)

__global__ void __launch_bounds__(256, 1) edge_kernel(
    const float* __restrict__ aG, const float* __restrict__ bG,
    const float* __restrict__ Xin, float* __restrict__ Xout,
    float* __restrict__ aggG,
    const int* __restrict__ ecol, const int* __restrict__ chain,
    const float* __restrict__ W2g, const float* __restrict__ be2g,
    const float* __restrict__ Wxg, int layer)
{
    extern __shared__ float sm[];
    float* M1     = sm + S_M1;    // stride 132
    float* W2     = sm + S_W2;    // stride 136
    float* a_s    = sm + S_AS;
    float* wd2_s  = sm + S_WD2;
    float* etab_s = sm + S_ETAB;
    float* be2_s  = sm + S_BE2;
    float* Wx_s   = sm + S_WX;
    float* rel_s  = sm + S_REL;
    float* coef_s = sm + S_COEF;
    float* coefp  = sm + S_COEFP;
    float* aggp   = sm + S_AGGP;
    int*   col_s  = (int*)(sm + S_COL);
    int*   et_s   = (int*)(sm + S_ET);

    int tid = threadIdx.x;

    for (int i = tid; i < 128*32; i += 256){
        int row = i >> 5, cg = (i & 31);
        float4 v = ((const float4*)W2g)[row*32 + cg];
        float4 p;
        p.x = f2tf32f(v.x);
        p.y = f2tf32f(v.y);
        p.z = f2tf32f(v.z);
        p.w = f2tf32f(v.w);
        *(float4*)&W2[row*136 + cg*4] = p;
    }
    if (tid < 128){
        wd2_s[tid]     = g_wd2[layer*128 + tid];
        etab_s[tid]    = g_etab[layer*256 + tid];
        etab_s[128+tid]= g_etab[layer*256 + 128 + tid];
        be2_s[tid]     = be2g[tid];
        Wx_s[tid]      = Wxg[tid];
    }

    int w  = tid >> 5, lane = tid & 31;
    int wr = w >> 2, wc = w & 3;
    int mr = wr * 48, nc0 = wc * 32;
    int gq = lane >> 2, lq = lane & 3;

    for (int r = blockIdx.x; r < NN; r += gridDim.x){
        if (tid < 128) a_s[tid] = aG[(size_t)r*128 + tid];
        if (tid < 96){
            int c = ecol[r*96 + tid];
            col_s[tid] = c;
            float dx = Xin[r*3]   - Xin[c*3];
            float dy = Xin[r*3+1] - Xin[c*3+1];
            float dz = Xin[r*3+2] - Xin[c*3+2];
            rel_s[tid*4]   = dx;
            rel_s[tid*4+1] = dy;
            rel_s[tid*4+2] = dz;
            rel_s[tid*4+3] = dx*dx + dy*dy + dz*dz;
            et_s[tid] = (chain[c] != chain[r]) ? 1 : 0;
        }
        __syncthreads();

        for (int idx = tid; idx < 96*32; idx += 256){
            int j = idx >> 5, k = (idx & 31) * 4;
            int c = col_s[j];
            float4 bn = *(const float4*)&bG[(size_t)c*128 + k];
            float d2 = rel_s[j*4+3];
            const float* et = etab_s + et_s[j]*128;
            float4 p;
            p.x = silu_f(a_s[k+0] + bn.x + d2*wd2_s[k+0] + et[k+0]);
            p.y = silu_f(a_s[k+1] + bn.y + d2*wd2_s[k+1] + et[k+1]);
            p.z = silu_f(a_s[k+2] + bn.z + d2*wd2_s[k+2] + et[k+2]);
            p.w = silu_f(a_s[k+3] + bn.w + d2*wd2_s[k+3] + et[k+3]);
            p.x = f2tf32f(p.x);
            p.y = f2tf32f(p.y);
            p.z = f2tf32f(p.z);
            p.w = f2tf32f(p.w);
            *(float4*)&M1[j*132 + k] = p;
        }
        __syncthreads();

        float acc[3][4][4];
#pragma unroll
        for (int mt = 0; mt < 3; mt++)
#pragma unroll
            for (int nt = 0; nt < 4; nt++)
#pragma unroll
                for (int q = 0; q < 4; q++) acc[mt][nt][q] = 0.f;

#pragma unroll 4
        for (int k0 = 0; k0 < 128; k0 += 8){
            unsigned afr[3][4];
#pragma unroll
            for (int mt = 0; mt < 3; mt++){
                int rr = mr + mt*16 + gq;
                afr[mt][0] = __float_as_uint(M1[rr*132      + k0 + lq]);
                afr[mt][1] = __float_as_uint(M1[(rr+8)*132  + k0 + lq]);
                afr[mt][2] = __float_as_uint(M1[rr*132      + k0 + lq + 4]);
                afr[mt][3] = __float_as_uint(M1[(rr+8)*132  + k0 + lq + 4]);
            }
#pragma unroll
            for (int nt = 0; nt < 4; nt++){
                int n = nc0 + nt*8 + gq;
                unsigned b0 = __float_as_uint(W2[(k0 + lq)*136 + n]);
                unsigned b1 = __float_as_uint(W2[(k0 + lq + 4)*136 + n]);
#pragma unroll
                for (int mt = 0; mt < 3; mt++)
                    mma_tf32(acc[mt][nt], afr[mt], b0, b1);
            }
        }
        __syncthreads();

        float cf[3][2] = {{0.f,0.f},{0.f,0.f},{0.f,0.f}};
#pragma unroll
        for (int mt = 0; mt < 3; mt++){
            int rr = mr + mt*16 + gq;
#pragma unroll
            for (int nt = 0; nt < 4; nt++){
                int col = nc0 + nt*8 + lq*2;
                float wx0 = Wx_s[col], wx1 = Wx_s[col+1];
                float b0 = be2_s[col], b1 = be2_s[col+1];
                float v0 = silu_f(acc[mt][nt][0] + b0);
                float v1 = silu_f(acc[mt][nt][1] + b1);
                float v2 = silu_f(acc[mt][nt][2] + b0);
                float v3 = silu_f(acc[mt][nt][3] + b1);
                M1[rr*132 + col]       = v0;
                M1[rr*132 + col + 1]   = v1;
                M1[(rr+8)*132 + col]   = v2;
                M1[(rr+8)*132 + col+1] = v3;
                cf[mt][0] += v0*wx0 + v1*wx1;
                cf[mt][1] += v2*wx0 + v3*wx1;
            }
        }
#pragma unroll
        for (int mt = 0; mt < 3; mt++){
#pragma unroll
            for (int h = 0; h < 2; h++){
                float c = cf[mt][h];
                c += __shfl_xor_sync(0xffffffffu, c, 1);
                c += __shfl_xor_sync(0xffffffffu, c, 2);
                if (lq == 0) coefp[wc*96 + mr + mt*16 + h*8 + gq] = c;
            }
        }
        __syncthreads();

        if (tid < 96)
            coef_s[tid] = coefp[tid] + coefp[96+tid] + coefp[192+tid] + coefp[288+tid];
        {
            int col = tid & 127, grp = tid >> 7;
            float s = 0.f;
#pragma unroll 8
            for (int j = grp*48; j < grp*48 + 48; j++) s += M1[j*132 + col];
            aggp[grp*128 + col] = s;
        }
        __syncthreads();

        if (tid < 128)
            aggG[(size_t)r*128 + tid] = aggp[tid] + aggp[128 + tid];
        if (w < 3){
            float s = coef_s[lane]    * rel_s[lane*4 + w]
                    + coef_s[lane+32] * rel_s[(lane+32)*4 + w]
                    + coef_s[lane+64] * rel_s[(lane+64)*4 + w];
            s += __shfl_xor_sync(0xffffffffu, s, 16);
            s += __shfl_xor_sync(0xffffffffu, s, 8);
            s += __shfl_xor_sync(0xffffffffu, s, 4);
            s += __shfl_xor_sync(0xffffffffu, s, 2);
            s += __shfl_xor_sync(0xffffffffu, s, 1);
            if (lane == 0) Xout[r*3 + w] = Xin[r*3 + w] + s;
        }
        __syncthreads();
    }
}

// ---------------- losses ----------------
__global__ void loss_partial(const float* __restrict__ H0, const float* __restrict__ H1,
                             const float* __restrict__ X0, const float* __restrict__ X1,
                             const int* __restrict__ shiftp,
                             const float* __restrict__ Xf)
{
    __shared__ float red[64];
    float s[5] = {0,0,0,0,0};
    int shift = *shiftp;
    for (int i = blockIdx.x*blockDim.x + threadIdx.x; i < NN; i += gridDim.x*blockDim.x){
        if (!g_mask[i]) continue;
        int j = (i + shift) % NN; if (j < 0) j += NN;
        float hp = 0.f, hn = 0.f;
        const float4* vp = (const float4*)(g_vH + (size_t)i*64);
        const float4* a1 = (const float4*)(H1 + (size_t)i*64);
        const float4* a0 = (const float4*)(H0 + (size_t)i*64);
        const float4* b1 = (const float4*)(H1 + (size_t)j*64);
        const float4* b0 = (const float4*)(H0 + (size_t)j*64);
#pragma unroll
        for (int k = 0; k < 16; k++){
            float4 p = vp[k], x1 = a1[k], x0 = a0[k], y1 = b1[k], y0 = b0[k];
            float d;
            d = p.x - (x1.x - x0.x); hp += d*d;
            d = p.y - (x1.y - x0.y); hp += d*d;
            d = p.z - (x1.z - x0.z); hp += d*d;
            d = p.w - (x1.w - x0.w); hp += d*d;
            d = p.x - (y1.x - y0.x); hn += d*d;
            d = p.y - (y1.y - y0.y); hn += d*d;
            d = p.z - (y1.z - y0.z); hn += d*d;
            d = p.w - (y1.w - y0.w); hn += d*d;
        }
        float xp = 0.f, xn = 0.f;
        for (int k = 0; k < 3; k++){
            float p = Xf[i*3 + k];
            float d  = p - (X1[i*3+k] - X0[i*3+k]); xp += d*d;
            float dn = p - (X1[j*3+k] - X0[j*3+k]); xn += dn*dn;
        }
        s[0] += hp; s[1] += xp; s[2] += hn; s[3] += xn; s[4] += 1.f;
    }
    for (int q = 0; q < 5; q++){
        red[threadIdx.x] = s[q]; __syncthreads();
        for (int d = 32; d > 0; d >>= 1){
            if (threadIdx.x < d) red[threadIdx.x] += red[threadIdx.x + d];
            __syncthreads();
        }
        if (threadIdx.x == 0) g_lpart[blockIdx.x*5 + q] = red[0];
        __syncthreads();
    }
}

__global__ void loss_final(float* __restrict__ out, int nb){
    if (threadIdx.x == 0){
        float s[5] = {0,0,0,0,0};
        for (int b = 0; b < nb; b++)
            for (int q = 0; q < 5; q++) s[q] += g_lpart[b*5 + q];
        float msum = s[4] + 1e-8f;
        float lHp = s[0]/msum, lXp = s[1]/msum, lHn = s[2]/msum, lXn = s[3]/msum;
        out[0] = lHp - 0.05f*lHn;
        out[1] = lXp - 0.05f*lXn;
        out[2] = lHp; out[3] = lXp; out[4] = lHn; out[5] = lXn;
    }
}

// ---------------- host launch ----------------
extern "C" void kernel_launch(void* const* d_in, const int* in_sizes, int n_in,
                              void* d_out, int out_size)
{
    (void)in_sizes; (void)n_in; (void)out_size;
    const float* H0    = (const float*)d_in[0];
    const float* X0    = (const float*)d_in[1];
    const float* H1    = (const float*)d_in[2];
    const float* X1    = (const float*)d_in[3];
    const float* cond  = (const float*)d_in[4];
    const float* tg    = (const float*)d_in[5];
    const float* Wi1   = (const float*)d_in[6];
    const float* bi1   = (const float*)d_in[7];
    const float* Wi2   = (const float*)d_in[8];
    const float* bi2   = (const float*)d_in[9];
    const float* Wi3   = (const float*)d_in[10];
    const float* bi3   = (const float*)d_in[11];
    const float* etab  = (const float*)d_in[12];
    const float* We1   = (const float*)d_in[13];
    const float* be1   = (const float*)d_in[14];
    const float* We2   = (const float*)d_in[15];
    const float* be2   = (const float*)d_in[16];
    const float* Wx    = (const float*)d_in[17];
    const float* Wh1   = (const float*)d_in[18];
    const float* bh1   = (const float*)d_in[19];
    const float* Wh2   = (const float*)d_in[20];
    const float* bh2   = (const float*)d_in[21];
    const float* Wout  = (const float*)d_in[22];
    const float* bout  = (const float*)d_in[23];
    const int*   edges = (const int*)d_in[24];
    const int*   chain = (const int*)d_in[25];
    const unsigned char* mask = (const unsigned char*)d_in[26];
    const int*   lengths = (const int*)d_in[27];
    const int*   shiftp  = (const int*)d_in[28];
    const int*   ecol = edges + EE;

    float *p_Hin, *p_h, *p_tmp, *p_a, *p_bn, *p_agg, *p_X, *p_vH, *p_tw;
    cudaGetSymbolAddress((void**)&p_Hin, g_Hin);
    cudaGetSymbolAddress((void**)&p_h,   g_h);
    cudaGetSymbolAddress((void**)&p_tmp, g_tmp);
    cudaGetSymbolAddress((void**)&p_a,   g_a);
    cudaGetSymbolAddress((void**)&p_bn,  g_bn);
    cudaGetSymbolAddress((void**)&p_agg, g_agg);
    cudaGetSymbolAddress((void**)&p_X,   g_X);
    cudaGetSymbolAddress((void**)&p_vH,  g_vH);
    cudaGetSymbolAddress((void**)&p_tw,  g_tw);

    int nsm = 148;
    cudaDeviceGetAttribute(&nsm, cudaDevAttrMultiProcessorCount, 0);
    if (nsm <= 0) nsm = 148;

    cudaFuncSetAttribute(edge_kernel,
                         cudaFuncAttributeMaxDynamicSharedMemorySize, SMEM_BYTES);

    setup_all<<<1, 256>>>(mask, lengths);
    node_prep<<<NN, 128>>>(H0, X0, H1, X1, cond, tg);
    prep_edge_all<<<3, 128>>>(We1, be1, etab);
    prep_w<<<128, 256>>>(Wi1, Wi2, Wi3, We1, Wh1, Wh2);

    // input MLP: 320 -> 128 (relu) -> 128 (relu) -> 128
    tgemm<<<96, 256>>>(p_Hin, 320, nullptr, 0, p_tw + OFF_I1, bi1, nullptr, p_h,   1);
    tgemm<<<96, 256>>>(p_h,   128, nullptr, 0, p_tw + OFF_I2, bi2, nullptr, p_tmp, 1);
    tgemm<<<96, 256>>>(p_tmp, 128, nullptr, 0, p_tw + OFF_I3, bi3, nullptr, p_h,   0);

    int cur = 0;
    for (int l = 0; l < 3; l++){
        tgemm_dual<<<dim3(96,2), 256>>>(p_h, p_tw + OFF_EA + l*16384,
                                        p_tw + OFF_EB + l*16384, p_a, p_bn);
        edge_kernel<<<nsm, 256, SMEM_BYTES>>>(p_a, p_bn,
                                             p_X + cur*NN*3, p_X + (1-cur)*NN*3,
                                             p_agg, ecol, chain,
                                             We2 + (size_t)l*128*128,
                                             be2 + l*128, Wx + l*128, l);
        cur = 1 - cur;
        tgemm<<<96, 256>>>(p_h,   128, p_agg, 128, p_tw + OFF_H1 + l*32768,
                           bh1 + l*128, nullptr, p_tmp, 2);
        tgemm<<<96, 256>>>(p_tmp, 128, nullptr, 0,  p_tw + OFF_H2 + l*16384,
                           bh2 + l*128, p_h, p_h, 0);
    }

    gemm16<64><<<128, 128>>>(p_h, 128, Wout, bout, p_vH);

    loss_partial<<<48, 64>>>(H0, H1, X0, X1, shiftp, p_X + cur*NN*3);
    loss_final<<<1, 32>>>((float*)d_out, 48);
}

// round 13
// speedup vs baseline: 3.9253x; 1.1487x over previous
#include <cuda_runtime.h>
#include <math.h>

#define NN 3072
#define BB 32
#define LL 96
#define EE (NN*LL)
#define HIDD 128
#define LATD 64

// ---------------- device scratch (no allocations allowed) ----------------
__device__ float g_Hin[NN*320];
__device__ float g_h[NN*HIDD];
__device__ float g_tmp[NN*HIDD];
__device__ float g_a[NN*HIDD];
__device__ float g_bn[NN*HIDD];
__device__ float g_agg[NN*HIDD];
__device__ float g_X[2][NN*3];
__device__ float g_vH[NN*LATD];
__device__ float g_wd2[3*HIDD];
__device__ float g_etab[3*2*HIDD];
__device__ int   g_off[BB+1];
__device__ int   g_mask[NN];
__device__ float g_lpart[64*5];

// tf32 pre-converted weights (offsets in floats)
#define OFF_I1 0
#define OFF_I2 40960
#define OFF_I3 57344
#define OFF_EA 73728
#define OFF_EB 122880
#define OFF_H1 172032
#define OFF_H2 270336
__device__ float g_tw[319488];

// silu via hardware tanh: silu(x) = 0.5x * (1 + tanh(0.5x))  -- 1 MUFU not 2
__device__ __forceinline__ float silu_f(float v){
    float h = 0.5f * v;
    float t;
    asm("tanh.approx.f32 %0, %1;" : "=f"(t) : "f"(h));
    return h * (1.f + t);
}
__device__ __forceinline__ unsigned f2tf32(float f){
    unsigned r; asm("cvt.rna.tf32.f32 %0, %1;" : "=r"(r) : "f"(f)); return r;
}
__device__ __forceinline__ float f2tf32f(float f){
    return __uint_as_float(f2tf32(f));
}
__device__ __forceinline__ void mma_tf32(float (&d)[4], const unsigned (&a)[4],
                                         unsigned b0, unsigned b1){
    asm volatile("mma.sync.aligned.m16n8k8.row.col.f32.tf32.tf32.f32 "
        "{%0,%1,%2,%3}, {%4,%5,%6,%7}, {%8,%9}, {%0,%1,%2,%3};\n"
        : "+f"(d[0]), "+f"(d[1]), "+f"(d[2]), "+f"(d[3])
        : "r"(a[0]), "r"(a[1]), "r"(a[2]), "r"(a[3]), "r"(b0), "r"(b1));
}
__device__ __forceinline__ unsigned sptr(const void* p){
    return (unsigned)__cvta_generic_to_shared(p);
}
__device__ __forceinline__ void cpa16(unsigned dst, const void* src){
    asm volatile("cp.async.cg.shared.global [%0], [%1], 16;\n" :: "r"(dst), "l"(src));
}
__device__ __forceinline__ void cpa_commit(){
    asm volatile("cp.async.commit_group;\n" ::: "memory");
}
template<int N> __device__ __forceinline__ void cpa_wait(){
    asm volatile("cp.async.wait_group %0;\n" :: "n"(N) : "memory");
}

// ---------------- setup: mask dtype auto-detect + offsets ----------------
__global__ void setup_all(const unsigned char* __restrict__ m,
                          const int* __restrict__ lengths){
    __shared__ int s_big, s_odd;
    int tid = threadIdx.x;
    if (tid == 0){
        s_big = 0; s_odd = 0;
        int s = 0;
        for (int b = 0; b < BB; b++){ g_off[b] = s; s += lengths[b]; }
        g_off[BB] = s;
    }
    __syncthreads();
    int big = 0, odd = 0;
    for (int i = tid; i < NN; i += blockDim.x){
        unsigned char v = m[i];
        if (v > 1) big = 1;
        if ((i & 3) && v) odd = 1;
    }
    if (big) s_big = 1;
    if (odd) s_odd = 1;
    __syncthreads();
    if (s_big){
        const float* mf = (const float*)m;
        for (int i = tid; i < NN; i += blockDim.x) g_mask[i] = (mf[i] != 0.f) ? 1 : 0;
    } else if (s_odd){
        for (int i = tid; i < NN; i += blockDim.x) g_mask[i] = m[i] ? 1 : 0;
    } else {
        const int* mi = (const int*)m;
        for (int i = tid; i < NN; i += blockDim.x) g_mask[i] = mi[i] ? 1 : 0;
    }
}

__global__ void node_prep(const float* __restrict__ H0, const float* __restrict__ X0,
                          const float* __restrict__ H1, const float* __restrict__ X1,
                          const float* __restrict__ cond, const float* __restrict__ tg)
{
    int i = blockIdx.x;
    int k = threadIdx.x;
    __shared__ float t_sh; __shared__ int m_sh;
    if (k == 0){
        int b = 0;
        while (b + 1 < BB && g_off[b+1] <= i) b++;
        t_sh = tg[b];
        m_sh = g_mask[i];
    }
    __syncthreads();
    float t = t_sh; int m = m_sh;
    if (k < 64){
        float h0 = H0[i*64+k], h1 = H1[i*64+k];
        g_Hin[i*320 + k] = m ? (1.f - t)*h0 + t*h1 : h1;
        float f = expf(-logf(10000.f) * (float)k / 63.f);
        float ang = t * f;
        g_Hin[i*320 + 192 + k] = sinf(ang);
        g_Hin[i*320 + 256 + k] = cosf(ang);
    }
    g_Hin[i*320 + 64 + k] = cond[i*128 + k];
    if (k < 3){
        float x0 = X0[i*3+k], x1 = X1[i*3+k];
        g_X[0][i*3+k] = m ? (1.f - t)*x0 + t*x1 : x1;
    }
}

// all 3 layers at once
__global__ void prep_edge_all(const float* __restrict__ We1, const float* __restrict__ be1,
                              const float* __restrict__ etable)
{
    int l = blockIdx.x;
    int k = threadIdx.x;  // 128
    const float* W = We1 + (size_t)l*289*128;
    g_wd2[l*128 + k] = W[256*128 + k];
    for (int t = 0; t < 2; t++){
        float s = be1[l*128 + k];
        for (int e = 0; e < 32; e++) s += etable[t*32 + e] * W[(257 + e)*128 + k];
        g_etab[l*256 + t*128 + k] = s;
    }
}

// tf32 weight pre-conversion (bit-identical to converting at read time)
__global__ void prep_w(const float* __restrict__ Wi1, const float* __restrict__ Wi2,
                       const float* __restrict__ Wi3, const float* __restrict__ We1,
                       const float* __restrict__ Wh1, const float* __restrict__ Wh2)
{
    int i0 = blockIdx.x*blockDim.x + threadIdx.x;
    int st = gridDim.x*blockDim.x;
    for (int i = i0; i < 40960; i += st) g_tw[OFF_I1+i] = f2tf32f(Wi1[i]);
    for (int i = i0; i < 16384; i += st) g_tw[OFF_I2+i] = f2tf32f(Wi2[i]);
    for (int i = i0; i < 16384; i += st) g_tw[OFF_I3+i] = f2tf32f(Wi3[i]);
    for (int i = i0; i < 49152; i += st){
        int l = i >> 14, r = i & 16383;
        g_tw[OFF_EA+i] = f2tf32f(We1[(size_t)l*36992 + r]);
        g_tw[OFF_EB+i] = f2tf32f(We1[(size_t)l*36992 + 16384 + r]);
    }
    for (int i = i0; i < 98304; i += st) g_tw[OFF_H1+i] = f2tf32f(Wh1[i]);
    for (int i = i0; i < 49152; i += st) g_tw[OFF_H2+i] = f2tf32f(Wh2[i]);
}

// ---------------- tensor-core node GEMM (NOUT=128) ------------------------
struct TG {
    float As[2][32*36];
    float Ws[2][32*136];
};

__device__ __forceinline__ void tgemm_core(
    const float* __restrict__ A1, int K1,
    const float* __restrict__ A2, int K2,
    const float* __restrict__ W,
    const float* __restrict__ bias,
    const float* __restrict__ resid,
    float* __restrict__ out, int act, TG& S, int gr0)
{
    int tid = threadIdx.x;
    int w = tid >> 5, lane = tid & 31;
    int wr = w >> 2, wc = w & 3;
    int gq = lane >> 2, lq = lane & 3;
    int K = K1 + K2;
    int ntiles = K >> 5;

    int srow = tid >> 3, skc = tid & 7;

    float acc[4][4];
#pragma unroll
    for (int nt = 0; nt < 4; nt++)
#pragma unroll
        for (int q = 0; q < 4; q++) acc[nt][q] = 0.f;

    {
        int k = skc*4;
        const float* src = (k < K1) ? A1 + (size_t)(gr0+srow)*K1 + k
                                    : A2 + (size_t)(gr0+srow)*K2 + (k - K1);
        cpa16(sptr(&S.As[0][srow*36 + skc*4]), src);
#pragma unroll
        for (int i = 0; i < 4; i++){
            int idx = tid + i*256;
            int kk = idx >> 5, c = idx & 31;
            cpa16(sptr(&S.Ws[0][kk*136 + c*4]), W + (size_t)kk*128 + c*4);
        }
        cpa_commit();
    }

    for (int t = 0; t < ntiles; t++){
        int b = t & 1;
        if (t + 1 < ntiles){
            int nb = b ^ 1;
            int k = (t+1)*32 + skc*4;
            const float* src = (k < K1) ? A1 + (size_t)(gr0+srow)*K1 + k
                                        : A2 + (size_t)(gr0+srow)*K2 + (k - K1);
            cpa16(sptr(&S.As[nb][srow*36 + skc*4]), src);
            const float* Wt = W + (size_t)(t+1)*32*128;
#pragma unroll
            for (int i = 0; i < 4; i++){
                int idx = tid + i*256;
                int kk = idx >> 5, c = idx & 31;
                cpa16(sptr(&S.Ws[nb][kk*136 + c*4]), Wt + (size_t)kk*128 + c*4);
            }
            cpa_commit();
            cpa_wait<1>();
        } else {
            cpa_wait<0>();
        }
        __syncthreads();
        const float* as = S.As[b];
        const float* ws = S.Ws[b];
#pragma unroll
        for (int ks = 0; ks < 4; ks++){
            int k0 = ks*8;
            int rr = wr*16 + gq;
            unsigned afr[4];
            afr[0] = f2tf32(as[rr*36     + k0 + lq]);
            afr[1] = f2tf32(as[(rr+8)*36 + k0 + lq]);
            afr[2] = f2tf32(as[rr*36     + k0 + lq + 4]);
            afr[3] = f2tf32(as[(rr+8)*36 + k0 + lq + 4]);
#pragma unroll
            for (int nt = 0; nt < 4; nt++){
                int n = wc*32 + nt*8 + gq;
                unsigned b0 = __float_as_uint(ws[(k0 + lq)*136 + n]);
                unsigned b1 = __float_as_uint(ws[(k0 + lq + 4)*136 + n]);
                mma_tf32(acc[nt], afr, b0, b1);
            }
        }
        __syncthreads();
    }

    int r0 = gr0 + wr*16 + gq;
#pragma unroll
    for (int nt = 0; nt < 4; nt++){
        int col = wc*32 + nt*8 + lq*2;
        float b0 = bias ? bias[col] : 0.f;
        float b1 = bias ? bias[col+1] : 0.f;
        float v0 = acc[nt][0] + b0, v1 = acc[nt][1] + b1;
        float v2 = acc[nt][2] + b0, v3 = acc[nt][3] + b1;
        if (act == 1){
            v0 = fmaxf(v0,0.f); v1 = fmaxf(v1,0.f);
            v2 = fmaxf(v2,0.f); v3 = fmaxf(v3,0.f);
        } else if (act == 2){
            v0 = silu_f(v0); v1 = silu_f(v1);
            v2 = silu_f(v2); v3 = silu_f(v3);
        }
        if (resid){
            float2 r0v = *(const float2*)&resid[(size_t)r0*128 + col];
            float2 r1v = *(const float2*)&resid[(size_t)(r0+8)*128 + col];
            v0 += r0v.x; v1 += r0v.y; v2 += r1v.x; v3 += r1v.y;
        }
        *(float2*)&out[(size_t)r0*128 + col]     = make_float2(v0, v1);
        *(float2*)&out[(size_t)(r0+8)*128 + col] = make_float2(v2, v3);
    }
}

__global__ void __launch_bounds__(256, 1) tgemm(
    const float* __restrict__ A1, int K1,
    const float* __restrict__ A2, int K2,
    const float* __restrict__ W,
    const float* __restrict__ bias,
    const float* __restrict__ resid,
    float* __restrict__ out, int act)
{
    __shared__ TG S;
    tgemm_core(A1, K1, A2, K2, W, bias, resid, out, act, S, blockIdx.x*32);
}

__global__ void __launch_bounds__(256, 1) tgemm_dual(
    const float* __restrict__ A,
    const float* __restrict__ WA, const float* __restrict__ WB,
    float* __restrict__ outA, float* __restrict__ outB)
{
    __shared__ TG S;
    const float* W  = blockIdx.y ? WB : WA;
    float* out      = blockIdx.y ? outB : outA;
    tgemm_core(A, 128, nullptr, 0, W, nullptr, nullptr, out, 0, S, blockIdx.x*32);
}

// ---------------- fp32 node GEMM for NOUT=64 (Wout, output precision) -----
template<int NOUT>
__global__ void __launch_bounds__(128, 4) gemm16(
    const float* __restrict__ A1, int K1,
    const float* __restrict__ W,
    const float* __restrict__ bias,
    float* __restrict__ out)
{
    constexpr int ROWS = 24;
    constexpr int NC4  = NOUT / 4;
    constexpr int TR   = 128 / NC4;
    constexpr int R    = ROWS / TR;
    __shared__ float As[2][ROWS*32];
    __shared__ float Ws[2][32*NOUT];

    int tid = threadIdx.x;
    int tx = tid % NC4, ty = tid / NC4;
    int c0 = tx*4, r0 = ty*R;
    int gr0 = blockIdx.x * ROWS;
    int K = K1;
    int ntiles = K >> 5;

    float acc[R][4];
#pragma unroll
    for (int i = 0; i < R; i++)
#pragma unroll
        for (int j = 0; j < 4; j++) acc[i][j] = 0.f;

    {
        for (int i = tid; i < ROWS*8; i += 128){
            int row = i >> 3, kc = i & 7;
            cpa16(sptr(&As[0][row*32 + kc*4]), A1 + (size_t)(gr0+row)*K + kc*4);
        }
        for (int i = tid; i < 8*NOUT; i += 128)
            cpa16(sptr(&Ws[0][i*4]), W + (size_t)i*4);
        cpa_commit();
    }

    for (int t = 0; t < ntiles; t++){
        int b = t & 1;
        if (t + 1 < ntiles){
            int nb = b ^ 1;
            for (int i = tid; i < ROWS*8; i += 128){
                int row = i >> 3, kc = i & 7;
                cpa16(sptr(&As[nb][row*32 + kc*4]),
                      A1 + (size_t)(gr0+row)*K + (t+1)*32 + kc*4);
            }
            const float* Wt = W + (size_t)(t+1)*32*NOUT;
            for (int i = tid; i < 8*NOUT; i += 128)
                cpa16(sptr(&Ws[nb][i*4]), Wt + (size_t)i*4);
            cpa_commit();
            cpa_wait<1>();
        } else {
            cpa_wait<0>();
        }
        __syncthreads();
        const float* as = As[b];
        const float* ws = Ws[b];
#pragma unroll
        for (int kk = 0; kk < 32; kk++){
            float4 w = *(const float4*)&ws[kk*NOUT + c0];
            float a[R];
#pragma unroll
            for (int i = 0; i < R; i++) a[i] = as[(r0+i)*32 + kk];
#pragma unroll
            for (int i = 0; i < R; i++){
                acc[i][0] += a[i]*w.x; acc[i][1] += a[i]*w.y;
                acc[i][2] += a[i]*w.z; acc[i][3] += a[i]*w.w;
            }
        }
        __syncthreads();
    }

    float4 bv = make_float4(0.f,0.f,0.f,0.f);
    if (bias) bv = *(const float4*)&bias[c0];
#pragma unroll
    for (int i = 0; i < R; i++){
        int g = gr0 + r0 + i;
        float4 v;
        v.x = acc[i][0] + bv.x; v.y = acc[i][1] + bv.y;
        v.z = acc[i][2] + bv.z; v.w = acc[i][3] + bv.w;
        *(float4*)&out[(size_t)g*NOUT + c0] = v;
    }
}

// ---------------- persistent fused edge kernel (gather double-buffered) ---
#define S_M1    0                     // 96*132 = 12672
#define S_W2    12672                 // 128*136 = 17408
#define S_BRAW  30080                 // 96*128 = 12288 (single buffer)
#define S_A     42368                 // 2*128
#define S_WD2   42624                 // 128
#define S_ETAB  42752                 // 256
#define S_BE2   43008                 // 128
#define S_WX    43136                 // 128
#define S_REL   43264                 // 2*96*4 = 768
#define S_COEF  44032                 // 96
#define S_COEFP 44128                 // 384
#define S_AGGP  44512                 // 256
#define S_ET    44768                 // 2*96 ints
#define S_TOTF  44960
#define SMEM_BYTES (S_TOTF*4)

__global__ void __launch_bounds__(256, 1) edge_kernel(
    const float* __restrict__ aG, const float* __restrict__ bG,
    const float* __restrict__ Xin, float* __restrict__ Xout,
    float* __restrict__ aggG,
    const int* __restrict__ ecol, const int* __restrict__ chain,
    const float* __restrict__ W2g, const float* __restrict__ be2g,
    const float* __restrict__ Wxg, int layer)
{
    extern __shared__ float sm[];
    float* M1     = sm + S_M1;    // stride 132
    float* W2     = sm + S_W2;    // stride 136
    float* braw   = sm + S_BRAW;  // 96 x 128
    float* a_s    = sm + S_A;     // [2][128]
    float* wd2_s  = sm + S_WD2;
    float* etab_s = sm + S_ETAB;
    float* be2_s  = sm + S_BE2;
    float* Wx_s   = sm + S_WX;
    float* rel_s  = sm + S_REL;   // [2][96*4]
    float* coef_s = sm + S_COEF;
    float* coefp  = sm + S_COEFP;
    float* aggp   = sm + S_AGGP;
    int*   et_s   = (int*)(sm + S_ET);  // [2][96]

    int tid = threadIdx.x;

    // one-time staging: W2 (tf32, stride 136) + per-layer constants
    for (int i = tid; i < 128*32; i += 256){
        int row = i >> 5, cg = (i & 31);
        float4 v = ((const float4*)W2g)[row*32 + cg];
        float4 p;
        p.x = f2tf32f(v.x);
        p.y = f2tf32f(v.y);
        p.z = f2tf32f(v.z);
        p.w = f2tf32f(v.w);
        *(float4*)&W2[row*136 + cg*4] = p;
    }
    if (tid < 128){
        wd2_s[tid]     = g_wd2[layer*128 + tid];
        etab_s[tid]    = g_etab[layer*256 + tid];
        etab_s[128+tid]= g_etab[layer*256 + 128 + tid];
        be2_s[tid]     = be2g[tid];
        Wx_s[tid]      = Wxg[tid];
    }

    int w  = tid >> 5, lane = tid & 31;
    int wr = w >> 2, wc = w & 3;
    int mr = wr * 48, nc0 = wc * 32;
    int gq = lane >> 2, lq = lane & 3;

    int cur = 0;
    int r = blockIdx.x;

    // prologue prefetch for first node (full 128-float rows: 32 x 16B chunks)
    if (r < NN){
        if (tid < 96){
            int c = ecol[r*96 + tid];
            float dx = Xin[r*3]   - Xin[c*3];
            float dy = Xin[r*3+1] - Xin[c*3+1];
            float dz = Xin[r*3+2] - Xin[c*3+2];
            rel_s[tid*4]   = dx;
            rel_s[tid*4+1] = dy;
            rel_s[tid*4+2] = dz;
            rel_s[tid*4+3] = dx*dx + dy*dy + dz*dz;
            et_s[tid] = (chain[c] != chain[r]) ? 1 : 0;
#pragma unroll
            for (int ch = 0; ch < 32; ch++)
                cpa16(sptr(&braw[tid*128 + ch*4]), bG + (size_t)c*128 + ch*4);
        } else if (tid < 128){
            cpa16(sptr(&a_s[(tid-96)*4]), aG + (size_t)r*128 + (tid-96)*4);
        }
        cpa_commit();
    }

    while (r < NN){
        int r_next = r + gridDim.x;
        cpa_wait<0>();
        __syncthreads();   // braw / a_s[cur] / rel[cur] / et[cur] ready; prev iter fully retired

        // phase 1: m1 = silu(a + b + d2*wd2 + etab) -> tf32 M1
        {
            const float* aa = a_s + cur*128;
            const float* rl = rel_s + cur*384;
            const int*   et = et_s + cur*96;
            for (int idx = tid; idx < 96*32; idx += 256){
                int j = idx >> 5, k = (idx & 31) * 4;
                float4 bn = *(const float4*)&braw[j*128 + k];
                float d2 = rl[j*4+3];
                const float* etb = etab_s + et[j]*128;
                float4 p;
                p.x = silu_f(aa[k+0] + bn.x + d2*wd2_s[k+0] + etb[k+0]);
                p.y = silu_f(aa[k+1] + bn.y + d2*wd2_s[k+1] + etb[k+1]);
                p.z = silu_f(aa[k+2] + bn.z + d2*wd2_s[k+2] + etb[k+2]);
                p.w = silu_f(aa[k+3] + bn.w + d2*wd2_s[k+3] + etb[k+3]);
                p.x = f2tf32f(p.x);
                p.y = f2tf32f(p.y);
                p.z = f2tf32f(p.z);
                p.w = f2tf32f(p.w);
                *(float4*)&M1[j*132 + k] = p;
            }
        }
        __syncthreads();   // braw fully consumed; M1 ready

        // prefetch next node's data (lands during tensor phase)
        if (r_next < NN){
            int nxt = cur ^ 1;
            if (tid < 96){
                int c = ecol[r_next*96 + tid];
                float dx = Xin[r_next*3]   - Xin[c*3];
                float dy = Xin[r_next*3+1] - Xin[c*3+1];
                float dz = Xin[r_next*3+2] - Xin[c*3+2];
                rel_s[nxt*384 + tid*4]   = dx;
                rel_s[nxt*384 + tid*4+1] = dy;
                rel_s[nxt*384 + tid*4+2] = dz;
                rel_s[nxt*384 + tid*4+3] = dx*dx + dy*dy + dz*dz;
                et_s[nxt*96 + tid] = (chain[c] != chain[r_next]) ? 1 : 0;
#pragma unroll
                for (int ch = 0; ch < 32; ch++)
                    cpa16(sptr(&braw[tid*128 + ch*4]), bG + (size_t)c*128 + ch*4);
            } else if (tid < 128){
                cpa16(sptr(&a_s[(cur^1)*128 + (tid-96)*4]),
                      aG + (size_t)r_next*128 + (tid-96)*4);
            }
            cpa_commit();
        }

        // phase 2: tensor GEMM 96x128 @ 128x128
        float acc[3][4][4];
#pragma unroll
        for (int mt = 0; mt < 3; mt++)
#pragma unroll
            for (int nt = 0; nt < 4; nt++)
#pragma unroll
                for (int q = 0; q < 4; q++) acc[mt][nt][q] = 0.f;

#pragma unroll 4
        for (int k0 = 0; k0 < 128; k0 += 8){
            unsigned afr[3][4];
#pragma unroll
            for (int mt = 0; mt < 3; mt++){
                int rr = mr + mt*16 + gq;
                afr[mt][0] = __float_as_uint(M1[rr*132      + k0 + lq]);
                afr[mt][1] = __float_as_uint(M1[(rr+8)*132  + k0 + lq]);
                afr[mt][2] = __float_as_uint(M1[rr*132      + k0 + lq + 4]);
                afr[mt][3] = __float_as_uint(M1[(rr+8)*132  + k0 + lq + 4]);
            }
#pragma unroll
            for (int nt = 0; nt < 4; nt++){
                int n = nc0 + nt*8 + gq;
                unsigned b0 = __float_as_uint(W2[(k0 + lq)*136 + n]);
                unsigned b1 = __float_as_uint(W2[(k0 + lq + 4)*136 + n]);
#pragma unroll
                for (int mt = 0; mt < 3; mt++)
                    mma_tf32(acc[mt][nt], afr[mt], b0, b1);
            }
        }
        __syncthreads();   // M1 reads done before m2 overwrite

        // epilogue: m2 = silu(acc+be2) -> M1; coef partials
        float cf[3][2] = {{0.f,0.f},{0.f,0.f},{0.f,0.f}};
#pragma unroll
        for (int mt = 0; mt < 3; mt++){
            int rr = mr + mt*16 + gq;
#pragma unroll
            for (int nt = 0; nt < 4; nt++){
                int col = nc0 + nt*8 + lq*2;
                float wx0 = Wx_s[col], wx1 = Wx_s[col+1];
                float b0 = be2_s[col], b1 = be2_s[col+1];
                float v0 = silu_f(acc[mt][nt][0] + b0);
                float v1 = silu_f(acc[mt][nt][1] + b1);
                float v2 = silu_f(acc[mt][nt][2] + b0);
                float v3 = silu_f(acc[mt][nt][3] + b1);
                M1[rr*132 + col]       = v0;
                M1[rr*132 + col + 1]   = v1;
                M1[(rr+8)*132 + col]   = v2;
                M1[(rr+8)*132 + col+1] = v3;
                cf[mt][0] += v0*wx0 + v1*wx1;
                cf[mt][1] += v2*wx0 + v3*wx1;
            }
        }
#pragma unroll
        for (int mt = 0; mt < 3; mt++){
#pragma unroll
            for (int h = 0; h < 2; h++){
                float c = cf[mt][h];
                c += __shfl_xor_sync(0xffffffffu, c, 1);
                c += __shfl_xor_sync(0xffffffffu, c, 2);
                if (lq == 0) coefp[wc*96 + mr + mt*16 + h*8 + gq] = c;
            }
        }
        __syncthreads();

        if (tid < 96)
            coef_s[tid] = coefp[tid] + coefp[96+tid] + coefp[192+tid] + coefp[288+tid];
        {
            int col = tid & 127, grp = tid >> 7;
            float s = 0.f;
#pragma unroll 8
            for (int j = grp*48; j < grp*48 + 48; j++) s += M1[j*132 + col];
            aggp[grp*128 + col] = s;
        }
        __syncthreads();

        if (tid < 128)
            aggG[(size_t)r*128 + tid] = aggp[tid] + aggp[128 + tid];
        if (w < 3){
            const float* rl = rel_s + cur*384;
            float s = coef_s[lane]    * rl[lane*4 + w]
                    + coef_s[lane+32] * rl[(lane+32)*4 + w]
                    + coef_s[lane+64] * rl[(lane+64)*4 + w];
            s += __shfl_xor_sync(0xffffffffu, s, 16);
            s += __shfl_xor_sync(0xffffffffu, s, 8);
            s += __shfl_xor_sync(0xffffffffu, s, 4);
            s += __shfl_xor_sync(0xffffffffu, s, 2);
            s += __shfl_xor_sync(0xffffffffu, s, 1);
            if (lane == 0) Xout[r*3 + w] = Xin[r*3 + w] + s;
        }
        r = r_next; cur ^= 1;
    }
}

// ---------------- losses ----------------
__global__ void loss_partial(const float* __restrict__ H0, const float* __restrict__ H1,
                             const float* __restrict__ X0, const float* __restrict__ X1,
                             const int* __restrict__ shiftp,
                             const float* __restrict__ Xf)
{
    __shared__ float red[64];
    float s[5] = {0,0,0,0,0};
    int shift = *shiftp;
    for (int i = blockIdx.x*blockDim.x + threadIdx.x; i < NN; i += gridDim.x*blockDim.x){
        if (!g_mask[i]) continue;
        int j = (i + shift) % NN; if (j < 0) j += NN;
        float hp = 0.f, hn = 0.f;
        const float4* vp = (const float4*)(g_vH + (size_t)i*64);
        const float4* a1 = (const float4*)(H1 + (size_t)i*64);
        const float4* a0 = (const float4*)(H0 + (size_t)i*64);
        const float4* b1 = (const float4*)(H1 + (size_t)j*64);
        const float4* b0 = (const float4*)(H0 + (size_t)j*64);
#pragma unroll
        for (int k = 0; k < 16; k++){
            float4 p = vp[k], x1 = a1[k], x0 = a0[k], y1 = b1[k], y0 = b0[k];
            float d;
            d = p.x - (x1.x - x0.x); hp += d*d;
            d = p.y - (x1.y - x0.y); hp += d*d;
            d = p.z - (x1.z - x0.z); hp += d*d;
            d = p.w - (x1.w - x0.w); hp += d*d;
            d = p.x - (y1.x - y0.x); hn += d*d;
            d = p.y - (y1.y - y0.y); hn += d*d;
            d = p.z - (y1.z - y0.z); hn += d*d;
            d = p.w - (y1.w - y0.w); hn += d*d;
        }
        float xp = 0.f, xn = 0.f;
        for (int k = 0; k < 3; k++){
            float p = Xf[i*3 + k];
            float d  = p - (X1[i*3+k] - X0[i*3+k]); xp += d*d;
            float dn = p - (X1[j*3+k] - X0[j*3+k]); xn += dn*dn;
        }
        s[0] += hp; s[1] += xp; s[2] += hn; s[3] += xn; s[4] += 1.f;
    }
    for (int q = 0; q < 5; q++){
        red[threadIdx.x] = s[q]; __syncthreads();
        for (int d = 32; d > 0; d >>= 1){
            if (threadIdx.x < d) red[threadIdx.x] += red[threadIdx.x + d];
            __syncthreads();
        }
        if (threadIdx.x == 0) g_lpart[blockIdx.x*5 + q] = red[0];
        __syncthreads();
    }
}

__global__ void loss_final(float* __restrict__ out, int nb){
    if (threadIdx.x == 0){
        float s[5] = {0,0,0,0,0};
        for (int b = 0; b < nb; b++)
            for (int q = 0; q < 5; q++) s[q] += g_lpart[b*5 + q];
        float msum = s[4] + 1e-8f;
        float lHp = s[0]/msum, lXp = s[1]/msum, lHn = s[2]/msum, lXn = s[3]/msum;
        out[0] = lHp - 0.05f*lHn;
        out[1] = lXp - 0.05f*lXn;
        out[2] = lHp; out[3] = lXp; out[4] = lHn; out[5] = lXn;
    }
}

// ---------------- host launch ----------------
extern "C" void kernel_launch(void* const* d_in, const int* in_sizes, int n_in,
                              void* d_out, int out_size)
{
    (void)in_sizes; (void)n_in; (void)out_size;
    const float* H0    = (const float*)d_in[0];
    const float* X0    = (const float*)d_in[1];
    const float* H1    = (const float*)d_in[2];
    const float* X1    = (const float*)d_in[3];
    const float* cond  = (const float*)d_in[4];
    const float* tg    = (const float*)d_in[5];
    const float* Wi1   = (const float*)d_in[6];
    const float* bi1   = (const float*)d_in[7];
    const float* Wi2   = (const float*)d_in[8];
    const float* bi2   = (const float*)d_in[9];
    const float* Wi3   = (const float*)d_in[10];
    const float* bi3   = (const float*)d_in[11];
    const float* etab  = (const float*)d_in[12];
    const float* We1   = (const float*)d_in[13];
    const float* be1   = (const float*)d_in[14];
    const float* We2   = (const float*)d_in[15];
    const float* be2   = (const float*)d_in[16];
    const float* Wx    = (const float*)d_in[17];
    const float* Wh1   = (const float*)d_in[18];
    const float* bh1   = (const float*)d_in[19];
    const float* Wh2   = (const float*)d_in[20];
    const float* bh2   = (const float*)d_in[21];
    const float* Wout  = (const float*)d_in[22];
    const float* bout  = (const float*)d_in[23];
    const int*   edges = (const int*)d_in[24];
    const int*   chain = (const int*)d_in[25];
    const unsigned char* mask = (const unsigned char*)d_in[26];
    const int*   lengths = (const int*)d_in[27];
    const int*   shiftp  = (const int*)d_in[28];
    const int*   ecol = edges + EE;

    float *p_Hin, *p_h, *p_tmp, *p_a, *p_bn, *p_agg, *p_X, *p_vH, *p_tw;
    cudaGetSymbolAddress((void**)&p_Hin, g_Hin);
    cudaGetSymbolAddress((void**)&p_h,   g_h);
    cudaGetSymbolAddress((void**)&p_tmp, g_tmp);
    cudaGetSymbolAddress((void**)&p_a,   g_a);
    cudaGetSymbolAddress((void**)&p_bn,  g_bn);
    cudaGetSymbolAddress((void**)&p_agg, g_agg);
    cudaGetSymbolAddress((void**)&p_X,   g_X);
    cudaGetSymbolAddress((void**)&p_vH,  g_vH);
    cudaGetSymbolAddress((void**)&p_tw,  g_tw);

    int nsm = 148;
    cudaDeviceGetAttribute(&nsm, cudaDevAttrMultiProcessorCount, 0);
    if (nsm <= 0) nsm = 148;

    cudaFuncSetAttribute(edge_kernel,
                         cudaFuncAttributeMaxDynamicSharedMemorySize, SMEM_BYTES);

    setup_all<<<1, 256>>>(mask, lengths);
    node_prep<<<NN, 128>>>(H0, X0, H1, X1, cond, tg);
    prep_edge_all<<<3, 128>>>(We1, be1, etab);
    prep_w<<<128, 256>>>(Wi1, Wi2, Wi3, We1, Wh1, Wh2);

    // input MLP: 320 -> 128 (relu) -> 128 (relu) -> 128
    tgemm<<<96, 256>>>(p_Hin, 320, nullptr, 0, p_tw + OFF_I1, bi1, nullptr, p_h,   1);
    tgemm<<<96, 256>>>(p_h,   128, nullptr, 0, p_tw + OFF_I2, bi2, nullptr, p_tmp, 1);
    tgemm<<<96, 256>>>(p_tmp, 128, nullptr, 0, p_tw + OFF_I3, bi3, nullptr, p_h,   0);

    int cur = 0;
    for (int l = 0; l < 3; l++){
        tgemm_dual<<<dim3(96,2), 256>>>(p_h, p_tw + OFF_EA + l*16384,
                                        p_tw + OFF_EB + l*16384, p_a, p_bn);
        edge_kernel<<<nsm, 256, SMEM_BYTES>>>(p_a, p_bn,
                                             p_X + cur*NN*3, p_X + (1-cur)*NN*3,
                                             p_agg, ecol, chain,
                                             We2 + (size_t)l*128*128,
                                             be2 + l*128, Wx + l*128, l);
        cur = 1 - cur;
        tgemm<<<96, 256>>>(p_h,   128, p_agg, 128, p_tw + OFF_H1 + l*32768,
                           bh1 + l*128, nullptr, p_tmp, 2);
        tgemm<<<96, 256>>>(p_tmp, 128, nullptr, 0,  p_tw + OFF_H2 + l*16384,
                           bh2 + l*128, p_h, p_h, 0);
    }

    gemm16<64><<<128, 128>>>(p_h, 128, Wout, bout, p_vH);

    loss_partial<<<48, 64>>>(H0, H1, X0, X1, shiftp, p_X + cur*NN*3);
    loss_final<<<1, 32>>>((float*)d_out, 48);
}

// round 14
// speedup vs baseline: 3.9913x; 1.0168x over previous
#include <cuda_runtime.h>
#include <math.h>

#define NN 3072
#define BB 32
#define LL 96
#define EE (NN*LL)
#define HIDD 128
#define LATD 64

// ---------------- device scratch (no allocations allowed) ----------------
__device__ float g_Hin[NN*320];
__device__ float g_h[NN*HIDD];
__device__ float g_a[NN*HIDD];
__device__ float g_bn[NN*HIDD];
__device__ float g_agg[NN*HIDD];
__device__ float g_X[2][NN*3];
__device__ float g_vH[NN*LATD];
__device__ float g_wd2[3*HIDD];
__device__ float g_etab[3*2*HIDD];
__device__ int   g_off[BB+1];
__device__ int   g_mask[NN];
__device__ float g_lpart[64*5];

// tf32 pre-converted weights (offsets in floats)
#define OFF_I1 0
#define OFF_I2 40960
#define OFF_I3 57344
#define OFF_EA 73728
#define OFF_EB 122880
#define OFF_H1 172032
#define OFF_H2 270336
__device__ float g_tw[319488];

// silu via hardware tanh: silu(x) = 0.5x * (1 + tanh(0.5x))
__device__ __forceinline__ float silu_f(float v){
    float h = 0.5f * v;
    float t;
    asm("tanh.approx.f32 %0, %1;" : "=f"(t) : "f"(h));
    return h * (1.f + t);
}
__device__ __forceinline__ unsigned f2tf32(float f){
    unsigned r; asm("cvt.rna.tf32.f32 %0, %1;" : "=r"(r) : "f"(f)); return r;
}
__device__ __forceinline__ float f2tf32f(float f){
    return __uint_as_float(f2tf32(f));
}
__device__ __forceinline__ void mma_tf32(float (&d)[4], const unsigned (&a)[4],
                                         unsigned b0, unsigned b1){
    asm volatile("mma.sync.aligned.m16n8k8.row.col.f32.tf32.tf32.f32 "
        "{%0,%1,%2,%3}, {%4,%5,%6,%7}, {%8,%9}, {%0,%1,%2,%3};\n"
        : "+f"(d[0]), "+f"(d[1]), "+f"(d[2]), "+f"(d[3])
        : "r"(a[0]), "r"(a[1]), "r"(a[2]), "r"(a[3]), "r"(b0), "r"(b1));
}
__device__ __forceinline__ unsigned sptr(const void* p){
    return (unsigned)__cvta_generic_to_shared(p);
}
__device__ __forceinline__ void cpa16(unsigned dst, const void* src){
    asm volatile("cp.async.cg.shared.global [%0], [%1], 16;\n" :: "r"(dst), "l"(src));
}
__device__ __forceinline__ void cpa_commit(){
    asm volatile("cp.async.commit_group;\n" ::: "memory");
}
template<int N> __device__ __forceinline__ void cpa_wait(){
    asm volatile("cp.async.wait_group %0;\n" :: "n"(N) : "memory");
}

// ---------------- setup: mask dtype auto-detect + offsets ----------------
__global__ void setup_all(const unsigned char* __restrict__ m,
                          const int* __restrict__ lengths){
    __shared__ int s_big, s_odd;
    int tid = threadIdx.x;
    if (tid == 0){
        s_big = 0; s_odd = 0;
        int s = 0;
        for (int b = 0; b < BB; b++){ g_off[b] = s; s += lengths[b]; }
        g_off[BB] = s;
    }
    __syncthreads();
    int big = 0, odd = 0;
    for (int i = tid; i < NN; i += blockDim.x){
        unsigned char v = m[i];
        if (v > 1) big = 1;
        if ((i & 3) && v) odd = 1;
    }
    if (big) s_big = 1;
    if (odd) s_odd = 1;
    __syncthreads();
    if (s_big){
        const float* mf = (const float*)m;
        for (int i = tid; i < NN; i += blockDim.x) g_mask[i] = (mf[i] != 0.f) ? 1 : 0;
    } else if (s_odd){
        for (int i = tid; i < NN; i += blockDim.x) g_mask[i] = m[i] ? 1 : 0;
    } else {
        const int* mi = (const int*)m;
        for (int i = tid; i < NN; i += blockDim.x) g_mask[i] = mi[i] ? 1 : 0;
    }
}

__global__ void node_prep(const float* __restrict__ H0, const float* __restrict__ X0,
                          const float* __restrict__ H1, const float* __restrict__ X1,
                          const float* __restrict__ cond, const float* __restrict__ tg)
{
    int i = blockIdx.x;
    int k = threadIdx.x;
    __shared__ float t_sh; __shared__ int m_sh;
    if (k == 0){
        int b = 0;
        while (b + 1 < BB && g_off[b+1] <= i) b++;
        t_sh = tg[b];
        m_sh = g_mask[i];
    }
    __syncthreads();
    float t = t_sh; int m = m_sh;
    if (k < 64){
        float h0 = H0[i*64+k], h1 = H1[i*64+k];
        g_Hin[i*320 + k] = m ? (1.f - t)*h0 + t*h1 : h1;
        float f = expf(-logf(10000.f) * (float)k / 63.f);
        float ang = t * f;
        g_Hin[i*320 + 192 + k] = sinf(ang);
        g_Hin[i*320 + 256 + k] = cosf(ang);
    }
    g_Hin[i*320 + 64 + k] = cond[i*128 + k];
    if (k < 3){
        float x0 = X0[i*3+k], x1 = X1[i*3+k];
        g_X[0][i*3+k] = m ? (1.f - t)*x0 + t*x1 : x1;
    }
}

__global__ void prep_edge_all(const float* __restrict__ We1, const float* __restrict__ be1,
                              const float* __restrict__ etable)
{
    int l = blockIdx.x;
    int k = threadIdx.x;  // 128
    const float* W = We1 + (size_t)l*289*128;
    g_wd2[l*128 + k] = W[256*128 + k];
    for (int t = 0; t < 2; t++){
        float s = be1[l*128 + k];
        for (int e = 0; e < 32; e++) s += etable[t*32 + e] * W[(257 + e)*128 + k];
        g_etab[l*256 + t*128 + k] = s;
    }
}

__global__ void prep_w(const float* __restrict__ Wi1, const float* __restrict__ Wi2,
                       const float* __restrict__ Wi3, const float* __restrict__ We1,
                       const float* __restrict__ Wh1, const float* __restrict__ Wh2)
{
    int i0 = blockIdx.x*blockDim.x + threadIdx.x;
    int st = gridDim.x*blockDim.x;
    for (int i = i0; i < 40960; i += st) g_tw[OFF_I1+i] = f2tf32f(Wi1[i]);
    for (int i = i0; i < 16384; i += st) g_tw[OFF_I2+i] = f2tf32f(Wi2[i]);
    for (int i = i0; i < 16384; i += st) g_tw[OFF_I3+i] = f2tf32f(Wi3[i]);
    for (int i = i0; i < 49152; i += st){
        int l = i >> 14, r = i & 16383;
        g_tw[OFF_EA+i] = f2tf32f(We1[(size_t)l*36992 + r]);
        g_tw[OFF_EB+i] = f2tf32f(We1[(size_t)l*36992 + 16384 + r]);
    }
    for (int i = i0; i < 98304; i += st) g_tw[OFF_H1+i] = f2tf32f(Wh1[i]);
    for (int i = i0; i < 49152; i += st) g_tw[OFF_H2+i] = f2tf32f(Wh2[i]);
}

// ---------------- fused node-side tensor GEMM machinery --------------------
// Warp grid 2x4 over 32 rows x 128 cols; warp tile 16x32.
// smem floats: As[2][32*36]=2304, Ws[2][32*136]=8704, act[32*132]=4224
#define NS_AS  0
#define NS_WS  2304
#define NS_ACT 11008
#define NS_TOTF 15232
#define NS_BYTES (NS_TOTF*4)

// A staged from fp32 global (concat A1/A2); W from tf32 global (raw bits)
__device__ __forceinline__ void tg_stageA(
    const float* __restrict__ A1, int K1, const float* __restrict__ A2, int K2,
    const float* __restrict__ Wt, float* As, float* Ws,
    float (&acc)[4][4], int gr0)
{
    int tid = threadIdx.x;
    int w = tid >> 5, lane = tid & 31;
    int wr = w >> 2, wc = w & 3;
    int gq = lane >> 2, lq = lane & 3;
    int K = K1 + K2, ntiles = K >> 5;
    int srow = tid >> 3, skc = tid & 7;

#pragma unroll
    for (int nt = 0; nt < 4; nt++)
#pragma unroll
        for (int q = 0; q < 4; q++) acc[nt][q] = 0.f;

    {
        int k = skc*4;
        const float* src = (k < K1) ? A1 + (size_t)(gr0+srow)*K1 + k
                                    : A2 + (size_t)(gr0+srow)*K2 + (k - K1);
        cpa16(sptr(&As[srow*36 + skc*4]), src);
#pragma unroll
        for (int i = 0; i < 4; i++){
            int idx = tid + i*256;
            int kk = idx >> 5, c = idx & 31;
            cpa16(sptr(&Ws[kk*136 + c*4]), Wt + (size_t)kk*128 + c*4);
        }
        cpa_commit();
    }

    for (int t = 0; t < ntiles; t++){
        int b = t & 1;
        if (t + 1 < ntiles){
            int nb = b ^ 1;
            int k = (t+1)*32 + skc*4;
            const float* src = (k < K1) ? A1 + (size_t)(gr0+srow)*K1 + k
                                        : A2 + (size_t)(gr0+srow)*K2 + (k - K1);
            cpa16(sptr(&As[nb*1152 + srow*36 + skc*4]), src);
            const float* Wtt = Wt + (size_t)(t+1)*32*128;
#pragma unroll
            for (int i = 0; i < 4; i++){
                int idx = tid + i*256;
                int kk = idx >> 5, c = idx & 31;
                cpa16(sptr(&Ws[nb*4352 + kk*136 + c*4]), Wtt + (size_t)kk*128 + c*4);
            }
            cpa_commit();
            cpa_wait<1>();
        } else {
            cpa_wait<0>();
        }
        __syncthreads();
        const float* as = As + b*1152;
        const float* ws = Ws + b*4352;
        int rr = wr*16 + gq;
#pragma unroll
        for (int ks = 0; ks < 4; ks++){
            int k0 = ks*8;
            unsigned afr[4];
            afr[0] = f2tf32(as[rr*36     + k0 + lq]);
            afr[1] = f2tf32(as[(rr+8)*36 + k0 + lq]);
            afr[2] = f2tf32(as[rr*36     + k0 + lq + 4]);
            afr[3] = f2tf32(as[(rr+8)*36 + k0 + lq + 4]);
#pragma unroll
            for (int nt = 0; nt < 4; nt++){
                int n = wc*32 + nt*8 + gq;
                unsigned b0 = __float_as_uint(ws[(k0 + lq)*136 + n]);
                unsigned b1 = __float_as_uint(ws[(k0 + lq + 4)*136 + n]);
                mma_tf32(acc[nt], afr, b0, b1);
            }
        }
        __syncthreads();
    }
}

// A resident in act smem (tf32 bits, stride 132, 32 rows, K=128)
__device__ __forceinline__ void tg_actA(
    const float* act, const float* __restrict__ Wt, float* Ws, float (&acc)[4][4])
{
    int tid = threadIdx.x;
    int w = tid >> 5, lane = tid & 31;
    int wr = w >> 2, wc = w & 3;
    int gq = lane >> 2, lq = lane & 3;

#pragma unroll
    for (int nt = 0; nt < 4; nt++)
#pragma unroll
        for (int q = 0; q < 4; q++) acc[nt][q] = 0.f;

    {
#pragma unroll
        for (int i = 0; i < 4; i++){
            int idx = tid + i*256;
            int kk = idx >> 5, c = idx & 31;
            cpa16(sptr(&Ws[kk*136 + c*4]), Wt + (size_t)kk*128 + c*4);
        }
        cpa_commit();
    }
    for (int t = 0; t < 4; t++){
        int b = t & 1;
        if (t + 1 < 4){
            int nb = b ^ 1;
            const float* Wtt = Wt + (size_t)(t+1)*32*128;
#pragma unroll
            for (int i = 0; i < 4; i++){
                int idx = tid + i*256;
                int kk = idx >> 5, c = idx & 31;
                cpa16(sptr(&Ws[nb*4352 + kk*136 + c*4]), Wtt + (size_t)kk*128 + c*4);
            }
            cpa_commit();
            cpa_wait<1>();
        } else {
            cpa_wait<0>();
        }
        __syncthreads();
        const float* ws = Ws + b*4352;
        int rr = wr*16 + gq;
        int kb = t*32;
#pragma unroll
        for (int ks = 0; ks < 4; ks++){
            int k0 = ks*8;
            unsigned afr[4];
            afr[0] = __float_as_uint(act[rr*132     + kb + k0 + lq]);
            afr[1] = __float_as_uint(act[(rr+8)*132 + kb + k0 + lq]);
            afr[2] = __float_as_uint(act[rr*132     + kb + k0 + lq + 4]);
            afr[3] = __float_as_uint(act[(rr+8)*132 + kb + k0 + lq + 4]);
#pragma unroll
            for (int nt = 0; nt < 4; nt++){
                int n = wc*32 + nt*8 + gq;
                unsigned b0 = __float_as_uint(ws[(k0 + lq)*136 + n]);
                unsigned b1 = __float_as_uint(ws[(k0 + lq + 4)*136 + n]);
                mma_tf32(acc[nt], afr, b0, b1);
            }
        }
        __syncthreads();
    }
}

// epilogue: v = act_fn(acc + bias) (+resid); optional fp32 gout; optional act tf32
__device__ __forceinline__ void epi(
    float (&acc)[4][4], const float* __restrict__ bias, int mode,
    float* actbuf, float* __restrict__ gout, const float* __restrict__ resid, int gr0)
{
    int tid = threadIdx.x;
    int w = tid >> 5, lane = tid & 31;
    int wr = w >> 2, wc = w & 3;
    int gq = lane >> 2, lq = lane & 3;
    int rr = wr*16 + gq;
#pragma unroll
    for (int nt = 0; nt < 4; nt++){
        int col = wc*32 + nt*8 + lq*2;
        float b0 = 0.f, b1 = 0.f;
        if (bias){ b0 = bias[col]; b1 = bias[col+1]; }
        float v0 = acc[nt][0] + b0, v1 = acc[nt][1] + b1;
        float v2 = acc[nt][2] + b0, v3 = acc[nt][3] + b1;
        if (mode == 1){
            v0 = fmaxf(v0,0.f); v1 = fmaxf(v1,0.f);
            v2 = fmaxf(v2,0.f); v3 = fmaxf(v3,0.f);
        } else if (mode == 2){
            v0 = silu_f(v0); v1 = silu_f(v1);
            v2 = silu_f(v2); v3 = silu_f(v3);
        }
        if (resid){
            v0 += resid[(size_t)(gr0+rr)*128 + col];
            v1 += resid[(size_t)(gr0+rr)*128 + col + 1];
            v2 += resid[(size_t)(gr0+rr+8)*128 + col];
            v3 += resid[(size_t)(gr0+rr+8)*128 + col + 1];
        }
        if (gout){
            *(float2*)&gout[(size_t)(gr0+rr)*128 + col]   = make_float2(v0, v1);
            *(float2*)&gout[(size_t)(gr0+rr+8)*128 + col] = make_float2(v2, v3);
        }
        if (actbuf){
            actbuf[rr*132 + col]       = f2tf32f(v0);
            actbuf[rr*132 + col + 1]   = f2tf32f(v1);
            actbuf[(rr+8)*132 + col]   = f2tf32f(v2);
            actbuf[(rr+8)*132 + col+1] = f2tf32f(v3);
        }
    }
}

// input MLP (3 GEMMs) + layer-0 a/b duals (2 GEMMs), one launch
__global__ void __launch_bounds__(256, 1) mlp_dual(
    const float* __restrict__ bi1, const float* __restrict__ bi2,
    const float* __restrict__ bi3)
{
    extern __shared__ float sm[];
    float* As  = sm + NS_AS;
    float* Ws  = sm + NS_WS;
    float* act = sm + NS_ACT;
    int gr0 = blockIdx.x * 32;
    float acc[4][4];

    tg_stageA(g_Hin, 320, nullptr, 0, g_tw + OFF_I1, As, Ws, acc, gr0);
    epi(acc, bi1, 1, act, nullptr, nullptr, gr0);
    __syncthreads();
    tg_actA(act, g_tw + OFF_I2, Ws, acc);
    epi(acc, bi2, 1, act, nullptr, nullptr, gr0);
    __syncthreads();
    tg_actA(act, g_tw + OFF_I3, Ws, acc);
    epi(acc, bi3, 0, act, g_h, nullptr, gr0);
    __syncthreads();
    tg_actA(act, g_tw + OFF_EA, Ws, acc);
    epi(acc, nullptr, 0, nullptr, g_a, nullptr, gr0);
    tg_actA(act, g_tw + OFF_EB, Ws, acc);
    epi(acc, nullptr, 0, nullptr, g_bn, nullptr, gr0);
}

// h-update (2 GEMMs) + optional next-layer a/b duals (2 GEMMs)
__global__ void __launch_bounds__(256, 1) hup_kernel(
    const float* __restrict__ bh1, const float* __restrict__ bh2,
    int l, int with_dual)
{
    extern __shared__ float sm[];
    float* As  = sm + NS_AS;
    float* Ws  = sm + NS_WS;
    float* act = sm + NS_ACT;
    int gr0 = blockIdx.x * 32;
    float acc[4][4];

    tg_stageA(g_h, 128, g_agg, 128, g_tw + OFF_H1 + l*32768, As, Ws, acc, gr0);
    epi(acc, bh1, 2, act, nullptr, nullptr, gr0);
    __syncthreads();
    tg_actA(act, g_tw + OFF_H2 + l*16384, Ws, acc);
    epi(acc, bh2, 0, act, g_h, g_h, gr0);
    __syncthreads();
    if (with_dual){
        tg_actA(act, g_tw + OFF_EA + (l+1)*16384, Ws, acc);
        epi(acc, nullptr, 0, nullptr, g_a, nullptr, gr0);
        tg_actA(act, g_tw + OFF_EB + (l+1)*16384, Ws, acc);
        epi(acc, nullptr, 0, nullptr, g_bn, nullptr, gr0);
    }
}

// ---------------- fp32 node GEMM for NOUT=64 (Wout, output precision) -----
template<int NOUT>
__global__ void __launch_bounds__(128, 4) gemm16(
    const float* __restrict__ A1, int K1,
    const float* __restrict__ W,
    const float* __restrict__ bias,
    float* __restrict__ out)
{
    constexpr int ROWS = 24;
    constexpr int NC4  = NOUT / 4;
    constexpr int TR   = 128 / NC4;
    constexpr int R    = ROWS / TR;
    __shared__ float As[2][ROWS*32];
    __shared__ float Ws[2][32*NOUT];

    int tid = threadIdx.x;
    int tx = tid % NC4, ty = tid / NC4;
    int c0 = tx*4, r0 = ty*R;
    int gr0 = blockIdx.x * ROWS;
    int K = K1;
    int ntiles = K >> 5;

    float acc[R][4];
#pragma unroll
    for (int i = 0; i < R; i++)
#pragma unroll
        for (int j = 0; j < 4; j++) acc[i][j] = 0.f;

    {
        for (int i = tid; i < ROWS*8; i += 128){
            int row = i >> 3, kc = i & 7;
            cpa16(sptr(&As[0][row*32 + kc*4]), A1 + (size_t)(gr0+row)*K + kc*4);
        }
        for (int i = tid; i < 8*NOUT; i += 128)
            cpa16(sptr(&Ws[0][i*4]), W + (size_t)i*4);
        cpa_commit();
    }

    for (int t = 0; t < ntiles; t++){
        int b = t & 1;
        if (t + 1 < ntiles){
            int nb = b ^ 1;
            for (int i = tid; i < ROWS*8; i += 128){
                int row = i >> 3, kc = i & 7;
                cpa16(sptr(&As[nb][row*32 + kc*4]),
                      A1 + (size_t)(gr0+row)*K + (t+1)*32 + kc*4);
            }
            const float* Wt = W + (size_t)(t+1)*32*NOUT;
            for (int i = tid; i < 8*NOUT; i += 128)
                cpa16(sptr(&Ws[nb][i*4]), Wt + (size_t)i*4);
            cpa_commit();
            cpa_wait<1>();
        } else {
            cpa_wait<0>();
        }
        __syncthreads();
        const float* as = As[b];
        const float* ws = Ws[b];
#pragma unroll
        for (int kk = 0; kk < 32; kk++){
            float4 w = *(const float4*)&ws[kk*NOUT + c0];
            float a[R];
#pragma unroll
            for (int i = 0; i < R; i++) a[i] = as[(r0+i)*32 + kk];
#pragma unroll
            for (int i = 0; i < R; i++){
                acc[i][0] += a[i]*w.x; acc[i][1] += a[i]*w.y;
                acc[i][2] += a[i]*w.z; acc[i][3] += a[i]*w.w;
            }
        }
        __syncthreads();
    }

    float4 bv = make_float4(0.f,0.f,0.f,0.f);
    if (bias) bv = *(const float4*)&bias[c0];
#pragma unroll
    for (int i = 0; i < R; i++){
        int g = gr0 + r0 + i;
        float4 v;
        v.x = acc[i][0] + bv.x; v.y = acc[i][1] + bv.y;
        v.z = acc[i][2] + bv.z; v.w = acc[i][3] + bv.w;
        *(float4*)&out[(size_t)g*NOUT + c0] = v;
    }
}

// ---------------- persistent fused edge kernel (gather double-buffered) ---
#define S_M1    0                     // 96*132 = 12672
#define S_W2    12672                 // 128*136 = 17408
#define S_BRAW  30080                 // 96*128 = 12288 (single buffer)
#define S_A     42368                 // 2*128
#define S_WD2   42624                 // 128
#define S_ETAB  42752                 // 256
#define S_BE2   43008                 // 128
#define S_WX    43136                 // 128
#define S_REL   43264                 // 2*96*4 = 768
#define S_COEF  44032                 // 96
#define S_COEFP 44128                 // 384
#define S_AGGP  44512                 // 256
#define S_ET    44768                 // 2*96 ints
#define S_TOTF  44960
#define SMEM_BYTES (S_TOTF*4)

__global__ void __launch_bounds__(256, 1) edge_kernel(
    const float* __restrict__ aG, const float* __restrict__ bG,
    const float* __restrict__ Xin, float* __restrict__ Xout,
    float* __restrict__ aggG,
    const int* __restrict__ ecol, const int* __restrict__ chain,
    const float* __restrict__ W2g, const float* __restrict__ be2g,
    const float* __restrict__ Wxg, int layer)
{
    extern __shared__ float sm[];
    float* M1     = sm + S_M1;    // stride 132
    float* W2     = sm + S_W2;    // stride 136
    float* braw   = sm + S_BRAW;  // 96 x 128
    float* a_s    = sm + S_A;     // [2][128]
    float* wd2_s  = sm + S_WD2;
    float* etab_s = sm + S_ETAB;
    float* be2_s  = sm + S_BE2;
    float* Wx_s   = sm + S_WX;
    float* rel_s  = sm + S_REL;   // [2][96*4]
    float* coef_s = sm + S_COEF;
    float* coefp  = sm + S_COEFP;
    float* aggp   = sm + S_AGGP;
    int*   et_s   = (int*)(sm + S_ET);  // [2][96]

    int tid = threadIdx.x;

    for (int i = tid; i < 128*32; i += 256){
        int row = i >> 5, cg = (i & 31);
        float4 v = ((const float4*)W2g)[row*32 + cg];
        float4 p;
        p.x = f2tf32f(v.x);
        p.y = f2tf32f(v.y);
        p.z = f2tf32f(v.z);
        p.w = f2tf32f(v.w);
        *(float4*)&W2[row*136 + cg*4] = p;
    }
    if (tid < 128){
        wd2_s[tid]     = g_wd2[layer*128 + tid];
        etab_s[tid]    = g_etab[layer*256 + tid];
        etab_s[128+tid]= g_etab[layer*256 + 128 + tid];
        be2_s[tid]     = be2g[tid];
        Wx_s[tid]      = Wxg[tid];
    }

    int w  = tid >> 5, lane = tid & 31;
    int wr = w >> 2, wc = w & 3;
    int mr = wr * 48, nc0 = wc * 32;
    int gq = lane >> 2, lq = lane & 3;

    int cur = 0;
    int r = blockIdx.x;

    if (r < NN){
        if (tid < 96){
            int c = ecol[r*96 + tid];
            float dx = Xin[r*3]   - Xin[c*3];
            float dy = Xin[r*3+1] - Xin[c*3+1];
            float dz = Xin[r*3+2] - Xin[c*3+2];
            rel_s[tid*4]   = dx;
            rel_s[tid*4+1] = dy;
            rel_s[tid*4+2] = dz;
            rel_s[tid*4+3] = dx*dx + dy*dy + dz*dz;
            et_s[tid] = (chain[c] != chain[r]) ? 1 : 0;
#pragma unroll
            for (int ch = 0; ch < 32; ch++)
                cpa16(sptr(&braw[tid*128 + ch*4]), bG + (size_t)c*128 + ch*4);
        } else if (tid < 128){
            cpa16(sptr(&a_s[(tid-96)*4]), aG + (size_t)r*128 + (tid-96)*4);
        }
        cpa_commit();
    }

    while (r < NN){
        int r_next = r + gridDim.x;
        cpa_wait<0>();
        __syncthreads();

        // phase 1
        {
            const float* aa = a_s + cur*128;
            const float* rl = rel_s + cur*384;
            const int*   et = et_s + cur*96;
            for (int idx = tid; idx < 96*32; idx += 256){
                int j = idx >> 5, k = (idx & 31) * 4;
                float4 bn = *(const float4*)&braw[j*128 + k];
                float d2 = rl[j*4+3];
                const float* etb = etab_s + et[j]*128;
                float4 p;
                p.x = silu_f(aa[k+0] + bn.x + d2*wd2_s[k+0] + etb[k+0]);
                p.y = silu_f(aa[k+1] + bn.y + d2*wd2_s[k+1] + etb[k+1]);
                p.z = silu_f(aa[k+2] + bn.z + d2*wd2_s[k+2] + etb[k+2]);
                p.w = silu_f(aa[k+3] + bn.w + d2*wd2_s[k+3] + etb[k+3]);
                p.x = f2tf32f(p.x);
                p.y = f2tf32f(p.y);
                p.z = f2tf32f(p.z);
                p.w = f2tf32f(p.w);
                *(float4*)&M1[j*132 + k] = p;
            }
        }
        __syncthreads();

        if (r_next < NN){
            int nxt = cur ^ 1;
            if (tid < 96){
                int c = ecol[r_next*96 + tid];
                float dx = Xin[r_next*3]   - Xin[c*3];
                float dy = Xin[r_next*3+1] - Xin[c*3+1];
                float dz = Xin[r_next*3+2] - Xin[c*3+2];
                rel_s[nxt*384 + tid*4]   = dx;
                rel_s[nxt*384 + tid*4+1] = dy;
                rel_s[nxt*384 + tid*4+2] = dz;
                rel_s[nxt*384 + tid*4+3] = dx*dx + dy*dy + dz*dz;
                et_s[nxt*96 + tid] = (chain[c] != chain[r_next]) ? 1 : 0;
#pragma unroll
                for (int ch = 0; ch < 32; ch++)
                    cpa16(sptr(&braw[tid*128 + ch*4]), bG + (size_t)c*128 + ch*4);
            } else if (tid < 128){
                cpa16(sptr(&a_s[(cur^1)*128 + (tid-96)*4]),
                      aG + (size_t)r_next*128 + (tid-96)*4);
            }
            cpa_commit();
        }

        // phase 2: tensor GEMM
        float acc[3][4][4];
#pragma unroll
        for (int mt = 0; mt < 3; mt++)
#pragma unroll
            for (int nt = 0; nt < 4; nt++)
#pragma unroll
                for (int q = 0; q < 4; q++) acc[mt][nt][q] = 0.f;

#pragma unroll 4
        for (int k0 = 0; k0 < 128; k0 += 8){
            unsigned afr[3][4];
#pragma unroll
            for (int mt = 0; mt < 3; mt++){
                int rr = mr + mt*16 + gq;
                afr[mt][0] = __float_as_uint(M1[rr*132      + k0 + lq]);
                afr[mt][1] = __float_as_uint(M1[(rr+8)*132  + k0 + lq]);
                afr[mt][2] = __float_as_uint(M1[rr*132      + k0 + lq + 4]);
                afr[mt][3] = __float_as_uint(M1[(rr+8)*132  + k0 + lq + 4]);
            }
#pragma unroll
            for (int nt = 0; nt < 4; nt++){
                int n = nc0 + nt*8 + gq;
                unsigned b0 = __float_as_uint(W2[(k0 + lq)*136 + n]);
                unsigned b1 = __float_as_uint(W2[(k0 + lq + 4)*136 + n]);
#pragma unroll
                for (int mt = 0; mt < 3; mt++)
                    mma_tf32(acc[mt][nt], afr[mt], b0, b1);
            }
        }
        __syncthreads();

        float cf[3][2] = {{0.f,0.f},{0.f,0.f},{0.f,0.f}};
#pragma unroll
        for (int mt = 0; mt < 3; mt++){
            int rr = mr + mt*16 + gq;
#pragma unroll
            for (int nt = 0; nt < 4; nt++){
                int col = nc0 + nt*8 + lq*2;
                float wx0 = Wx_s[col], wx1 = Wx_s[col+1];
                float b0 = be2_s[col], b1 = be2_s[col+1];
                float v0 = silu_f(acc[mt][nt][0] + b0);
                float v1 = silu_f(acc[mt][nt][1] + b1);
                float v2 = silu_f(acc[mt][nt][2] + b0);
                float v3 = silu_f(acc[mt][nt][3] + b1);
                M1[rr*132 + col]       = v0;
                M1[rr*132 + col + 1]   = v1;
                M1[(rr+8)*132 + col]   = v2;
                M1[(rr+8)*132 + col+1] = v3;
                cf[mt][0] += v0*wx0 + v1*wx1;
                cf[mt][1] += v2*wx0 + v3*wx1;
            }
        }
#pragma unroll
        for (int mt = 0; mt < 3; mt++){
#pragma unroll
            for (int h = 0; h < 2; h++){
                float c = cf[mt][h];
                c += __shfl_xor_sync(0xffffffffu, c, 1);
                c += __shfl_xor_sync(0xffffffffu, c, 2);
                if (lq == 0) coefp[wc*96 + mr + mt*16 + h*8 + gq] = c;
            }
        }
        __syncthreads();

        if (tid < 96)
            coef_s[tid] = coefp[tid] + coefp[96+tid] + coefp[192+tid] + coefp[288+tid];
        {
            int col = tid & 127, grp = tid >> 7;
            float s = 0.f;
#pragma unroll 8
            for (int j = grp*48; j < grp*48 + 48; j++) s += M1[j*132 + col];
            aggp[grp*128 + col] = s;
        }
        __syncthreads();

        if (tid < 128)
            aggG[(size_t)r*128 + tid] = aggp[tid] + aggp[128 + tid];
        if (w < 3){
            const float* rl = rel_s + cur*384;
            float s = coef_s[lane]    * rl[lane*4 + w]
                    + coef_s[lane+32] * rl[(lane+32)*4 + w]
                    + coef_s[lane+64] * rl[(lane+64)*4 + w];
            s += __shfl_xor_sync(0xffffffffu, s, 16);
            s += __shfl_xor_sync(0xffffffffu, s, 8);
            s += __shfl_xor_sync(0xffffffffu, s, 4);
            s += __shfl_xor_sync(0xffffffffu, s, 2);
            s += __shfl_xor_sync(0xffffffffu, s, 1);
            if (lane == 0) Xout[r*3 + w] = Xin[r*3 + w] + s;
        }
        r = r_next; cur ^= 1;
    }
}

// ---------------- losses ----------------
__global__ void loss_partial(const float* __restrict__ H0, const float* __restrict__ H1,
                             const float* __restrict__ X0, const float* __restrict__ X1,
                             const int* __restrict__ shiftp,
                             const float* __restrict__ Xf)
{
    __shared__ float red[64];
    float s[5] = {0,0,0,0,0};
    int shift = *shiftp;
    for (int i = blockIdx.x*blockDim.x + threadIdx.x; i < NN; i += gridDim.x*blockDim.x){
        if (!g_mask[i]) continue;
        int j = (i + shift) % NN; if (j < 0) j += NN;
        float hp = 0.f, hn = 0.f;
        const float4* vp = (const float4*)(g_vH + (size_t)i*64);
        const float4* a1 = (const float4*)(H1 + (size_t)i*64);
        const float4* a0 = (const float4*)(H0 + (size_t)i*64);
        const float4* b1 = (const float4*)(H1 + (size_t)j*64);
        const float4* b0 = (const float4*)(H0 + (size_t)j*64);
#pragma unroll
        for (int k = 0; k < 16; k++){
            float4 p = vp[k], x1 = a1[k], x0 = a0[k], y1 = b1[k], y0 = b0[k];
            float d;
            d = p.x - (x1.x - x0.x); hp += d*d;
            d = p.y - (x1.y - x0.y); hp += d*d;
            d = p.z - (x1.z - x0.z); hp += d*d;
            d = p.w - (x1.w - x0.w); hp += d*d;
            d = p.x - (y1.x - y0.x); hn += d*d;
            d = p.y - (y1.y - y0.y); hn += d*d;
            d = p.z - (y1.z - y0.z); hn += d*d;
            d = p.w - (y1.w - y0.w); hn += d*d;
        }
        float xp = 0.f, xn = 0.f;
        for (int k = 0; k < 3; k++){
            float p = Xf[i*3 + k];
            float d  = p - (X1[i*3+k] - X0[i*3+k]); xp += d*d;
            float dn = p - (X1[j*3+k] - X0[j*3+k]); xn += dn*dn;
        }
        s[0] += hp; s[1] += xp; s[2] += hn; s[3] += xn; s[4] += 1.f;
    }
    for (int q = 0; q < 5; q++){
        red[threadIdx.x] = s[q]; __syncthreads();
        for (int d = 32; d > 0; d >>= 1){
            if (threadIdx.x < d) red[threadIdx.x] += red[threadIdx.x + d];
            __syncthreads();
        }
        if (threadIdx.x == 0) g_lpart[blockIdx.x*5 + q] = red[0];
        __syncthreads();
    }
}

__global__ void loss_final(float* __restrict__ out, int nb){
    if (threadIdx.x == 0){
        float s[5] = {0,0,0,0,0};
        for (int b = 0; b < nb; b++)
            for (int q = 0; q < 5; q++) s[q] += g_lpart[b*5 + q];
        float msum = s[4] + 1e-8f;
        float lHp = s[0]/msum, lXp = s[1]/msum, lHn = s[2]/msum, lXn = s[3]/msum;
        out[0] = lHp - 0.05f*lHn;
        out[1] = lXp - 0.05f*lXn;
        out[2] = lHp; out[3] = lXp; out[4] = lHn; out[5] = lXn;
    }
}

// ---------------- host launch ----------------
extern "C" void kernel_launch(void* const* d_in, const int* in_sizes, int n_in,
                              void* d_out, int out_size)
{
    (void)in_sizes; (void)n_in; (void)out_size;
    const float* H0    = (const float*)d_in[0];
    const float* X0    = (const float*)d_in[1];
    const float* H1    = (const float*)d_in[2];
    const float* X1    = (const float*)d_in[3];
    const float* cond  = (const float*)d_in[4];
    const float* tg    = (const float*)d_in[5];
    const float* Wi1   = (const float*)d_in[6];
    const float* bi1   = (const float*)d_in[7];
    const float* Wi2   = (const float*)d_in[8];
    const float* bi2   = (const float*)d_in[9];
    const float* Wi3   = (const float*)d_in[10];
    const float* bi3   = (const float*)d_in[11];
    const float* etab  = (const float*)d_in[12];
    const float* We1   = (const float*)d_in[13];
    const float* be1   = (const float*)d_in[14];
    const float* We2   = (const float*)d_in[15];
    const float* be2   = (const float*)d_in[16];
    const float* Wx    = (const float*)d_in[17];
    const float* Wh1   = (const float*)d_in[18];
    const float* bh1   = (const float*)d_in[19];
    const float* Wh2   = (const float*)d_in[20];
    const float* bh2   = (const float*)d_in[21];
    const float* Wout  = (const float*)d_in[22];
    const float* bout  = (const float*)d_in[23];
    const int*   edges = (const int*)d_in[24];
    const int*   chain = (const int*)d_in[25];
    const unsigned char* mask = (const unsigned char*)d_in[26];
    const int*   lengths = (const int*)d_in[27];
    const int*   shiftp  = (const int*)d_in[28];
    const int*   ecol = edges + EE;

    float *p_h, *p_a, *p_bn, *p_agg, *p_X, *p_vH;
    cudaGetSymbolAddress((void**)&p_h,   g_h);
    cudaGetSymbolAddress((void**)&p_a,   g_a);
    cudaGetSymbolAddress((void**)&p_bn,  g_bn);
    cudaGetSymbolAddress((void**)&p_agg, g_agg);
    cudaGetSymbolAddress((void**)&p_X,   g_X);
    cudaGetSymbolAddress((void**)&p_vH,  g_vH);

    int nsm = 148;
    cudaDeviceGetAttribute(&nsm, cudaDevAttrMultiProcessorCount, 0);
    if (nsm <= 0) nsm = 148;

    cudaFuncSetAttribute(edge_kernel,
                         cudaFuncAttributeMaxDynamicSharedMemorySize, SMEM_BYTES);
    cudaFuncSetAttribute(mlp_dual,
                         cudaFuncAttributeMaxDynamicSharedMemorySize, NS_BYTES);
    cudaFuncSetAttribute(hup_kernel,
                         cudaFuncAttributeMaxDynamicSharedMemorySize, NS_BYTES);

    setup_all<<<1, 256>>>(mask, lengths);
    node_prep<<<NN, 128>>>(H0, X0, H1, X1, cond, tg);
    prep_edge_all<<<3, 128>>>(We1, be1, etab);
    prep_w<<<128, 256>>>(Wi1, Wi2, Wi3, We1, Wh1, Wh2);

    mlp_dual<<<96, 256, NS_BYTES>>>(bi1, bi2, bi3);

    int cur = 0;
    for (int l = 0; l < 3; l++){
        edge_kernel<<<nsm, 256, SMEM_BYTES>>>(p_a, p_bn,
                                             p_X + cur*NN*3, p_X + (1-cur)*NN*3,
                                             p_agg, ecol, chain,
                                             We2 + (size_t)l*128*128,
                                             be2 + l*128, Wx + l*128, l);
        cur = 1 - cur;
        hup_kernel<<<96, 256, NS_BYTES>>>(bh1 + l*128, bh2 + l*128, l, l < 2);
    }

    gemm16<64><<<128, 128>>>(p_h, 128, Wout, bout, p_vH);

    loss_partial<<<48, 64>>>(H0, H1, X0, X1, shiftp, p_X + cur*NN*3);
    loss_final<<<1, 32>>>((float*)d_out, 48);
}

// round 15
// speedup vs baseline: 4.2848x; 1.0735x over previous
#include <cuda_runtime.h>
#include <math.h>

#define NN 3072
#define BB 32
#define LL 96
#define EE (NN*LL)
#define HIDD 128
#define LATD 64

// ---------------- device scratch (no allocations allowed) ----------------
__device__ float g_Hin[NN*320];
__device__ float g_h[NN*HIDD];
__device__ float g_a[NN*HIDD];
__device__ float g_bn[NN*HIDD];
__device__ float g_agg[NN*HIDD];
__device__ float g_X[2][NN*3];
__device__ float g_vH[NN*LATD];
__device__ float g_wd2[3*HIDD];
__device__ float g_etab[3*2*HIDD];
__device__ int   g_off[BB+1];
__device__ int   g_mask[NN];
__device__ float g_lpart[64*5];

// tf32 pre-converted weights (offsets in floats)
#define OFF_I1 0
#define OFF_I2 40960
#define OFF_I3 57344
#define OFF_EA 73728
#define OFF_EB 122880
#define OFF_H1 172032
#define OFF_H2 270336
__device__ float g_tw[319488];

// silu via hardware tanh: silu(x) = 0.5x * (1 + tanh(0.5x))
__device__ __forceinline__ float silu_f(float v){
    float h = 0.5f * v;
    float t;
    asm("tanh.approx.f32 %0, %1;" : "=f"(t) : "f"(h));
    return h * (1.f + t);
}
__device__ __forceinline__ unsigned f2tf32(float f){
    unsigned r; asm("cvt.rna.tf32.f32 %0, %1;" : "=r"(r) : "f"(f)); return r;
}
__device__ __forceinline__ float f2tf32f(float f){
    return __uint_as_float(f2tf32(f));
}
__device__ __forceinline__ void mma_tf32(float (&d)[4], const unsigned (&a)[4],
                                         unsigned b0, unsigned b1){
    asm volatile("mma.sync.aligned.m16n8k8.row.col.f32.tf32.tf32.f32 "
        "{%0,%1,%2,%3}, {%4,%5,%6,%7}, {%8,%9}, {%0,%1,%2,%3};\n"
        : "+f"(d[0]), "+f"(d[1]), "+f"(d[2]), "+f"(d[3])
        : "r"(a[0]), "r"(a[1]), "r"(a[2]), "r"(a[3]), "r"(b0), "r"(b1));
}
__device__ __forceinline__ unsigned sptr(const void* p){
    return (unsigned)__cvta_generic_to_shared(p);
}
__device__ __forceinline__ void cpa16(unsigned dst, const void* src){
    asm volatile("cp.async.cg.shared.global [%0], [%1], 16;\n" :: "r"(dst), "l"(src));
}
__device__ __forceinline__ void cpa_commit(){
    asm volatile("cp.async.commit_group;\n" ::: "memory");
}
template<int N> __device__ __forceinline__ void cpa_wait(){
    asm volatile("cp.async.wait_group %0;\n" :: "n"(N) : "memory");
}

// ---------------- setup: mask dtype auto-detect + offsets ----------------
__global__ void setup_all(const unsigned char* __restrict__ m,
                          const int* __restrict__ lengths){
    __shared__ int s_big, s_odd;
    int tid = threadIdx.x;
    if (tid == 0){
        s_big = 0; s_odd = 0;
        int s = 0;
        for (int b = 0; b < BB; b++){ g_off[b] = s; s += lengths[b]; }
        g_off[BB] = s;
    }
    __syncthreads();
    int big = 0, odd = 0;
    for (int i = tid; i < NN; i += blockDim.x){
        unsigned char v = m[i];
        if (v > 1) big = 1;
        if ((i & 3) && v) odd = 1;
    }
    if (big) s_big = 1;
    if (odd) s_odd = 1;
    __syncthreads();
    if (s_big){
        const float* mf = (const float*)m;
        for (int i = tid; i < NN; i += blockDim.x) g_mask[i] = (mf[i] != 0.f) ? 1 : 0;
    } else if (s_odd){
        for (int i = tid; i < NN; i += blockDim.x) g_mask[i] = m[i] ? 1 : 0;
    } else {
        const int* mi = (const int*)m;
        for (int i = tid; i < NN; i += blockDim.x) g_mask[i] = mi[i] ? 1 : 0;
    }
}

__global__ void node_prep(const float* __restrict__ H0, const float* __restrict__ X0,
                          const float* __restrict__ H1, const float* __restrict__ X1,
                          const float* __restrict__ cond, const float* __restrict__ tg)
{
    int i = blockIdx.x;
    int k = threadIdx.x;
    __shared__ float t_sh; __shared__ int m_sh;
    if (k == 0){
        int b = 0;
        while (b + 1 < BB && g_off[b+1] <= i) b++;
        t_sh = tg[b];
        m_sh = g_mask[i];
    }
    __syncthreads();
    float t = t_sh; int m = m_sh;
    if (k < 64){
        float h0 = H0[i*64+k], h1 = H1[i*64+k];
        g_Hin[i*320 + k] = m ? (1.f - t)*h0 + t*h1 : h1;
        float f = expf(-logf(10000.f) * (float)k / 63.f);
        float ang = t * f;
        g_Hin[i*320 + 192 + k] = sinf(ang);
        g_Hin[i*320 + 256 + k] = cosf(ang);
    }
    g_Hin[i*320 + 64 + k] = cond[i*128 + k];
    if (k < 3){
        float x0 = X0[i*3+k], x1 = X1[i*3+k];
        g_X[0][i*3+k] = m ? (1.f - t)*x0 + t*x1 : x1;
    }
}

__global__ void prep_edge_all(const float* __restrict__ We1, const float* __restrict__ be1,
                              const float* __restrict__ etable)
{
    int l = blockIdx.x;
    int k = threadIdx.x;  // 128
    const float* W = We1 + (size_t)l*289*128;
    g_wd2[l*128 + k] = W[256*128 + k];
    for (int t = 0; t < 2; t++){
        float s = be1[l*128 + k];
        for (int e = 0; e < 32; e++) s += etable[t*32 + e] * W[(257 + e)*128 + k];
        g_etab[l*256 + t*128 + k] = s;
    }
}

__global__ void prep_w(const float* __restrict__ Wi1, const float* __restrict__ Wi2,
                       const float* __restrict__ Wi3, const float* __restrict__ We1,
                       const float* __restrict__ Wh1, const float* __restrict__ Wh2)
{
    int i0 = blockIdx.x*blockDim.x + threadIdx.x;
    int st = gridDim.x*blockDim.x;
    for (int i = i0; i < 40960; i += st) g_tw[OFF_I1+i] = f2tf32f(Wi1[i]);
    for (int i = i0; i < 16384; i += st) g_tw[OFF_I2+i] = f2tf32f(Wi2[i]);
    for (int i = i0; i < 16384; i += st) g_tw[OFF_I3+i] = f2tf32f(Wi3[i]);
    for (int i = i0; i < 49152; i += st){
        int l = i >> 14, r = i & 16383;
        g_tw[OFF_EA+i] = f2tf32f(We1[(size_t)l*36992 + r]);
        g_tw[OFF_EB+i] = f2tf32f(We1[(size_t)l*36992 + 16384 + r]);
    }
    for (int i = i0; i < 98304; i += st) g_tw[OFF_H1+i] = f2tf32f(Wh1[i]);
    for (int i = i0; i < 49152; i += st) g_tw[OFF_H2+i] = f2tf32f(Wh2[i]);
}

// ---------------- fused node-side tensor GEMM machinery --------------------
#define NS_AS  0
#define NS_WS  2304
#define NS_ACT 11008
#define NS_TOTF 15232
#define NS_BYTES (NS_TOTF*4)

__device__ __forceinline__ void tg_stageA(
    const float* __restrict__ A1, int K1, const float* __restrict__ A2, int K2,
    const float* __restrict__ Wt, float* As, float* Ws,
    float (&acc)[4][4], int gr0)
{
    int tid = threadIdx.x;
    int w = tid >> 5, lane = tid & 31;
    int wr = w >> 2, wc = w & 3;
    int gq = lane >> 2, lq = lane & 3;
    int K = K1 + K2, ntiles = K >> 5;
    int srow = tid >> 3, skc = tid & 7;

#pragma unroll
    for (int nt = 0; nt < 4; nt++)
#pragma unroll
        for (int q = 0; q < 4; q++) acc[nt][q] = 0.f;

    {
        int k = skc*4;
        const float* src = (k < K1) ? A1 + (size_t)(gr0+srow)*K1 + k
                                    : A2 + (size_t)(gr0+srow)*K2 + (k - K1);
        cpa16(sptr(&As[srow*36 + skc*4]), src);
#pragma unroll
        for (int i = 0; i < 4; i++){
            int idx = tid + i*256;
            int kk = idx >> 5, c = idx & 31;
            cpa16(sptr(&Ws[kk*136 + c*4]), Wt + (size_t)kk*128 + c*4);
        }
        cpa_commit();
    }

    for (int t = 0; t < ntiles; t++){
        int b = t & 1;
        if (t + 1 < ntiles){
            int nb = b ^ 1;
            int k = (t+1)*32 + skc*4;
            const float* src = (k < K1) ? A1 + (size_t)(gr0+srow)*K1 + k
                                        : A2 + (size_t)(gr0+srow)*K2 + (k - K1);
            cpa16(sptr(&As[nb*1152 + srow*36 + skc*4]), src);
            const float* Wtt = Wt + (size_t)(t+1)*32*128;
#pragma unroll
            for (int i = 0; i < 4; i++){
                int idx = tid + i*256;
                int kk = idx >> 5, c = idx & 31;
                cpa16(sptr(&Ws[nb*4352 + kk*136 + c*4]), Wtt + (size_t)kk*128 + c*4);
            }
            cpa_commit();
            cpa_wait<1>();
        } else {
            cpa_wait<0>();
        }
        __syncthreads();
        const float* as = As + b*1152;
        const float* ws = Ws + b*4352;
        int rr = wr*16 + gq;
#pragma unroll
        for (int ks = 0; ks < 4; ks++){
            int k0 = ks*8;
            unsigned afr[4];
            afr[0] = f2tf32(as[rr*36     + k0 + lq]);
            afr[1] = f2tf32(as[(rr+8)*36 + k0 + lq]);
            afr[2] = f2tf32(as[rr*36     + k0 + lq + 4]);
            afr[3] = f2tf32(as[(rr+8)*36 + k0 + lq + 4]);
#pragma unroll
            for (int nt = 0; nt < 4; nt++){
                int n = wc*32 + nt*8 + gq;
                unsigned b0 = __float_as_uint(ws[(k0 + lq)*136 + n]);
                unsigned b1 = __float_as_uint(ws[(k0 + lq + 4)*136 + n]);
                mma_tf32(acc[nt], afr, b0, b1);
            }
        }
        __syncthreads();
    }
}

__device__ __forceinline__ void tg_actA(
    const float* act, const float* __restrict__ Wt, float* Ws, float (&acc)[4][4])
{
    int tid = threadIdx.x;
    int w = tid >> 5, lane = tid & 31;
    int wr = w >> 2, wc = w & 3;
    int gq = lane >> 2, lq = lane & 3;

#pragma unroll
    for (int nt = 0; nt < 4; nt++)
#pragma unroll
        for (int q = 0; q < 4; q++) acc[nt][q] = 0.f;

    {
#pragma unroll
        for (int i = 0; i < 4; i++){
            int idx = tid + i*256;
            int kk = idx >> 5, c = idx & 31;
            cpa16(sptr(&Ws[kk*136 + c*4]), Wt + (size_t)kk*128 + c*4);
        }
        cpa_commit();
    }
    for (int t = 0; t < 4; t++){
        int b = t & 1;
        if (t + 1 < 4){
            int nb = b ^ 1;
            const float* Wtt = Wt + (size_t)(t+1)*32*128;
#pragma unroll
            for (int i = 0; i < 4; i++){
                int idx = tid + i*256;
                int kk = idx >> 5, c = idx & 31;
                cpa16(sptr(&Ws[nb*4352 + kk*136 + c*4]), Wtt + (size_t)kk*128 + c*4);
            }
            cpa_commit();
            cpa_wait<1>();
        } else {
            cpa_wait<0>();
        }
        __syncthreads();
        const float* ws = Ws + b*4352;
        int rr = wr*16 + gq;
        int kb = t*32;
#pragma unroll
        for (int ks = 0; ks < 4; ks++){
            int k0 = ks*8;
            unsigned afr[4];
            afr[0] = __float_as_uint(act[rr*132     + kb + k0 + lq]);
            afr[1] = __float_as_uint(act[(rr+8)*132 + kb + k0 + lq]);
            afr[2] = __float_as_uint(act[rr*132     + kb + k0 + lq + 4]);
            afr[3] = __float_as_uint(act[(rr+8)*132 + kb + k0 + lq + 4]);
#pragma unroll
            for (int nt = 0; nt < 4; nt++){
                int n = wc*32 + nt*8 + gq;
                unsigned b0 = __float_as_uint(ws[(k0 + lq)*136 + n]);
                unsigned b1 = __float_as_uint(ws[(k0 + lq + 4)*136 + n]);
                mma_tf32(acc[nt], afr, b0, b1);
            }
        }
        __syncthreads();
    }
}

__device__ __forceinline__ void epi(
    float (&acc)[4][4], const float* __restrict__ bias, int mode,
    float* actbuf, float* __restrict__ gout, const float* __restrict__ resid, int gr0)
{
    int tid = threadIdx.x;
    int w = tid >> 5, lane = tid & 31;
    int wr = w >> 2, wc = w & 3;
    int gq = lane >> 2, lq = lane & 3;
    int rr = wr*16 + gq;
#pragma unroll
    for (int nt = 0; nt < 4; nt++){
        int col = wc*32 + nt*8 + lq*2;
        float b0 = 0.f, b1 = 0.f;
        if (bias){ b0 = bias[col]; b1 = bias[col+1]; }
        float v0 = acc[nt][0] + b0, v1 = acc[nt][1] + b1;
        float v2 = acc[nt][2] + b0, v3 = acc[nt][3] + b1;
        if (mode == 1){
            v0 = fmaxf(v0,0.f); v1 = fmaxf(v1,0.f);
            v2 = fmaxf(v2,0.f); v3 = fmaxf(v3,0.f);
        } else if (mode == 2){
            v0 = silu_f(v0); v1 = silu_f(v1);
            v2 = silu_f(v2); v3 = silu_f(v3);
        }
        if (resid){
            v0 += resid[(size_t)(gr0+rr)*128 + col];
            v1 += resid[(size_t)(gr0+rr)*128 + col + 1];
            v2 += resid[(size_t)(gr0+rr+8)*128 + col];
            v3 += resid[(size_t)(gr0+rr+8)*128 + col + 1];
        }
        if (gout){
            *(float2*)&gout[(size_t)(gr0+rr)*128 + col]   = make_float2(v0, v1);
            *(float2*)&gout[(size_t)(gr0+rr+8)*128 + col] = make_float2(v2, v3);
        }
        if (actbuf){
            actbuf[rr*132 + col]       = f2tf32f(v0);
            actbuf[rr*132 + col + 1]   = f2tf32f(v1);
            actbuf[(rr+8)*132 + col]   = f2tf32f(v2);
            actbuf[(rr+8)*132 + col+1] = f2tf32f(v3);
        }
    }
}

__global__ void __launch_bounds__(256, 1) mlp_dual(
    const float* __restrict__ bi1, const float* __restrict__ bi2,
    const float* __restrict__ bi3)
{
    extern __shared__ float sm[];
    float* As  = sm + NS_AS;
    float* Ws  = sm + NS_WS;
    float* act = sm + NS_ACT;
    int gr0 = blockIdx.x * 32;
    float acc[4][4];

    tg_stageA(g_Hin, 320, nullptr, 0, g_tw + OFF_I1, As, Ws, acc, gr0);
    epi(acc, bi1, 1, act, nullptr, nullptr, gr0);
    __syncthreads();
    tg_actA(act, g_tw + OFF_I2, Ws, acc);
    epi(acc, bi2, 1, act, nullptr, nullptr, gr0);
    __syncthreads();
    tg_actA(act, g_tw + OFF_I3, Ws, acc);
    epi(acc, bi3, 0, act, g_h, nullptr, gr0);
    __syncthreads();
    tg_actA(act, g_tw + OFF_EA, Ws, acc);
    epi(acc, nullptr, 0, nullptr, g_a, nullptr, gr0);
    tg_actA(act, g_tw + OFF_EB, Ws, acc);
    epi(acc, nullptr, 0, nullptr, g_bn, nullptr, gr0);
}

__global__ void __launch_bounds__(256, 1) hup_kernel(
    const float* __restrict__ bh1, const float* __restrict__ bh2,
    int l, int with_dual)
{
    extern __shared__ float sm[];
    float* As  = sm + NS_AS;
    float* Ws  = sm + NS_WS;
    float* act = sm + NS_ACT;
    int gr0 = blockIdx.x * 32;
    float acc[4][4];

    tg_stageA(g_h, 128, g_agg, 128, g_tw + OFF_H1 + l*32768, As, Ws, acc, gr0);
    epi(acc, bh1, 2, act, nullptr, nullptr, gr0);
    __syncthreads();
    tg_actA(act, g_tw + OFF_H2 + l*16384, Ws, acc);
    epi(acc, bh2, 0, act, g_h, g_h, gr0);
    __syncthreads();
    if (with_dual){
        tg_actA(act, g_tw + OFF_EA + (l+1)*16384, Ws, acc);
        epi(acc, nullptr, 0, nullptr, g_a, nullptr, gr0);
        tg_actA(act, g_tw + OFF_EB + (l+1)*16384, Ws, acc);
        epi(acc, nullptr, 0, nullptr, g_bn, nullptr, gr0);
    }
}

// ---------------- fp32 node GEMM for NOUT=64 (Wout, output precision) -----
template<int NOUT>
__global__ void __launch_bounds__(128, 4) gemm16(
    const float* __restrict__ A1, int K1,
    const float* __restrict__ W,
    const float* __restrict__ bias,
    float* __restrict__ out)
{
    constexpr int ROWS = 24;
    constexpr int NC4  = NOUT / 4;
    constexpr int TR   = 128 / NC4;
    constexpr int R    = ROWS / TR;
    __shared__ float As[2][ROWS*32];
    __shared__ float Ws[2][32*NOUT];

    int tid = threadIdx.x;
    int tx = tid % NC4, ty = tid / NC4;
    int c0 = tx*4, r0 = ty*R;
    int gr0 = blockIdx.x * ROWS;
    int K = K1;
    int ntiles = K >> 5;

    float acc[R][4];
#pragma unroll
    for (int i = 0; i < R; i++)
#pragma unroll
        for (int j = 0; j < 4; j++) acc[i][j] = 0.f;

    {
        for (int i = tid; i < ROWS*8; i += 128){
            int row = i >> 3, kc = i & 7;
            cpa16(sptr(&As[0][row*32 + kc*4]), A1 + (size_t)(gr0+row)*K + kc*4);
        }
        for (int i = tid; i < 8*NOUT; i += 128)
            cpa16(sptr(&Ws[0][i*4]), W + (size_t)i*4);
        cpa_commit();
    }

    for (int t = 0; t < ntiles; t++){
        int b = t & 1;
        if (t + 1 < ntiles){
            int nb = b ^ 1;
            for (int i = tid; i < ROWS*8; i += 128){
                int row = i >> 3, kc = i & 7;
                cpa16(sptr(&As[nb][row*32 + kc*4]),
                      A1 + (size_t)(gr0+row)*K + (t+1)*32 + kc*4);
            }
            const float* Wt = W + (size_t)(t+1)*32*NOUT;
            for (int i = tid; i < 8*NOUT; i += 128)
                cpa16(sptr(&Ws[nb][i*4]), Wt + (size_t)i*4);
            cpa_commit();
            cpa_wait<1>();
        } else {
            cpa_wait<0>();
        }
        __syncthreads();
        const float* as = As[b];
        const float* ws = Ws[b];
#pragma unroll
        for (int kk = 0; kk < 32; kk++){
            float4 w = *(const float4*)&ws[kk*NOUT + c0];
            float a[R];
#pragma unroll
            for (int i = 0; i < R; i++) a[i] = as[(r0+i)*32 + kk];
#pragma unroll
            for (int i = 0; i < R; i++){
                acc[i][0] += a[i]*w.x; acc[i][1] += a[i]*w.y;
                acc[i][2] += a[i]*w.z; acc[i][3] += a[i]*w.w;
            }
        }
        __syncthreads();
    }

    float4 bv = make_float4(0.f,0.f,0.f,0.f);
    if (bias) bv = *(const float4*)&bias[c0];
#pragma unroll
    for (int i = 0; i < R; i++){
        int g = gr0 + r0 + i;
        float4 v;
        v.x = acc[i][0] + bv.x; v.y = acc[i][1] + bv.y;
        v.z = acc[i][2] + bv.z; v.w = acc[i][3] + bv.w;
        *(float4*)&out[(size_t)g*NOUT + c0] = v;
    }
}

// ---------------- persistent fused edge kernel ----------------------------
// gather double-buffered; epilogue agg in registers (no m2 smem round-trip,
// no post-GEMM barrier -> MUFU epilogue overlaps sibling warps' MMA)
#define S_M1    0                     // 96*132 = 12672
#define S_W2    12672                 // 128*136 = 17408
#define S_BRAW  30080                 // 96*128 = 12288 (single buffer)
#define S_A     42368                 // 2*128
#define S_WD2   42624                 // 128
#define S_ETAB  42752                 // 256
#define S_BE2   43008                 // 128
#define S_WX    43136                 // 128
#define S_REL   43264                 // 2*96*4 = 768
#define S_COEF  44032                 // 96
#define S_COEFP 44128                 // 384
#define S_AGGP  44512                 // 256
#define S_ET    44768                 // 2*96 ints
#define S_TOTF  44960
#define SMEM_BYTES (S_TOTF*4)

__global__ void __launch_bounds__(256, 1) edge_kernel(
    const float* __restrict__ aG, const float* __restrict__ bG,
    const float* __restrict__ Xin, float* __restrict__ Xout,
    float* __restrict__ aggG,
    const int* __restrict__ ecol, const int* __restrict__ chain,
    const float* __restrict__ W2g, const float* __restrict__ be2g,
    const float* __restrict__ Wxg, int layer)
{
    extern __shared__ float sm[];
    float* M1     = sm + S_M1;    // stride 132
    float* W2     = sm + S_W2;    // stride 136
    float* braw   = sm + S_BRAW;  // 96 x 128
    float* a_s    = sm + S_A;     // [2][128]
    float* wd2_s  = sm + S_WD2;
    float* etab_s = sm + S_ETAB;
    float* be2_s  = sm + S_BE2;
    float* Wx_s   = sm + S_WX;
    float* rel_s  = sm + S_REL;   // [2][96*4]
    float* coef_s = sm + S_COEF;
    float* coefp  = sm + S_COEFP;
    float* aggp   = sm + S_AGGP;  // [2][128]
    int*   et_s   = (int*)(sm + S_ET);  // [2][96]

    int tid = threadIdx.x;

    for (int i = tid; i < 128*32; i += 256){
        int row = i >> 5, cg = (i & 31);
        float4 v = ((const float4*)W2g)[row*32 + cg];
        float4 p;
        p.x = f2tf32f(v.x);
        p.y = f2tf32f(v.y);
        p.z = f2tf32f(v.z);
        p.w = f2tf32f(v.w);
        *(float4*)&W2[row*136 + cg*4] = p;
    }
    if (tid < 128){
        wd2_s[tid]     = g_wd2[layer*128 + tid];
        etab_s[tid]    = g_etab[layer*256 + tid];
        etab_s[128+tid]= g_etab[layer*256 + 128 + tid];
        be2_s[tid]     = be2g[tid];
        Wx_s[tid]      = Wxg[tid];
    }

    int w  = tid >> 5, lane = tid & 31;
    int wr = w >> 2, wc = w & 3;
    int mr = wr * 48, nc0 = wc * 32;
    int gq = lane >> 2, lq = lane & 3;

    int cur = 0;
    int r = blockIdx.x;

    if (r < NN){
        if (tid < 96){
            int c = ecol[r*96 + tid];
            float dx = Xin[r*3]   - Xin[c*3];
            float dy = Xin[r*3+1] - Xin[c*3+1];
            float dz = Xin[r*3+2] - Xin[c*3+2];
            rel_s[tid*4]   = dx;
            rel_s[tid*4+1] = dy;
            rel_s[tid*4+2] = dz;
            rel_s[tid*4+3] = dx*dx + dy*dy + dz*dz;
            et_s[tid] = (chain[c] != chain[r]) ? 1 : 0;
#pragma unroll
            for (int ch = 0; ch < 32; ch++)
                cpa16(sptr(&braw[tid*128 + ch*4]), bG + (size_t)c*128 + ch*4);
        } else if (tid < 128){
            cpa16(sptr(&a_s[(tid-96)*4]), aG + (size_t)r*128 + (tid-96)*4);
        }
        cpa_commit();
    }

    while (r < NN){
        int r_next = r + gridDim.x;
        cpa_wait<0>();
        __syncthreads();

        // phase 1: m1 = silu(a + b + d2*wd2 + etab) -> tf32 M1
        {
            const float* aa = a_s + cur*128;
            const float* rl = rel_s + cur*384;
            const int*   et = et_s + cur*96;
            for (int idx = tid; idx < 96*32; idx += 256){
                int j = idx >> 5, k = (idx & 31) * 4;
                float4 bn = *(const float4*)&braw[j*128 + k];
                float d2 = rl[j*4+3];
                const float* etb = etab_s + et[j]*128;
                float4 p;
                p.x = silu_f(aa[k+0] + bn.x + d2*wd2_s[k+0] + etb[k+0]);
                p.y = silu_f(aa[k+1] + bn.y + d2*wd2_s[k+1] + etb[k+1]);
                p.z = silu_f(aa[k+2] + bn.z + d2*wd2_s[k+2] + etb[k+2]);
                p.w = silu_f(aa[k+3] + bn.w + d2*wd2_s[k+3] + etb[k+3]);
                p.x = f2tf32f(p.x);
                p.y = f2tf32f(p.y);
                p.z = f2tf32f(p.z);
                p.w = f2tf32f(p.w);
                *(float4*)&M1[j*132 + k] = p;
            }
        }
        __syncthreads();   // braw consumed; M1 ready

        // prefetch next node (lands during GEMM)
        if (r_next < NN){
            int nxt = cur ^ 1;
            if (tid < 96){
                int c = ecol[r_next*96 + tid];
                float dx = Xin[r_next*3]   - Xin[c*3];
                float dy = Xin[r_next*3+1] - Xin[c*3+1];
                float dz = Xin[r_next*3+2] - Xin[c*3+2];
                rel_s[nxt*384 + tid*4]   = dx;
                rel_s[nxt*384 + tid*4+1] = dy;
                rel_s[nxt*384 + tid*4+2] = dz;
                rel_s[nxt*384 + tid*4+3] = dx*dx + dy*dy + dz*dz;
                et_s[nxt*96 + tid] = (chain[c] != chain[r_next]) ? 1 : 0;
#pragma unroll
                for (int ch = 0; ch < 32; ch++)
                    cpa16(sptr(&braw[tid*128 + ch*4]), bG + (size_t)c*128 + ch*4);
            } else if (tid < 128){
                cpa16(sptr(&a_s[(cur^1)*128 + (tid-96)*4]),
                      aG + (size_t)r_next*128 + (tid-96)*4);
            }
            cpa_commit();
        }

        // phase 2: tensor GEMM 96x128 @ 128x128
        float acc[3][4][4];
#pragma unroll
        for (int mt = 0; mt < 3; mt++)
#pragma unroll
            for (int nt = 0; nt < 4; nt++)
#pragma unroll
                for (int q = 0; q < 4; q++) acc[mt][nt][q] = 0.f;

#pragma unroll 4
        for (int k0 = 0; k0 < 128; k0 += 8){
            unsigned afr[3][4];
#pragma unroll
            for (int mt = 0; mt < 3; mt++){
                int rr = mr + mt*16 + gq;
                afr[mt][0] = __float_as_uint(M1[rr*132      + k0 + lq]);
                afr[mt][1] = __float_as_uint(M1[(rr+8)*132  + k0 + lq]);
                afr[mt][2] = __float_as_uint(M1[rr*132      + k0 + lq + 4]);
                afr[mt][3] = __float_as_uint(M1[(rr+8)*132  + k0 + lq + 4]);
            }
#pragma unroll
            for (int nt = 0; nt < 4; nt++){
                int n = nc0 + nt*8 + gq;
                unsigned b0 = __float_as_uint(W2[(k0 + lq)*136 + n]);
                unsigned b1 = __float_as_uint(W2[(k0 + lq + 4)*136 + n]);
#pragma unroll
                for (int mt = 0; mt < 3; mt++)
                    mma_tf32(acc[mt][nt], afr[mt], b0, b1);
            }
        }
        // NO barrier here: epilogue reads only registers, writes only coefp/aggp.
        // M1/W2 are next touched after the loop-head __syncthreads.

        // epilogue: silu + coef partials + agg register reduction
        float cf[3][2] = {{0.f,0.f},{0.f,0.f},{0.f,0.f}};
        float sa[4][2];
#pragma unroll
        for (int nt = 0; nt < 4; nt++){ sa[nt][0] = 0.f; sa[nt][1] = 0.f; }
#pragma unroll
        for (int mt = 0; mt < 3; mt++){
#pragma unroll
            for (int nt = 0; nt < 4; nt++){
                int col = nc0 + nt*8 + lq*2;
                float wx0 = Wx_s[col], wx1 = Wx_s[col+1];
                float b0 = be2_s[col], b1 = be2_s[col+1];
                float v0 = silu_f(acc[mt][nt][0] + b0);
                float v1 = silu_f(acc[mt][nt][1] + b1);
                float v2 = silu_f(acc[mt][nt][2] + b0);
                float v3 = silu_f(acc[mt][nt][3] + b1);
                cf[mt][0] += v0*wx0 + v1*wx1;
                cf[mt][1] += v2*wx0 + v3*wx1;
                sa[nt][0] += v0 + v2;
                sa[nt][1] += v1 + v3;
            }
        }
        // agg: reduce over gq lanes (rows within this warp's 48-row band)
#pragma unroll
        for (int nt = 0; nt < 4; nt++){
#pragma unroll
            for (int p = 0; p < 2; p++){
                float s = sa[nt][p];
                s += __shfl_xor_sync(0xffffffffu, s, 4);
                s += __shfl_xor_sync(0xffffffffu, s, 8);
                s += __shfl_xor_sync(0xffffffffu, s, 16);
                sa[nt][p] = s;
            }
        }
        if (gq == 0){
#pragma unroll
            for (int nt = 0; nt < 4; nt++){
                int col = nc0 + nt*8 + lq*2;
                aggp[wr*128 + col]     = sa[nt][0];
                aggp[wr*128 + col + 1] = sa[nt][1];
            }
        }
        // coef partials (reduce over lq lanes)
#pragma unroll
        for (int mt = 0; mt < 3; mt++){
#pragma unroll
            for (int h = 0; h < 2; h++){
                float c = cf[mt][h];
                c += __shfl_xor_sync(0xffffffffu, c, 1);
                c += __shfl_xor_sync(0xffffffffu, c, 2);
                if (lq == 0) coefp[wc*96 + mr + mt*16 + h*8 + gq] = c;
            }
        }
        __syncthreads();

        if (tid < 96)
            coef_s[tid] = coefp[tid] + coefp[96+tid] + coefp[192+tid] + coefp[288+tid];
        if (tid < 128)
            aggG[(size_t)r*128 + tid] = aggp[tid] + aggp[128 + tid];
        __syncthreads();

        if (w < 3){
            const float* rl = rel_s + cur*384;
            float s = coef_s[lane]    * rl[lane*4 + w]
                    + coef_s[lane+32] * rl[(lane+32)*4 + w]
                    + coef_s[lane+64] * rl[(lane+64)*4 + w];
            s += __shfl_xor_sync(0xffffffffu, s, 16);
            s += __shfl_xor_sync(0xffffffffu, s, 8);
            s += __shfl_xor_sync(0xffffffffu, s, 4);
            s += __shfl_xor_sync(0xffffffffu, s, 2);
            s += __shfl_xor_sync(0xffffffffu, s, 1);
            if (lane == 0) Xout[r*3 + w] = Xin[r*3 + w] + s;
        }
        r = r_next; cur ^= 1;
    }
}

// ---------------- losses ----------------
__global__ void loss_partial(const float* __restrict__ H0, const float* __restrict__ H1,
                             const float* __restrict__ X0, const float* __restrict__ X1,
                             const int* __restrict__ shiftp,
                             const float* __restrict__ Xf)
{
    __shared__ float red[64];
    float s[5] = {0,0,0,0,0};
    int shift = *shiftp;
    for (int i = blockIdx.x*blockDim.x + threadIdx.x; i < NN; i += gridDim.x*blockDim.x){
        if (!g_mask[i]) continue;
        int j = (i + shift) % NN; if (j < 0) j += NN;
        float hp = 0.f, hn = 0.f;
        const float4* vp = (const float4*)(g_vH + (size_t)i*64);
        const float4* a1 = (const float4*)(H1 + (size_t)i*64);
        const float4* a0 = (const float4*)(H0 + (size_t)i*64);
        const float4* b1 = (const float4*)(H1 + (size_t)j*64);
        const float4* b0 = (const float4*)(H0 + (size_t)j*64);
#pragma unroll
        for (int k = 0; k < 16; k++){
            float4 p = vp[k], x1 = a1[k], x0 = a0[k], y1 = b1[k], y0 = b0[k];
            float d;
            d = p.x - (x1.x - x0.x); hp += d*d;
            d = p.y - (x1.y - x0.y); hp += d*d;
            d = p.z - (x1.z - x0.z); hp += d*d;
            d = p.w - (x1.w - x0.w); hp += d*d;
            d = p.x - (y1.x - y0.x); hn += d*d;
            d = p.y - (y1.y - y0.y); hn += d*d;
            d = p.z - (y1.z - y0.z); hn += d*d;
            d = p.w - (y1.w - y0.w); hn += d*d;
        }
        float xp = 0.f, xn = 0.f;
        for (int k = 0; k < 3; k++){
            float p = Xf[i*3 + k];
            float d  = p - (X1[i*3+k] - X0[i*3+k]); xp += d*d;
            float dn = p - (X1[j*3+k] - X0[j*3+k]); xn += dn*dn;
        }
        s[0] += hp; s[1] += xp; s[2] += hn; s[3] += xn; s[4] += 1.f;
    }
    for (int q = 0; q < 5; q++){
        red[threadIdx.x] = s[q]; __syncthreads();
        for (int d = 32; d > 0; d >>= 1){
            if (threadIdx.x < d) red[threadIdx.x] += red[threadIdx.x + d];
            __syncthreads();
        }
        if (threadIdx.x == 0) g_lpart[blockIdx.x*5 + q] = red[0];
        __syncthreads();
    }
}

__global__ void loss_final(float* __restrict__ out, int nb){
    if (threadIdx.x == 0){
        float s[5] = {0,0,0,0,0};
        for (int b = 0; b < nb; b++)
            for (int q = 0; q < 5; q++) s[q] += g_lpart[b*5 + q];
        float msum = s[4] + 1e-8f;
        float lHp = s[0]/msum, lXp = s[1]/msum, lHn = s[2]/msum, lXn = s[3]/msum;
        out[0] = lHp - 0.05f*lHn;
        out[1] = lXp - 0.05f*lXn;
        out[2] = lHp; out[3] = lXp; out[4] = lHn; out[5] = lXn;
    }
}

// ---------------- host launch ----------------
extern "C" void kernel_launch(void* const* d_in, const int* in_sizes, int n_in,
                              void* d_out, int out_size)
{
    (void)in_sizes; (void)n_in; (void)out_size;
    const float* H0    = (const float*)d_in[0];
    const float* X0    = (const float*)d_in[1];
    const float* H1    = (const float*)d_in[2];
    const float* X1    = (const float*)d_in[3];
    const float* cond  = (const float*)d_in[4];
    const float* tg    = (const float*)d_in[5];
    const float* Wi1   = (const float*)d_in[6];
    const float* bi1   = (const float*)d_in[7];
    const float* Wi2   = (const float*)d_in[8];
    const float* bi2   = (const float*)d_in[9];
    const float* Wi3   = (const float*)d_in[10];
    const float* bi3   = (const float*)d_in[11];
    const float* etab  = (const float*)d_in[12];
    const float* We1   = (const float*)d_in[13];
    const float* be1   = (const float*)d_in[14];
    const float* We2   = (const float*)d_in[15];
    const float* be2   = (const float*)d_in[16];
    const float* Wx    = (const float*)d_in[17];
    const float* Wh1   = (const float*)d_in[18];
    const float* bh1   = (const float*)d_in[19];
    const float* Wh2   = (const float*)d_in[20];
    const float* bh2   = (const float*)d_in[21];
    const float* Wout  = (const float*)d_in[22];
    const float* bout  = (const float*)d_in[23];
    const int*   edges = (const int*)d_in[24];
    const int*   chain = (const int*)d_in[25];
    const unsigned char* mask = (const unsigned char*)d_in[26];
    const int*   lengths = (const int*)d_in[27];
    const int*   shiftp  = (const int*)d_in[28];
    const int*   ecol = edges + EE;

    float *p_h, *p_a, *p_bn, *p_agg, *p_X, *p_vH;
    cudaGetSymbolAddress((void**)&p_h,   g_h);
    cudaGetSymbolAddress((void**)&p_a,   g_a);
    cudaGetSymbolAddress((void**)&p_bn,  g_bn);
    cudaGetSymbolAddress((void**)&p_agg, g_agg);
    cudaGetSymbolAddress((void**)&p_X,   g_X);
    cudaGetSymbolAddress((void**)&p_vH,  g_vH);

    int nsm = 148;
    cudaDeviceGetAttribute(&nsm, cudaDevAttrMultiProcessorCount, 0);
    if (nsm <= 0) nsm = 148;

    cudaFuncSetAttribute(edge_kernel,
                         cudaFuncAttributeMaxDynamicSharedMemorySize, SMEM_BYTES);
    cudaFuncSetAttribute(mlp_dual,
                         cudaFuncAttributeMaxDynamicSharedMemorySize, NS_BYTES);
    cudaFuncSetAttribute(hup_kernel,
                         cudaFuncAttributeMaxDynamicSharedMemorySize, NS_BYTES);

    setup_all<<<1, 256>>>(mask, lengths);
    node_prep<<<NN, 128>>>(H0, X0, H1, X1, cond, tg);
    prep_edge_all<<<3, 128>>>(We1, be1, etab);
    prep_w<<<128, 256>>>(Wi1, Wi2, Wi3, We1, Wh1, Wh2);

    mlp_dual<<<96, 256, NS_BYTES>>>(bi1, bi2, bi3);

    int cur = 0;
    for (int l = 0; l < 3; l++){
        edge_kernel<<<nsm, 256, SMEM_BYTES>>>(p_a, p_bn,
                                             p_X + cur*NN*3, p_X + (1-cur)*NN*3,
                                             p_agg, ecol, chain,
                                             We2 + (size_t)l*128*128,
                                             be2 + l*128, Wx + l*128, l);
        cur = 1 - cur;
        hup_kernel<<<96, 256, NS_BYTES>>>(bh1 + l*128, bh2 + l*128, l, l < 2);
    }

    gemm16<64><<<128, 128>>>(p_h, 128, Wout, bout, p_vH);

    loss_partial<<<48, 64>>>(H0, H1, X0, X1, shiftp, p_X + cur*NN*3);
    loss_final<<<1, 32>>>((float*)d_out, 48);
}

// round 17
// speedup vs baseline: 4.2948x; 1.0024x over previous
#include <cuda_runtime.h>
#include <math.h>

#define NN 3072
#define BB 32
#define LL 96
#define EE (NN*LL)
#define HIDD 128
#define LATD 64

// ---------------- device scratch (no allocations allowed) ----------------
__device__ float g_Hin[NN*320];
__device__ float g_h[NN*HIDD];
__device__ float g_a[NN*HIDD];
__device__ float g_bn[NN*HIDD];
__device__ float g_agg[NN*HIDD];
__device__ float g_X[2][NN*3];
__device__ float g_vH[NN*LATD];
__device__ float g_wd2[3*HIDD];
__device__ float g_etab[3*2*HIDD];
__device__ int   g_off[BB+1];
__device__ int   g_mask[NN];
__device__ float g_lpart[64*5];

// tf32 pre-converted weights (offsets in floats)
#define OFF_I1 0
#define OFF_I2 40960
#define OFF_I3 57344
#define OFF_EA 73728
#define OFF_EB 122880
#define OFF_H1 172032
#define OFF_H2 270336
__device__ float g_tw[319488];

// silu via hardware tanh: silu(x) = 0.5x * (1 + tanh(0.5x))
__device__ __forceinline__ float silu_f(float v){
    float h = 0.5f * v;
    float t;
    asm("tanh.approx.f32 %0, %1;" : "=f"(t) : "f"(h));
    return h * (1.f + t);
}
__device__ __forceinline__ unsigned f2tf32(float f){
    unsigned r; asm("cvt.rna.tf32.f32 %0, %1;" : "=r"(r) : "f"(f)); return r;
}
__device__ __forceinline__ float f2tf32f(float f){
    return __uint_as_float(f2tf32(f));
}
__device__ __forceinline__ void mma_tf32(float (&d)[4], const unsigned (&a)[4],
                                         unsigned b0, unsigned b1){
    asm volatile("mma.sync.aligned.m16n8k8.row.col.f32.tf32.tf32.f32 "
        "{%0,%1,%2,%3}, {%4,%5,%6,%7}, {%8,%9}, {%0,%1,%2,%3};\n"
        : "+f"(d[0]), "+f"(d[1]), "+f"(d[2]), "+f"(d[3])
        : "r"(a[0]), "r"(a[1]), "r"(a[2]), "r"(a[3]), "r"(b0), "r"(b1));
}
__device__ __forceinline__ unsigned sptr(const void* p){
    return (unsigned)__cvta_generic_to_shared(p);
}
__device__ __forceinline__ void cpa16(unsigned dst, const void* src){
    asm volatile("cp.async.cg.shared.global [%0], [%1], 16;\n" :: "r"(dst), "l"(src));
}
__device__ __forceinline__ void cpa_commit(){
    asm volatile("cp.async.commit_group;\n" ::: "memory");
}
template<int N> __device__ __forceinline__ void cpa_wait(){
    asm volatile("cp.async.wait_group %0;\n" :: "n"(N) : "memory");
}

// ---------------- setup: edge consts (blocks 0-2) + mask/offsets (block 3) -
__global__ void setup_all(const unsigned char* __restrict__ m,
                          const int* __restrict__ lengths,
                          const float* __restrict__ We1,
                          const float* __restrict__ be1,
                          const float* __restrict__ etable){
    int tid = threadIdx.x;
    if (blockIdx.x < 3){
        int l = blockIdx.x;
        if (tid < 128){
            int k = tid;
            const float* W = We1 + (size_t)l*289*128;
            g_wd2[l*128 + k] = W[256*128 + k];
            for (int t = 0; t < 2; t++){
                float s = be1[l*128 + k];
                for (int e = 0; e < 32; e++) s += etable[t*32 + e] * W[(257 + e)*128 + k];
                g_etab[l*256 + t*128 + k] = s;
            }
        }
        return;
    }
    __shared__ int s_big, s_odd;
    if (tid == 0){
        s_big = 0; s_odd = 0;
        int s = 0;
        for (int b = 0; b < BB; b++){ g_off[b] = s; s += lengths[b]; }
        g_off[BB] = s;
    }
    __syncthreads();
    int big = 0, odd = 0;
    for (int i = tid; i < NN; i += blockDim.x){
        unsigned char v = m[i];
        if (v > 1) big = 1;
        if ((i & 3) && v) odd = 1;
    }
    if (big) s_big = 1;
    if (odd) s_odd = 1;
    __syncthreads();
    if (s_big){
        const float* mf = (const float*)m;
        for (int i = tid; i < NN; i += blockDim.x) g_mask[i] = (mf[i] != 0.f) ? 1 : 0;
    } else if (s_odd){
        for (int i = tid; i < NN; i += blockDim.x) g_mask[i] = m[i] ? 1 : 0;
    } else {
        const int* mi = (const int*)m;
        for (int i = tid; i < NN; i += blockDim.x) g_mask[i] = mi[i] ? 1 : 0;
    }
}

__global__ void node_prep(const float* __restrict__ H0, const float* __restrict__ X0,
                          const float* __restrict__ H1, const float* __restrict__ X1,
                          const float* __restrict__ cond, const float* __restrict__ tg)
{
    int i = blockIdx.x;
    int k = threadIdx.x;
    __shared__ float t_sh; __shared__ int m_sh;
    if (k == 0){
        int b = 0;
        while (b + 1 < BB && g_off[b+1] <= i) b++;
        t_sh = tg[b];
        m_sh = g_mask[i];
    }
    __syncthreads();
    float t = t_sh; int m = m_sh;
    if (k < 64){
        float h0 = H0[i*64+k], h1 = H1[i*64+k];
        g_Hin[i*320 + k] = m ? (1.f - t)*h0 + t*h1 : h1;
        float f = expf(-logf(10000.f) * (float)k / 63.f);
        float ang = t * f;
        g_Hin[i*320 + 192 + k] = sinf(ang);
        g_Hin[i*320 + 256 + k] = cosf(ang);
    }
    g_Hin[i*320 + 64 + k] = cond[i*128 + k];
    if (k < 3){
        float x0 = X0[i*3+k], x1 = X1[i*3+k];
        g_X[0][i*3+k] = m ? (1.f - t)*x0 + t*x1 : x1;
    }
}

// tf32 weight pre-conversion (bit-identical to converting at read time)
__global__ void prep_w(const float* __restrict__ Wi1, const float* __restrict__ Wi2,
                       const float* __restrict__ Wi3, const float* __restrict__ We1,
                       const float* __restrict__ Wh1, const float* __restrict__ Wh2)
{
    int i0 = blockIdx.x*blockDim.x + threadIdx.x;
    int st = gridDim.x*blockDim.x;
    for (int i = i0; i < 40960; i += st) g_tw[OFF_I1+i] = f2tf32f(Wi1[i]);
    for (int i = i0; i < 16384; i += st) g_tw[OFF_I2+i] = f2tf32f(Wi2[i]);
    for (int i = i0; i < 16384; i += st) g_tw[OFF_I3+i] = f2tf32f(Wi3[i]);
    for (int i = i0; i < 49152; i += st){
        int l = i >> 14, r = i & 16383;
        g_tw[OFF_EA+i] = f2tf32f(We1[(size_t)l*36992 + r]);
        g_tw[OFF_EB+i] = f2tf32f(We1[(size_t)l*36992 + 16384 + r]);
    }
    for (int i = i0; i < 98304; i += st) g_tw[OFF_H1+i] = f2tf32f(Wh1[i]);
    for (int i = i0; i < 49152; i += st) g_tw[OFF_H2+i] = f2tf32f(Wh2[i]);
}

// ---------------- fused node-side tensor GEMM machinery --------------------
#define NS_AS  0
#define NS_WS  2304
#define NS_ACT 11008
#define NS_TOTF 15232
#define NS_BYTES (NS_TOTF*4)

__device__ __forceinline__ void tg_stageA(
    const float* __restrict__ A1, int K1, const float* __restrict__ A2, int K2,
    const float* __restrict__ Wt, float* As, float* Ws,
    float (&acc)[4][4], int gr0)
{
    int tid = threadIdx.x;
    int w = tid >> 5, lane = tid & 31;
    int wr = w >> 2, wc = w & 3;
    int gq = lane >> 2, lq = lane & 3;
    int K = K1 + K2, ntiles = K >> 5;
    int srow = tid >> 3, skc = tid & 7;

#pragma unroll
    for (int nt = 0; nt < 4; nt++)
#pragma unroll
        for (int q = 0; q < 4; q++) acc[nt][q] = 0.f;

    {
        int k = skc*4;
        const float* src = (k < K1) ? A1 + (size_t)(gr0+srow)*K1 + k
                                    : A2 + (size_t)(gr0+srow)*K2 + (k - K1);
        cpa16(sptr(&As[srow*36 + skc*4]), src);
#pragma unroll
        for (int i = 0; i < 4; i++){
            int idx = tid + i*256;
            int kk = idx >> 5, c = idx & 31;
            cpa16(sptr(&Ws[kk*136 + c*4]), Wt + (size_t)kk*128 + c*4);
        }
        cpa_commit();
    }

    for (int t = 0; t < ntiles; t++){
        int b = t & 1;
        if (t + 1 < ntiles){
            int nb = b ^ 1;
            int k = (t+1)*32 + skc*4;
            const float* src = (k < K1) ? A1 + (size_t)(gr0+srow)*K1 + k
                                        : A2 + (size_t)(gr0+srow)*K2 + (k - K1);
            cpa16(sptr(&As[nb*1152 + srow*36 + skc*4]), src);
            const float* Wtt = Wt + (size_t)(t+1)*32*128;
#pragma unroll
            for (int i = 0; i < 4; i++){
                int idx = tid + i*256;
                int kk = idx >> 5, c = idx & 31;
                cpa16(sptr(&Ws[nb*4352 + kk*136 + c*4]), Wtt + (size_t)kk*128 + c*4);
            }
            cpa_commit();
            cpa_wait<1>();
        } else {
            cpa_wait<0>();
        }
        __syncthreads();
        const float* as = As + b*1152;
        const float* ws = Ws + b*4352;
        int rr = wr*16 + gq;
#pragma unroll
        for (int ks = 0; ks < 4; ks++){
            int k0 = ks*8;
            unsigned afr[4];
            afr[0] = f2tf32(as[rr*36     + k0 + lq]);
            afr[1] = f2tf32(as[(rr+8)*36 + k0 + lq]);
            afr[2] = f2tf32(as[rr*36     + k0 + lq + 4]);
            afr[3] = f2tf32(as[(rr+8)*36 + k0 + lq + 4]);
#pragma unroll
            for (int nt = 0; nt < 4; nt++){
                int n = wc*32 + nt*8 + gq;
                unsigned b0 = __float_as_uint(ws[(k0 + lq)*136 + n]);
                unsigned b1 = __float_as_uint(ws[(k0 + lq + 4)*136 + n]);
                mma_tf32(acc[nt], afr, b0, b1);
            }
        }
        __syncthreads();
    }
}

__device__ __forceinline__ void tg_actA(
    const float* act, const float* __restrict__ Wt, float* Ws, float (&acc)[4][4])
{
    int tid = threadIdx.x;
    int w = tid >> 5, lane = tid & 31;
    int wr = w >> 2, wc = w & 3;
    int gq = lane >> 2, lq = lane & 3;

#pragma unroll
    for (int nt = 0; nt < 4; nt++)
#pragma unroll
        for (int q = 0; q < 4; q++) acc[nt][q] = 0.f;

    {
#pragma unroll
        for (int i = 0; i < 4; i++){
            int idx = tid + i*256;
            int kk = idx >> 5, c = idx & 31;
            cpa16(sptr(&Ws[kk*136 + c*4]), Wt + (size_t)kk*128 + c*4);
        }
        cpa_commit();
    }
    for (int t = 0; t < 4; t++){
        int b = t & 1;
        if (t + 1 < 4){
            int nb = b ^ 1;
            const float* Wtt = Wt + (size_t)(t+1)*32*128;
#pragma unroll
            for (int i = 0; i < 4; i++){
                int idx = tid + i*256;
                int kk = idx >> 5, c = idx & 31;
                cpa16(sptr(&Ws[nb*4352 + kk*136 + c*4]), Wtt + (size_t)kk*128 + c*4);
            }
            cpa_commit();
            cpa_wait<1>();
        } else {
            cpa_wait<0>();
        }
        __syncthreads();
        const float* ws = Ws + b*4352;
        int rr = wr*16 + gq;
        int kb = t*32;
#pragma unroll
        for (int ks = 0; ks < 4; ks++){
            int k0 = ks*8;
            unsigned afr[4];
            afr[0] = __float_as_uint(act[rr*132     + kb + k0 + lq]);
            afr[1] = __float_as_uint(act[(rr+8)*132 + kb + k0 + lq]);
            afr[2] = __float_as_uint(act[rr*132     + kb + k0 + lq + 4]);
            afr[3] = __float_as_uint(act[(rr+8)*132 + kb + k0 + lq + 4]);
#pragma unroll
            for (int nt = 0; nt < 4; nt++){
                int n = wc*32 + nt*8 + gq;
                unsigned b0 = __float_as_uint(ws[(k0 + lq)*136 + n]);
                unsigned b1 = __float_as_uint(ws[(k0 + lq + 4)*136 + n]);
                mma_tf32(acc[nt], afr, b0, b1);
            }
        }
        __syncthreads();
    }
}

__device__ __forceinline__ void epi(
    float (&acc)[4][4], const float* __restrict__ bias, int mode,
    float* actbuf, float* __restrict__ gout, const float* __restrict__ resid, int gr0)
{
    int tid = threadIdx.x;
    int w = tid >> 5, lane = tid & 31;
    int wr = w >> 2, wc = w & 3;
    int gq = lane >> 2, lq = lane & 3;
    int rr = wr*16 + gq;
#pragma unroll
    for (int nt = 0; nt < 4; nt++){
        int col = wc*32 + nt*8 + lq*2;
        float b0 = 0.f, b1 = 0.f;
        if (bias){ b0 = bias[col]; b1 = bias[col+1]; }
        float v0 = acc[nt][0] + b0, v1 = acc[nt][1] + b1;
        float v2 = acc[nt][2] + b0, v3 = acc[nt][3] + b1;
        if (mode == 1){
            v0 = fmaxf(v0,0.f); v1 = fmaxf(v1,0.f);
            v2 = fmaxf(v2,0.f); v3 = fmaxf(v3,0.f);
        } else if (mode == 2){
            v0 = silu_f(v0); v1 = silu_f(v1);
            v2 = silu_f(v2); v3 = silu_f(v3);
        }
        if (resid){
            v0 += resid[(size_t)(gr0+rr)*128 + col];
            v1 += resid[(size_t)(gr0+rr)*128 + col + 1];
            v2 += resid[(size_t)(gr0+rr+8)*128 + col];
            v3 += resid[(size_t)(gr0+rr+8)*128 + col + 1];
        }
        if (gout){
            *(float2*)&gout[(size_t)(gr0+rr)*128 + col]   = make_float2(v0, v1);
            *(float2*)&gout[(size_t)(gr0+rr+8)*128 + col] = make_float2(v2, v3);
        }
        if (actbuf){
            actbuf[rr*132 + col]       = f2tf32f(v0);
            actbuf[rr*132 + col + 1]   = f2tf32f(v1);
            actbuf[(rr+8)*132 + col]   = f2tf32f(v2);
            actbuf[(rr+8)*132 + col+1] = f2tf32f(v3);
        }
    }
}

__global__ void __launch_bounds__(256, 1) mlp_dual(
    const float* __restrict__ bi1, const float* __restrict__ bi2,
    const float* __restrict__ bi3)
{
    extern __shared__ float sm[];
    float* As  = sm + NS_AS;
    float* Ws  = sm + NS_WS;
    float* act = sm + NS_ACT;
    int gr0 = blockIdx.x * 32;
    float acc[4][4];

    tg_stageA(g_Hin, 320, nullptr, 0, g_tw + OFF_I1, As, Ws, acc, gr0);
    epi(acc, bi1, 1, act, nullptr, nullptr, gr0);
    __syncthreads();
    tg_actA(act, g_tw + OFF_I2, Ws, acc);
    epi(acc, bi2, 1, act, nullptr, nullptr, gr0);
    __syncthreads();
    tg_actA(act, g_tw + OFF_I3, Ws, acc);
    epi(acc, bi3, 0, act, g_h, nullptr, gr0);
    __syncthreads();
    tg_actA(act, g_tw + OFF_EA, Ws, acc);
    epi(acc, nullptr, 0, nullptr, g_a, nullptr, gr0);
    tg_actA(act, g_tw + OFF_EB, Ws, acc);
    epi(acc, nullptr, 0, nullptr, g_bn, nullptr, gr0);
}

__global__ void __launch_bounds__(256, 1) hup_kernel(
    const float* __restrict__ bh1, const float* __restrict__ bh2,
    int l, int with_dual)
{
    extern __shared__ float sm[];
    float* As  = sm + NS_AS;
    float* Ws  = sm + NS_WS;
    float* act = sm + NS_ACT;
    int gr0 = blockIdx.x * 32;
    float acc[4][4];

    tg_stageA(g_h, 128, g_agg, 128, g_tw + OFF_H1 + l*32768, As, Ws, acc, gr0);
    epi(acc, bh1, 2, act, nullptr, nullptr, gr0);
    __syncthreads();
    tg_actA(act, g_tw + OFF_H2 + l*16384, Ws, acc);
    epi(acc, bh2, 0, act, g_h, g_h, gr0);
    __syncthreads();
    if (with_dual){
        tg_actA(act, g_tw + OFF_EA + (l+1)*16384, Ws, acc);
        epi(acc, nullptr, 0, nullptr, g_a, nullptr, gr0);
        tg_actA(act, g_tw + OFF_EB + (l+1)*16384, Ws, acc);
        epi(acc, nullptr, 0, nullptr, g_bn, nullptr, gr0);
    }
}

// ---------------- fp32 node GEMM for NOUT=64 (Wout, output precision) -----
template<int NOUT>
__global__ void __launch_bounds__(128, 4) gemm16(
    const float* __restrict__ A1, int K1,
    const float* __restrict__ W,
    const float* __restrict__ bias,
    float* __restrict__ out)
{
    constexpr int ROWS = 24;
    constexpr int NC4  = NOUT / 4;
    constexpr int TR   = 128 / NC4;
    constexpr int R    = ROWS / TR;
    __shared__ float As[2][ROWS*32];
    __shared__ float Ws[2][32*NOUT];

    int tid = threadIdx.x;
    int tx = tid % NC4, ty = tid / NC4;
    int c0 = tx*4, r0 = ty*R;
    int gr0 = blockIdx.x * ROWS;
    int K = K1;
    int ntiles = K >> 5;

    float acc[R][4];
#pragma unroll
    for (int i = 0; i < R; i++)
#pragma unroll
        for (int j = 0; j < 4; j++) acc[i][j] = 0.f;

    {
        for (int i = tid; i < ROWS*8; i += 128){
            int row = i >> 3, kc = i & 7;
            cpa16(sptr(&As[0][row*32 + kc*4]), A1 + (size_t)(gr0+row)*K + kc*4);
        }
        for (int i = tid; i < 8*NOUT; i += 128)
            cpa16(sptr(&Ws[0][i*4]), W + (size_t)i*4);
        cpa_commit();
    }

    for (int t = 0; t < ntiles; t++){
        int b = t & 1;
        if (t + 1 < ntiles){
            int nb = b ^ 1;
            for (int i = tid; i < ROWS*8; i += 128){
                int row = i >> 3, kc = i & 7;
                cpa16(sptr(&As[nb][row*32 + kc*4]),
                      A1 + (size_t)(gr0+row)*K + (t+1)*32 + kc*4);
            }
            const float* Wt = W + (size_t)(t+1)*32*NOUT;
            for (int i = tid; i < 8*NOUT; i += 128)
                cpa16(sptr(&Ws[nb][i*4]), Wt + (size_t)i*4);
            cpa_commit();
            cpa_wait<1>();
        } else {
            cpa_wait<0>();
        }
        __syncthreads();
        const float* as = As[b];
        const float* ws = Ws[b];
#pragma unroll
        for (int kk = 0; kk < 32; kk++){
            float4 w = *(const float4*)&ws[kk*NOUT + c0];
            float a[R];
#pragma unroll
            for (int i = 0; i < R; i++) a[i] = as[(r0+i)*32 + kk];
#pragma unroll
            for (int i = 0; i < R; i++){
                acc[i][0] += a[i]*w.x; acc[i][1] += a[i]*w.y;
                acc[i][2] += a[i]*w.z; acc[i][3] += a[i]*w.w;
            }
        }
        __syncthreads();
    }

    float4 bv = make_float4(0.f,0.f,0.f,0.f);
    if (bias) bv = *(const float4*)&bias[c0];
#pragma unroll
    for (int i = 0; i < R; i++){
        int g = gr0 + r0 + i;
        float4 v;
        v.x = acc[i][0] + bv.x; v.y = acc[i][1] + bv.y;
        v.z = acc[i][2] + bv.z; v.w = acc[i][3] + bv.w;
        *(float4*)&out[(size_t)g*NOUT + c0] = v;
    }
}

// ---------------- persistent fused edge kernel ----------------------------
#define S_M1    0                     // 96*132 = 12672
#define S_W2    12672                 // 128*136 = 17408
#define S_BRAW  30080                 // 96*128 = 12288 (single buffer)
#define S_A     42368                 // 2*128
#define S_WD2   42624                 // 128
#define S_ETAB  42752                 // 256
#define S_BE2   43008                 // 128
#define S_WX    43136                 // 128
#define S_REL   43264                 // 2*96*4 = 768
#define S_COEF  44032                 // 96
#define S_COEFP 44128                 // 384
#define S_AGGP  44512                 // 256
#define S_ET    44768                 // 2*96 ints
#define S_TOTF  44960
#define SMEM_BYTES (S_TOTF*4)

__global__ void __launch_bounds__(256, 1) edge_kernel(
    const float* __restrict__ aG, const float* __restrict__ bG,
    const float* __restrict__ Xin, float* __restrict__ Xout,
    float* __restrict__ aggG,
    const int* __restrict__ ecol, const int* __restrict__ chain,
    const float* __restrict__ W2g, const float* __restrict__ be2g,
    const float* __restrict__ Wxg, int layer)
{
    extern __shared__ float sm[];
    float* M1     = sm + S_M1;    // stride 132
    float* W2     = sm + S_W2;    // stride 136
    float* braw   = sm + S_BRAW;  // 96 x 128
    float* a_s    = sm + S_A;     // [2][128]
    float* wd2_s  = sm + S_WD2;
    float* etab_s = sm + S_ETAB;
    float* be2_s  = sm + S_BE2;
    float* Wx_s   = sm + S_WX;
    float* rel_s  = sm + S_REL;   // [2][96*4]
    float* coef_s = sm + S_COEF;
    float* coefp  = sm + S_COEFP;
    float* aggp   = sm + S_AGGP;  // [2][128]
    int*   et_s   = (int*)(sm + S_ET);  // [2][96]

    int tid = threadIdx.x;

    for (int i = tid; i < 128*32; i += 256){
        int row = i >> 5, cg = (i & 31);
        float4 v = ((const float4*)W2g)[row*32 + cg];
        float4 p;
        p.x = f2tf32f(v.x);
        p.y = f2tf32f(v.y);
        p.z = f2tf32f(v.z);
        p.w = f2tf32f(v.w);
        *(float4*)&W2[row*136 + cg*4] = p;
    }
    if (tid < 128){
        wd2_s[tid]     = g_wd2[layer*128 + tid];
        etab_s[tid]    = g_etab[layer*256 + tid];
        etab_s[128+tid]= g_etab[layer*256 + 128 + tid];
        be2_s[tid]     = be2g[tid];
        Wx_s[tid]      = Wxg[tid];
    }

    int w  = tid >> 5, lane = tid & 31;
    int wr = w >> 2, wc = w & 3;
    int mr = wr * 48, nc0 = wc * 32;
    int gq = lane >> 2, lq = lane & 3;

    int cur = 0;
    int r = blockIdx.x;

    if (r < NN){
        if (tid < 96){
            int c = ecol[r*96 + tid];
            float dx = Xin[r*3]   - Xin[c*3];
            float dy = Xin[r*3+1] - Xin[c*3+1];
            float dz = Xin[r*3+2] - Xin[c*3+2];
            rel_s[tid*4]   = dx;
            rel_s[tid*4+1] = dy;
            rel_s[tid*4+2] = dz;
            rel_s[tid*4+3] = dx*dx + dy*dy + dz*dz;
            et_s[tid] = (chain[c] != chain[r]) ? 1 : 0;
#pragma unroll
            for (int ch = 0; ch < 32; ch++)
                cpa16(sptr(&braw[tid*128 + ch*4]), bG + (size_t)c*128 + ch*4);
        } else if (tid < 128){
            cpa16(sptr(&a_s[(tid-96)*4]), aG + (size_t)r*128 + (tid-96)*4);
        }
        cpa_commit();
    }

    while (r < NN){
        int r_next = r + gridDim.x;
        cpa_wait<0>();
        __syncthreads();

        // phase 1: m1 = silu(a + b + d2*wd2 + etab) -> tf32 M1
        {
            const float* aa = a_s + cur*128;
            const float* rl = rel_s + cur*384;
            const int*   et = et_s + cur*96;
            for (int idx = tid; idx < 96*32; idx += 256){
                int j = idx >> 5, k = (idx & 31) * 4;
                float4 bn = *(const float4*)&braw[j*128 + k];
                float d2 = rl[j*4+3];
                const float* etb = etab_s + et[j]*128;
                float4 p;
                p.x = silu_f(aa[k+0] + bn.x + d2*wd2_s[k+0] + etb[k+0]);
                p.y = silu_f(aa[k+1] + bn.y + d2*wd2_s[k+1] + etb[k+1]);
                p.z = silu_f(aa[k+2] + bn.z + d2*wd2_s[k+2] + etb[k+2]);
                p.w = silu_f(aa[k+3] + bn.w + d2*wd2_s[k+3] + etb[k+3]);
                p.x = f2tf32f(p.x);
                p.y = f2tf32f(p.y);
                p.z = f2tf32f(p.z);
                p.w = f2tf32f(p.w);
                *(float4*)&M1[j*132 + k] = p;
            }
        }
        __syncthreads();   // braw consumed; M1 ready

        // prefetch next node (lands during GEMM)
        if (r_next < NN){
            int nxt = cur ^ 1;
            if (tid < 96){
                int c = ecol[r_next*96 + tid];
                float dx = Xin[r_next*3]   - Xin[c*3];
                float dy = Xin[r_next*3+1] - Xin[c*3+1];
                float dz = Xin[r_next*3+2] - Xin[c*3+2];
                rel_s[nxt*384 + tid*4]   = dx;
                rel_s[nxt*384 + tid*4+1] = dy;
                rel_s[nxt*384 + tid*4+2] = dz;
                rel_s[nxt*384 + tid*4+3] = dx*dx + dy*dy + dz*dz;
                et_s[nxt*96 + tid] = (chain[c] != chain[r_next]) ? 1 : 0;
#pragma unroll
                for (int ch = 0; ch < 32; ch++)
                    cpa16(sptr(&braw[tid*128 + ch*4]), bG + (size_t)c*128 + ch*4);
            } else if (tid < 128){
                cpa16(sptr(&a_s[(cur^1)*128 + (tid-96)*4]),
                      aG + (size_t)r_next*128 + (tid-96)*4);
            }
            cpa_commit();
        }

        // phase 2: tensor GEMM 96x128 @ 128x128
        float acc[3][4][4];
#pragma unroll
        for (int mt = 0; mt < 3; mt++)
#pragma unroll
            for (int nt = 0; nt < 4; nt++)
#pragma unroll
                for (int q = 0; q < 4; q++) acc[mt][nt][q] = 0.f;

#pragma unroll 4
        for (int k0 = 0; k0 < 128; k0 += 8){
            unsigned afr[3][4];
#pragma unroll
            for (int mt = 0; mt < 3; mt++){
                int rr = mr + mt*16 + gq;
                afr[mt][0] = __float_as_uint(M1[rr*132      + k0 + lq]);
                afr[mt][1] = __float_as_uint(M1[(rr+8)*132  + k0 + lq]);
                afr[mt][2] = __float_as_uint(M1[rr*132      + k0 + lq + 4]);
                afr[mt][3] = __float_as_uint(M1[(rr+8)*132  + k0 + lq + 4]);
            }
#pragma unroll
            for (int nt = 0; nt < 4; nt++){
                int n = nc0 + nt*8 + gq;
                unsigned b0 = __float_as_uint(W2[(k0 + lq)*136 + n]);
                unsigned b1 = __float_as_uint(W2[(k0 + lq + 4)*136 + n]);
#pragma unroll
                for (int mt = 0; mt < 3; mt++)
                    mma_tf32(acc[mt][nt], afr[mt], b0, b1);
            }
        }
        // no barrier: epilogue is register-only + coefp/aggp writes

        float cf[3][2] = {{0.f,0.f},{0.f,0.f},{0.f,0.f}};
        float sa[4][2];
#pragma unroll
        for (int nt = 0; nt < 4; nt++){ sa[nt][0] = 0.f; sa[nt][1] = 0.f; }
#pragma unroll
        for (int mt = 0; mt < 3; mt++){
#pragma unroll
            for (int nt = 0; nt < 4; nt++){
                int col = nc0 + nt*8 + lq*2;
                float wx0 = Wx_s[col], wx1 = Wx_s[col+1];
                float b0 = be2_s[col], b1 = be2_s[col+1];
                float v0 = silu_f(acc[mt][nt][0] + b0);
                float v1 = silu_f(acc[mt][nt][1] + b1);
                float v2 = silu_f(acc[mt][nt][2] + b0);
                float v3 = silu_f(acc[mt][nt][3] + b1);
                cf[mt][0] += v0*wx0 + v1*wx1;
                cf[mt][1] += v2*wx0 + v3*wx1;
                sa[nt][0] += v0 + v2;
                sa[nt][1] += v1 + v3;
            }
        }
#pragma unroll
        for (int nt = 0; nt < 4; nt++){
#pragma unroll
            for (int p = 0; p < 2; p++){
                float s = sa[nt][p];
                s += __shfl_xor_sync(0xffffffffu, s, 4);
                s += __shfl_xor_sync(0xffffffffu, s, 8);
                s += __shfl_xor_sync(0xffffffffu, s, 16);
                sa[nt][p] = s;
            }
        }
        if (gq == 0){
#pragma unroll
            for (int nt = 0; nt < 4; nt++){
                int col = nc0 + nt*8 + lq*2;
                aggp[wr*128 + col]     = sa[nt][0];
                aggp[wr*128 + col + 1] = sa[nt][1];
            }
        }
#pragma unroll
        for (int mt = 0; mt < 3; mt++){
#pragma unroll
            for (int h = 0; h < 2; h++){
                float c = cf[mt][h];
                c += __shfl_xor_sync(0xffffffffu, c, 1);
                c += __shfl_xor_sync(0xffffffffu, c, 2);
                if (lq == 0) coefp[wc*96 + mr + mt*16 + h*8 + gq] = c;
            }
        }
        __syncthreads();

        if (tid < 96)
            coef_s[tid] = coefp[tid] + coefp[96+tid] + coefp[192+tid] + coefp[288+tid];
        if (tid < 128)
            aggG[(size_t)r*128 + tid] = aggp[tid] + aggp[128 + tid];
        __syncthreads();

        if (w < 3){
            const float* rl = rel_s + cur*384;
            float s = coef_s[lane]    * rl[lane*4 + w]
                    + coef_s[lane+32] * rl[(lane+32)*4 + w]
                    + coef_s[lane+64] * rl[(lane+64)*4 + w];
            s += __shfl_xor_sync(0xffffffffu, s, 16);
            s += __shfl_xor_sync(0xffffffffu, s, 8);
            s += __shfl_xor_sync(0xffffffffu, s, 4);
            s += __shfl_xor_sync(0xffffffffu, s, 2);
            s += __shfl_xor_sync(0xffffffffu, s, 1);
            if (lane == 0) Xout[r*3 + w] = Xin[r*3 + w] + s;
        }
        r = r_next; cur ^= 1;
    }
}

// ---------------- losses ----------------
__global__ void loss_partial(const float* __restrict__ H0, const float* __restrict__ H1,
                             const float* __restrict__ X0, const float* __restrict__ X1,
                             const int* __restrict__ shiftp,
                             const float* __restrict__ Xf)
{
    __shared__ float red[64];
    float s[5] = {0,0,0,0,0};
    int shift = *shiftp;
    for (int i = blockIdx.x*blockDim.x + threadIdx.x; i < NN; i += gridDim.x*blockDim.x){
        if (!g_mask[i]) continue;
        int j = (i + shift) % NN; if (j < 0) j += NN;
        float hp = 0.f, hn = 0.f;
        const float4* vp = (const float4*)(g_vH + (size_t)i*64);
        const float4* a1 = (const float4*)(H1 + (size_t)i*64);
        const float4* a0 = (const float4*)(H0 + (size_t)i*64);
        const float4* b1 = (const float4*)(H1 + (size_t)j*64);
        const float4* b0 = (const float4*)(H0 + (size_t)j*64);
#pragma unroll
        for (int k = 0; k < 16; k++){
            float4 p = vp[k], x1 = a1[k], x0 = a0[k], y1 = b1[k], y0 = b0[k];
            float d;
            d = p.x - (x1.x - x0.x); hp += d*d;
            d = p.y - (x1.y - x0.y); hp += d*d;
            d = p.z - (x1.z - x0.z); hp += d*d;
            d = p.w - (x1.w - x0.w); hp += d*d;
            d = p.x - (y1.x - y0.x); hn += d*d;
            d = p.y - (y1.y - y0.y); hn += d*d;
            d = p.z - (y1.z - y0.z); hn += d*d;
            d = p.w - (y1.w - y0.w); hn += d*d;
        }
        float xp = 0.f, xn = 0.f;
        for (int k = 0; k < 3; k++){
            float p = Xf[i*3 + k];
            float d  = p - (X1[i*3+k] - X0[i*3+k]); xp += d*d;
            float dn = p - (X1[j*3+k] - X0[j*3+k]); xn += dn*dn;
        }
        s[0] += hp; s[1] += xp; s[2] += hn; s[3] += xn; s[4] += 1.f;
    }
    for (int q = 0; q < 5; q++){
        red[threadIdx.x] = s[q]; __syncthreads();
        for (int d = 32; d > 0; d >>= 1){
            if (threadIdx.x < d) red[threadIdx.x] += red[threadIdx.x + d];
            __syncthreads();
        }
        if (threadIdx.x == 0) g_lpart[blockIdx.x*5 + q] = red[0];
        __syncthreads();
    }
}

__global__ void loss_final(float* __restrict__ out, int nb){
    if (threadIdx.x == 0){
        float s[5] = {0,0,0,0,0};
        for (int b = 0; b < nb; b++)
            for (int q = 0; q < 5; q++) s[q] += g_lpart[b*5 + q];
        float msum = s[4] + 1e-8f;
        float lHp = s[0]/msum, lXp = s[1]/msum, lHn = s[2]/msum, lXn = s[3]/msum;
        out[0] = lHp - 0.05f*lHn;
        out[1] = lXp - 0.05f*lXn;
        out[2] = lHp; out[3] = lXp; out[4] = lHn; out[5] = lXn;
    }
}

// ---------------- host launch ----------------
extern "C" void kernel_launch(void* const* d_in, const int* in_sizes, int n_in,
                              void* d_out, int out_size)
{
    (void)in_sizes; (void)n_in; (void)out_size;
    const float* H0    = (const float*)d_in[0];
    const float* X0    = (const float*)d_in[1];
    const float* H1    = (const float*)d_in[2];
    const float* X1    = (const float*)d_in[3];
    const float* cond  = (const float*)d_in[4];
    const float* tg    = (const float*)d_in[5];
    const float* Wi1   = (const float*)d_in[6];
    const float* bi1   = (const float*)d_in[7];
    const float* Wi2   = (const float*)d_in[8];
    const float* bi2   = (const float*)d_in[9];
    const float* Wi3   = (const float*)d_in[10];
    const float* bi3   = (const float*)d_in[11];
    const float* etab  = (const float*)d_in[12];
    const float* We1   = (const float*)d_in[13];
    const float* be1   = (const float*)d_in[14];
    const float* We2   = (const float*)d_in[15];
    const float* be2   = (const float*)d_in[16];
    const float* Wx    = (const float*)d_in[17];
    const float* Wh1   = (const float*)d_in[18];
    const float* bh1   = (const float*)d_in[19];
    const float* Wh2   = (const float*)d_in[20];
    const float* bh2   = (const float*)d_in[21];
    const float* Wout  = (const float*)d_in[22];
    const float* bout  = (const float*)d_in[23];
    const int*   edges = (const int*)d_in[24];
    const int*   chain = (const int*)d_in[25];
    const unsigned char* mask = (const unsigned char*)d_in[26];
    const int*   lengths = (const int*)d_in[27];
    const int*   shiftp  = (const int*)d_in[28];
    const int*   ecol = edges + EE;

    float *p_h, *p_a, *p_bn, *p_agg, *p_X, *p_vH;
    cudaGetSymbolAddress((void**)&p_h,   g_h);
    cudaGetSymbolAddress((void**)&p_a,   g_a);
    cudaGetSymbolAddress((void**)&p_bn,  g_bn);
    cudaGetSymbolAddress((void**)&p_agg, g_agg);
    cudaGetSymbolAddress((void**)&p_X,   g_X);
    cudaGetSymbolAddress((void**)&p_vH,  g_vH);

    int nsm = 148;
    cudaDeviceGetAttribute(&nsm, cudaDevAttrMultiProcessorCount, 0);
    if (nsm <= 0) nsm = 148;

    cudaFuncSetAttribute(edge_kernel,
                         cudaFuncAttributeMaxDynamicSharedMemorySize, SMEM_BYTES);
    cudaFuncSetAttribute(mlp_dual,
                         cudaFuncAttributeMaxDynamicSharedMemorySize, NS_BYTES);
    cudaFuncSetAttribute(hup_kernel,
                         cudaFuncAttributeMaxDynamicSharedMemorySize, NS_BYTES);

    setup_all<<<4, 256>>>(mask, lengths, We1, be1, etab);
    node_prep<<<NN, 128>>>(H0, X0, H1, X1, cond, tg);
    prep_w<<<128, 256>>>(Wi1, Wi2, Wi3, We1, Wh1, Wh2);

    mlp_dual<<<96, 256, NS_BYTES>>>(bi1, bi2, bi3);

    int cur = 0;
    for (int l = 0; l < 3; l++){
        edge_kernel<<<nsm, 256, SMEM_BYTES>>>(p_a, p_bn,
                                             p_X + cur*NN*3, p_X + (1-cur)*NN*3,
                                             p_agg, ecol, chain,
                                             We2 + (size_t)l*128*128,
                                             be2 + l*128, Wx + l*128, l);
        cur = 1 - cur;
        hup_kernel<<<96, 256, NS_BYTES>>>(bh1 + l*128, bh2 + l*128, l, l < 2);
    }

    gemm16<64><<<128, 128>>>(p_h, 128, Wout, bout, p_vH);

    loss_partial<<<48, 64>>>(H0, H1, X0, X1, shiftp, p_X + cur*NN*3);
    loss_final<<<1, 32>>>((float*)d_out, 48);
}